// round 1
// baseline (speedup 1.0000x reference)
#include <cuda_runtime.h>
#include <cstdint>

// ---------------- problem dims ----------------
#define Bb 64
#define Nn 1024
#define Din 16
#define Dd 256
#define Hh 4
#define DH 64
#define Ll 3
#define DFF 1024
#define Kk 64
#define MM (Bb*Nn)          // 65536 rows

// ---------------- scratch (static device memory; no allocs allowed) ----------------
__device__ float g_h[MM*Dd];            // 64 MB   hidden state
__device__ float g_scr[MM*DFF];         // 256 MB  q|k|v|attn_out, or ffn hidden
__device__ float g_tmp[MM*Dd];          // 64 MB   proj out / ffn out / kv
__device__ float g_hmean[Bb*Dd];
__device__ float g_qv[Bb*Dd];
__device__ float g_t1[Bb*Dd];
__device__ float g_logits[Bb*Nn];
__device__ float g_scores[Bb*Nn];

// ---------------- embedding: h = x @ emb_W + emb_b ----------------
__global__ void embed_kernel(const float* __restrict__ x, const float* __restrict__ W,
                             const float* __restrict__ b, float* __restrict__ h)
{
    int m = blockIdx.x;            // row
    int d = threadIdx.x;           // 256 threads
    __shared__ float xs[Din];
    if (threadIdx.x < Din) xs[threadIdx.x] = x[m*Din + threadIdx.x];
    __syncthreads();
    float acc = b[d];
#pragma unroll
    for (int k = 0; k < Din; k++) acc = fmaf(xs[k], W[k*Dd + d], acc);
    h[(size_t)m*Dd + d] = acc;
}

// ---------------- SGEMM: C[M,N] = A[M,K] @ W[K,N] (+bias, +relu) ----------------
// 128x128 tile, BK=8, 256 threads, 8x8 per thread, float4, register prefetch.
template<int RELU>
__global__ __launch_bounds__(256, 2) void sgemm_kernel(
    const float* __restrict__ A, const float* __restrict__ W,
    const float* __restrict__ bias, float* __restrict__ C,
    int M, int Nd, int Kd)
{
    __shared__ float As[8][128];
    __shared__ float Ws[8][128];
    const int tid = threadIdx.x;
    const int bm = blockIdx.y, bn = blockIdx.x;
    const int arow = tid >> 1, acol = (tid & 1) << 2;    // A tile 128x8
    const int wrow = tid >> 5, wcol = (tid & 31) << 2;   // W tile 8x128
    const int tx = tid & 15, ty = tid >> 4;

    const float* Ap = A + (size_t)(bm*128 + arow)*Kd + acol;
    const float* Wp = W + (size_t)wrow*Nd + bn*128 + wcol;

    float acc[8][8];
#pragma unroll
    for (int i = 0; i < 8; i++)
#pragma unroll
        for (int j = 0; j < 8; j++) acc[i][j] = 0.f;

    float4 av = *(const float4*)Ap;
    float4 wv = *(const float4*)Wp;

    for (int k0 = 0; k0 < Kd; k0 += 8) {
        As[acol+0][arow] = av.x; As[acol+1][arow] = av.y;
        As[acol+2][arow] = av.z; As[acol+3][arow] = av.w;
        *(float4*)&Ws[wrow][wcol] = wv;
        __syncthreads();
        if (k0 + 8 < Kd) {
            av = *(const float4*)(Ap + k0 + 8);
            wv = *(const float4*)(Wp + (size_t)(k0 + 8)*Nd);
        }
#pragma unroll
        for (int kk = 0; kk < 8; kk++) {
            float af[8], wf[8];
            *(float4*)(af)   = *(const float4*)&As[kk][ty*8];
            *(float4*)(af+4) = *(const float4*)&As[kk][ty*8+4];
            *(float4*)(wf)   = *(const float4*)&Ws[kk][tx*8];
            *(float4*)(wf+4) = *(const float4*)&Ws[kk][tx*8+4];
#pragma unroll
            for (int i = 0; i < 8; i++)
#pragma unroll
                for (int j = 0; j < 8; j++)
                    acc[i][j] = fmaf(af[i], wf[j], acc[i][j]);
        }
        __syncthreads();
    }

    const int crow0 = bm*128 + ty*8;
    const int ccol0 = bn*128 + tx*8;
    float bc[8];
#pragma unroll
    for (int j = 0; j < 8; j++) bc[j] = bias ? bias[ccol0 + j] : 0.f;
#pragma unroll
    for (int i = 0; i < 8; i++) {
        float4 o1, o2;
        float v0 = acc[i][0]+bc[0], v1 = acc[i][1]+bc[1], v2 = acc[i][2]+bc[2], v3 = acc[i][3]+bc[3];
        float v4 = acc[i][4]+bc[4], v5 = acc[i][5]+bc[5], v6 = acc[i][6]+bc[6], v7 = acc[i][7]+bc[7];
        if (RELU) {
            v0=fmaxf(v0,0.f); v1=fmaxf(v1,0.f); v2=fmaxf(v2,0.f); v3=fmaxf(v3,0.f);
            v4=fmaxf(v4,0.f); v5=fmaxf(v5,0.f); v6=fmaxf(v6,0.f); v7=fmaxf(v7,0.f);
        }
        o1.x=v0; o1.y=v1; o1.z=v2; o1.w=v3;
        o2.x=v4; o2.y=v5; o2.z=v6; o2.w=v7;
        *(float4*)&C[(size_t)(crow0+i)*Nd + ccol0]     = o1;
        *(float4*)&C[(size_t)(crow0+i)*Nd + ccol0 + 4] = o2;
    }
}

// ---------------- fused flash attention (fp32, online softmax) ----------------
// grid: (N/128, H, B); 128 threads; 1 thread = 1 q row. q & o in registers,
// K/V tiles in SMEM (reads are warp-broadcast).
__global__ __launch_bounds__(128) void attn_kernel(
    const float* __restrict__ Q, const float* __restrict__ Kg,
    const float* __restrict__ V, float* __restrict__ O)
{
    __shared__ float Ks[64][64];
    __shared__ float Vs[64][64];
    const int qt = blockIdx.x, head = blockIdx.y, b = blockIdx.z;
    const int tid = threadIdx.x;
    const size_t base = ((size_t)b*Nn)*Dd + head*DH;
    const int qrow = qt*128 + tid;

    float q[64];
    const float* qp = Q + base + (size_t)qrow*Dd;
#pragma unroll
    for (int d = 0; d < 64; d += 4) {
        float4 t = *(const float4*)(qp + d);
        q[d] = t.x; q[d+1] = t.y; q[d+2] = t.z; q[d+3] = t.w;
    }
    const float scale = 0.125f;   // 1/sqrt(64)
    float m = -1e30f, l = 0.f;
    float o[64];
#pragma unroll
    for (int d = 0; d < 64; d++) o[d] = 0.f;

    for (int j0 = 0; j0 < Nn; j0 += 64) {
        for (int t = tid; t < 1024; t += 128) {
            int r = t >> 4, c = (t & 15) << 2;
            *(float4*)&Ks[r][c] = *(const float4*)(Kg + base + (size_t)(j0+r)*Dd + c);
            *(float4*)&Vs[r][c] = *(const float4*)(V  + base + (size_t)(j0+r)*Dd + c);
        }
        __syncthreads();
#pragma unroll
        for (int jj = 0; jj < 64; jj += 16) {
            float s[16];
#pragma unroll
            for (int j = 0; j < 16; j++) {
                float acc = 0.f;
#pragma unroll
                for (int d = 0; d < 64; d++) acc = fmaf(q[d], Ks[jj+j][d], acc);
                s[j] = acc * scale;
            }
            float mloc = m;
#pragma unroll
            for (int j = 0; j < 16; j++) mloc = fmaxf(mloc, s[j]);
            float corr = __expf(m - mloc);
            m = mloc;
            l *= corr;
#pragma unroll
            for (int d = 0; d < 64; d++) o[d] *= corr;
#pragma unroll
            for (int j = 0; j < 16; j++) {
                float p = __expf(s[j] - m);
                l += p;
#pragma unroll
                for (int d = 0; d < 64; d++) o[d] = fmaf(p, Vs[jj+j][d], o[d]);
            }
        }
        __syncthreads();
    }
    float invl = 1.f / l;
    float* op = O + base + (size_t)qrow*Dd;
#pragma unroll
    for (int d = 0; d < 64; d += 4) {
        float4 t;
        t.x = o[d]*invl; t.y = o[d+1]*invl; t.z = o[d+2]*invl; t.w = o[d+3]*invl;
        *(float4*)(op + d) = t;
    }
}

// ---------------- LayerNorm(h + res) in place, warp-per-row ----------------
__global__ void ln_res_kernel(float* __restrict__ h, const float* __restrict__ res,
                              const float* __restrict__ g, const float* __restrict__ bta)
{
    int row = blockIdx.x*8 + (threadIdx.x >> 5);
    int lane = threadIdx.x & 31;
    size_t off = (size_t)row * Dd;
    float v[8];
    float s = 0.f;
#pragma unroll
    for (int i = 0; i < 8; i++) {
        int c = lane + i*32;
        v[i] = h[off+c] + res[off+c];
        s += v[i];
    }
#pragma unroll
    for (int o = 16; o; o >>= 1) s += __shfl_xor_sync(0xffffffffu, s, o);
    float mean = s * (1.f/256.f);
    float vs = 0.f;
#pragma unroll
    for (int i = 0; i < 8; i++) { float d = v[i]-mean; vs = fmaf(d, d, vs); }
#pragma unroll
    for (int o = 16; o; o >>= 1) vs += __shfl_xor_sync(0xffffffffu, vs, o);
    float rstd = rsqrtf(vs * (1.f/256.f) + 1e-5f);
#pragma unroll
    for (int i = 0; i < 8; i++) {
        int c = lane + i*32;
        h[off+c] = (v[i]-mean)*rstd*g[c] + bta[c];
    }
}

// ---------------- h_mean[b,d] = mean_n h[b,n,d] ----------------
__global__ void hmean_kernel(const float* __restrict__ h, float* __restrict__ hm)
{
    int b = blockIdx.x, d = threadIdx.x;
    const float* p = h + (size_t)b*Nn*Dd + d;
    float s = 0.f;
#pragma unroll 8
    for (int n = 0; n < Nn; n++) s += p[(size_t)n*Dd];
    hm[b*Dd + d] = s * (1.f/1024.f);
}

// ---------------- small row GEMM: C[b,:] = A[b,:Kd] @ W[Kd,Nd] (+bias,+relu) ----------------
template<int RELU>
__global__ void rowgemm_kernel(const float* __restrict__ A, const float* __restrict__ W,
                               const float* __restrict__ bias, float* __restrict__ C,
                               int Kd, int Nd)
{
    int b = blockIdx.x;
    __shared__ float xs[1024];
    for (int i = threadIdx.x; i < Kd; i += blockDim.x) xs[i] = A[(size_t)b*Kd + i];
    __syncthreads();
    for (int d = threadIdx.x; d < Nd; d += blockDim.x) {
        float acc = bias ? bias[d] : 0.f;
        for (int k = 0; k < Kd; k++) acc = fmaf(xs[k], W[(size_t)k*Nd + d], acc);
        if (RELU) acc = fmaxf(acc, 0.f);
        C[(size_t)b*Nd + d] = acc;
    }
}

// ---------------- scores[b,n] = dot(qv[b], kv[b,n]) / 16 ----------------
__global__ void scores_kernel(const float* __restrict__ qv, const float* __restrict__ kv,
                              float* __restrict__ scores)
{
    int b = blockIdx.y;
    int n = blockIdx.x*8 + (threadIdx.x >> 5);
    int lane = threadIdx.x & 31;
    const float* k = kv + ((size_t)b*Nn + n)*Dd;
    const float* q = qv + b*Dd;
    float s = 0.f;
#pragma unroll
    for (int i = 0; i < 8; i++) { int c = lane + i*32; s = fmaf(q[c], k[c], s); }
#pragma unroll
    for (int o = 16; o; o >>= 1) s += __shfl_xor_sync(0xffffffffu, s, o);
    if (lane == 0) scores[b*Nn + n] = s * (1.f/16.f);
}

// ---------------- finale: softmaxes + top-64 + sel, one block per batch ----------------
__global__ void finale_kernel(const float* __restrict__ scores, const float* __restrict__ gumbel,
                              const float* __restrict__ logits,
                              float* __restrict__ out_w, float* __restrict__ out_idx,
                              float* __restrict__ out_sel)
{
    int b = blockIdx.x, tid = threadIdx.x;
    __shared__ float w[1024];
    __shared__ float al[1024];
    __shared__ float red[256];
    __shared__ int   redi[256];
    __shared__ int   selidx[64];

    // ---- weights = softmax((scores+gumbel)/tau) ----
    float lm = -1e30f;
    for (int i = tid; i < 1024; i += 256) {
        float v = (scores[b*Nn+i] + gumbel[b*Nn+i]) * 2.0f;  // /tau, tau=0.5
        w[i] = v; lm = fmaxf(lm, v);
    }
    red[tid] = lm; __syncthreads();
    for (int s = 128; s; s >>= 1) { if (tid < s) red[tid] = fmaxf(red[tid], red[tid+s]); __syncthreads(); }
    float M = red[0]; __syncthreads();
    float ls = 0.f;
    for (int i = tid; i < 1024; i += 256) { float e = __expf(w[i]-M); w[i] = e; ls += e; }
    red[tid] = ls; __syncthreads();
    for (int s = 128; s; s >>= 1) { if (tid < s) red[tid] += red[tid+s]; __syncthreads(); }
    float invS = 1.f / red[0]; __syncthreads();
    for (int i = tid; i < 1024; i += 256) {
        float wi = w[i]*invS; w[i] = wi; out_w[b*Nn+i] = wi;
    }

    // ---- alloc = softmax(logits) ----
    lm = -1e30f;
    for (int i = tid; i < 1024; i += 256) { float v = logits[b*Nn+i]; al[i] = v; lm = fmaxf(lm, v); }
    __syncthreads();
    red[tid] = lm; __syncthreads();
    for (int s = 128; s; s >>= 1) { if (tid < s) red[tid] = fmaxf(red[tid], red[tid+s]); __syncthreads(); }
    M = red[0]; __syncthreads();
    ls = 0.f;
    for (int i = tid; i < 1024; i += 256) { float e = __expf(al[i]-M); al[i] = e; ls += e; }
    red[tid] = ls; __syncthreads();
    for (int s = 128; s; s >>= 1) { if (tid < s) red[tid] += red[tid+s]; __syncthreads(); }
    invS = 1.f / red[0]; __syncthreads();
    for (int i = tid; i < 1024; i += 256) al[i] *= invS;
    __syncthreads();

    // ---- top-64 iterative argmax (ties -> lowest index, matching lax.top_k) ----
    for (int kk = 0; kk < 64; kk++) {
        float bv = -1e30f; int bi = 0x7fffffff;
        for (int i = tid; i < 1024; i += 256) {
            float v = w[i];
            if (v > bv) { bv = v; bi = i; }      // strict > keeps lowest index on tie
        }
        red[tid] = bv; redi[tid] = bi; __syncthreads();
        for (int s = 128; s; s >>= 1) {
            if (tid < s) {
                float ov = red[tid+s]; int oi = redi[tid+s];
                if (ov > red[tid] || (ov == red[tid] && oi < redi[tid])) { red[tid] = ov; redi[tid] = oi; }
            }
            __syncthreads();
        }
        if (tid == 0) { selidx[kk] = redi[0]; w[redi[0]] = -2e30f; }
        __syncthreads();
    }

    // ---- sel = normalize(alloc[topk_idx]) ----
    float sv = 0.f;
    if (tid < 64) sv = al[selidx[tid]];
    red[tid] = (tid < 64) ? sv : 0.f; __syncthreads();
    for (int s = 128; s; s >>= 1) { if (tid < s) red[tid] += red[tid+s]; __syncthreads(); }
    float inv = 1.f / (red[0] + 1e-12f);
    if (tid < 64) {
        out_idx[b*64 + tid] = (float)selidx[tid];
        out_sel[b*64 + tid] = sv * inv;
    }
}

// ---------------- launch ----------------
extern "C" void kernel_launch(void* const* d_in, const int* in_sizes, int n_in,
                              void* d_out, int out_size)
{
    const float* x       = (const float*)d_in[0];
    const float* gumbel  = (const float*)d_in[1];
    const float* emb_W   = (const float*)d_in[2];
    const float* emb_b   = (const float*)d_in[3];
    const float* Wq      = (const float*)d_in[4];
    const float* Wk      = (const float*)d_in[5];
    const float* Wv      = (const float*)d_in[6];
    const float* Wo      = (const float*)d_in[7];
    const float* ln1_g   = (const float*)d_in[8];
    const float* ln1_b   = (const float*)d_in[9];
    const float* ln2_g   = (const float*)d_in[10];
    const float* ln2_b   = (const float*)d_in[11];
    const float* ffn_W1  = (const float*)d_in[12];
    const float* ffn_b1  = (const float*)d_in[13];
    const float* ffn_W2  = (const float*)d_in[14];
    const float* ffn_b2  = (const float*)d_in[15];
    const float* sha_Wq  = (const float*)d_in[16];
    const float* sha_Wk  = (const float*)d_in[17];
    const float* alloc_W1= (const float*)d_in[18];
    const float* alloc_b1= (const float*)d_in[19];
    const float* alloc_W2= (const float*)d_in[20];
    const float* alloc_b2= (const float*)d_in[21];

    float *h, *scr, *tmp, *hmean, *qv, *t1, *logits, *scores;
    cudaGetSymbolAddress((void**)&h,      g_h);
    cudaGetSymbolAddress((void**)&scr,    g_scr);
    cudaGetSymbolAddress((void**)&tmp,    g_tmp);
    cudaGetSymbolAddress((void**)&hmean,  g_hmean);
    cudaGetSymbolAddress((void**)&qv,     g_qv);
    cudaGetSymbolAddress((void**)&t1,     g_t1);
    cudaGetSymbolAddress((void**)&logits, g_logits);
    cudaGetSymbolAddress((void**)&scores, g_scores);

    float* q  = scr;
    float* k  = scr + (size_t)MM*Dd;
    float* v  = scr + (size_t)2*MM*Dd;
    float* ao = scr + (size_t)3*MM*Dd;

    // embedding
    embed_kernel<<<MM, 256>>>(x, emb_W, emb_b, h);

    const dim3 gP(Dd/128, MM/128);     // projection gemm grid (2,512)
    const dim3 gF1(DFF/128, MM/128);   // ffn1 grid (8,512)

    for (int i = 0; i < Ll; i++) {
        sgemm_kernel<0><<<gP, 256>>>(h, Wq + (size_t)i*Dd*Dd, nullptr, q, MM, Dd, Dd);
        sgemm_kernel<0><<<gP, 256>>>(h, Wk + (size_t)i*Dd*Dd, nullptr, k, MM, Dd, Dd);
        sgemm_kernel<0><<<gP, 256>>>(h, Wv + (size_t)i*Dd*Dd, nullptr, v, MM, Dd, Dd);
        attn_kernel<<<dim3(Nn/128, Hh, Bb), 128>>>(q, k, v, ao);
        sgemm_kernel<0><<<gP, 256>>>(ao, Wo + (size_t)i*Dd*Dd, nullptr, tmp, MM, Dd, Dd);
        ln_res_kernel<<<MM/8, 256>>>(h, tmp, ln1_g + i*Dd, ln1_b + i*Dd);
        sgemm_kernel<1><<<gF1, 256>>>(h, ffn_W1 + (size_t)i*Dd*DFF, ffn_b1 + i*DFF, scr, MM, DFF, Dd);
        sgemm_kernel<0><<<gP, 256>>>(scr, ffn_W2 + (size_t)i*DFF*Dd, ffn_b2 + i*Dd, tmp, MM, Dd, DFF);
        ln_res_kernel<<<MM/8, 256>>>(h, tmp, ln2_g + i*Dd, ln2_b + i*Dd);
    }

    // router head
    hmean_kernel<<<Bb, 256>>>(h, hmean);
    rowgemm_kernel<0><<<Bb, 256>>>(hmean, sha_Wq, nullptr, qv, Dd, Dd);
    sgemm_kernel<0><<<gP, 256>>>(h, sha_Wk, nullptr, tmp, MM, Dd, Dd);  // kv in tmp
    scores_kernel<<<dim3(Nn/8, Bb), 256>>>(qv, tmp, scores);
    rowgemm_kernel<1><<<Bb, 256>>>(hmean, alloc_W1, alloc_b1, t1, Dd, Dd);
    rowgemm_kernel<0><<<Bb, 256>>>(t1, alloc_W2, alloc_b2, logits, Dd, Nn);

    float* out = (float*)d_out;
    finale_kernel<<<Bb, 256>>>(scores, gumbel, logits,
                               out,                 // weights  [64*1024]
                               out + Bb*Nn,         // topk_idx [64*64] (as float)
                               out + Bb*Nn + Bb*Kk  // sel      [64*64]
                               );
}

// round 2
// speedup vs baseline: 1.2949x; 1.2949x over previous
#include <cuda_runtime.h>
#include <cstdint>

// ---------------- problem dims ----------------
#define Bb 64
#define Nn 1024
#define Din 16
#define Dd 256
#define Hh 4
#define DH 64
#define Ll 3
#define DFF 1024
#define Kk 64
#define MM (Bb*Nn)          // 65536 rows

// ---------------- scratch (static device memory; no allocs allowed) ----------------
__device__ float g_h[MM*Dd];            // 64 MB   hidden state
__device__ float g_scr[MM*DFF];         // 256 MB  q|k|v|attn_out, or ffn hidden
__device__ float g_tmp[MM*Dd];          // 64 MB   proj out / ffn out / kv
__device__ float g_hmean[Bb*Dd];
__device__ float g_qv[Bb*Dd];
__device__ float g_t1[Bb*Dd];
__device__ float g_logits[Bb*Nn];
__device__ float g_scores[Bb*Nn];

// ---------------- embedding: h = x @ emb_W + emb_b ----------------
__global__ void embed_kernel(const float* __restrict__ x, const float* __restrict__ W,
                             const float* __restrict__ b, float* __restrict__ h)
{
    int m = blockIdx.x;            // row
    int d = threadIdx.x;           // 256 threads
    __shared__ float xs[Din];
    if (threadIdx.x < Din) xs[threadIdx.x] = x[m*Din + threadIdx.x];
    __syncthreads();
    float acc = b[d];
#pragma unroll
    for (int k = 0; k < Din; k++) acc = fmaf(xs[k], W[k*Dd + d], acc);
    h[(size_t)m*Dd + d] = acc;
}

// ---------------- TF32 tensor-core GEMM ----------------
// C[M,N] = A[M,K] @ W[K,N] (+bias, +relu)
// 128x128 tile, BK=16, 256 threads (8 warps), warp tile 32x64 via m16n8k8.tf32
__device__ __forceinline__ uint32_t f2tf32(float f) {
    uint32_t r;
    asm("cvt.rna.tf32.f32 %0, %1;" : "=r"(r) : "f"(f));
    return r;
}

__device__ __forceinline__ void mma_tf32(float* c, const uint32_t* a, const uint32_t* b) {
    asm volatile(
        "mma.sync.aligned.m16n8k8.row.col.f32.tf32.tf32.f32 "
        "{%0,%1,%2,%3}, {%4,%5,%6,%7}, {%8,%9}, {%0,%1,%2,%3};"
        : "+f"(c[0]), "+f"(c[1]), "+f"(c[2]), "+f"(c[3])
        : "r"(a[0]), "r"(a[1]), "r"(a[2]), "r"(a[3]), "r"(b[0]), "r"(b[1]));
}

#define AS_STRIDE 20   // 128 rows x (16 k + pad) -> conflict-free fragment reads
#define BS_STRIDE 136  // 16 k-rows x (128 n + pad)

template<int RELU>
__global__ __launch_bounds__(256, 2) void tgemm_kernel(
    const float* __restrict__ A, const float* __restrict__ W,
    const float* __restrict__ bias, float* __restrict__ C,
    int M, int Nd, int Kd)
{
    __shared__ __align__(16) float As[128*AS_STRIDE];
    __shared__ __align__(16) float Bs[16*BS_STRIDE];

    const int tid = threadIdx.x;
    const int warp = tid >> 5;
    const int lane = tid & 31;
    const int bm = blockIdx.y, bn = blockIdx.x;
    const int wm = warp & 3;          // 4 m-warps * 32 rows
    const int wn = warp >> 2;         // 2 n-warps * 64 cols
    const int qid = lane >> 2;        // 0..7
    const int tig = lane & 3;         // 0..3

    // global load coords
    // A tile: 128 rows x 16 k-cols = 512 float4; thread loads idx = tid, tid+256
    const int a_r0 = tid >> 2,  a_c0 = (tid & 3) << 2;          // idx = tid
    const int a_r1 = a_r0 + 64;                                 // idx = tid+256
    // B tile: 16 k-rows x 128 n-cols = 512 float4
    const int b_r0 = tid >> 5,  b_c0 = (tid & 31) << 2;
    const int b_r1 = b_r0 + 8;

    const float* Ap = A + (size_t)(bm*128)*Kd;
    const float* Wp = W + (size_t)bn*128;

    float acc[2][8][4];
#pragma unroll
    for (int mt = 0; mt < 2; mt++)
#pragma unroll
        for (int nt = 0; nt < 8; nt++)
#pragma unroll
            for (int i = 0; i < 4; i++) acc[mt][nt][i] = 0.f;

    float4 avr0 = *(const float4*)(Ap + (size_t)a_r0*Kd + a_c0);
    float4 avr1 = *(const float4*)(Ap + (size_t)a_r1*Kd + a_c0);
    float4 bvr0 = *(const float4*)(Wp + (size_t)b_r0*Nd + b_c0);
    float4 bvr1 = *(const float4*)(Wp + (size_t)b_r1*Nd + b_c0);

    const int niter = Kd >> 4;
    for (int it = 0; it < niter; it++) {
        // store (converted to tf32 bit patterns)
        {
            uint32_t t0 = f2tf32(avr0.x), t1 = f2tf32(avr0.y), t2 = f2tf32(avr0.z), t3 = f2tf32(avr0.w);
            uint32_t* p = (uint32_t*)&As[a_r0*AS_STRIDE + a_c0];
            p[0]=t0; p[1]=t1; p[2]=t2; p[3]=t3;
            t0 = f2tf32(avr1.x); t1 = f2tf32(avr1.y); t2 = f2tf32(avr1.z); t3 = f2tf32(avr1.w);
            p = (uint32_t*)&As[a_r1*AS_STRIDE + a_c0];
            p[0]=t0; p[1]=t1; p[2]=t2; p[3]=t3;
            t0 = f2tf32(bvr0.x); t1 = f2tf32(bvr0.y); t2 = f2tf32(bvr0.z); t3 = f2tf32(bvr0.w);
            p = (uint32_t*)&Bs[b_r0*BS_STRIDE + b_c0];
            p[0]=t0; p[1]=t1; p[2]=t2; p[3]=t3;
            t0 = f2tf32(bvr1.x); t1 = f2tf32(bvr1.y); t2 = f2tf32(bvr1.z); t3 = f2tf32(bvr1.w);
            p = (uint32_t*)&Bs[b_r1*BS_STRIDE + b_c0];
            p[0]=t0; p[1]=t1; p[2]=t2; p[3]=t3;
        }
        __syncthreads();

        if (it + 1 < niter) {
            const float* Ap2 = Ap + (it+1)*16;
            const float* Wp2 = Wp + (size_t)(it+1)*16*Nd;
            avr0 = *(const float4*)(Ap2 + (size_t)a_r0*Kd + a_c0);
            avr1 = *(const float4*)(Ap2 + (size_t)a_r1*Kd + a_c0);
            bvr0 = *(const float4*)(Wp2 + (size_t)b_r0*Nd + b_c0);
            bvr1 = *(const float4*)(Wp2 + (size_t)b_r1*Nd + b_c0);
        }

        const uint32_t* Asu = (const uint32_t*)As;
        const uint32_t* Bsu = (const uint32_t*)Bs;
#pragma unroll
        for (int ks = 0; ks < 2; ks++) {
            const int ka = ks*8 + tig;
            uint32_t afrag[2][4];
#pragma unroll
            for (int mt = 0; mt < 2; mt++) {
                int r = wm*32 + mt*16 + qid;
                afrag[mt][0] = Asu[r*AS_STRIDE + ka];
                afrag[mt][1] = Asu[(r+8)*AS_STRIDE + ka];
                afrag[mt][2] = Asu[r*AS_STRIDE + ka + 4];
                afrag[mt][3] = Asu[(r+8)*AS_STRIDE + ka + 4];
            }
#pragma unroll
            for (int nt = 0; nt < 8; nt++) {
                int cn = wn*64 + nt*8 + qid;
                uint32_t bfrag[2];
                bfrag[0] = Bsu[(ks*8 + tig)*BS_STRIDE + cn];
                bfrag[1] = Bsu[(ks*8 + tig + 4)*BS_STRIDE + cn];
#pragma unroll
                for (int mt = 0; mt < 2; mt++)
                    mma_tf32(acc[mt][nt], afrag[mt], bfrag);
            }
        }
        __syncthreads();
    }

    // epilogue
#pragma unroll
    for (int mt = 0; mt < 2; mt++) {
        int r0 = bm*128 + wm*32 + mt*16 + qid;
#pragma unroll
        for (int nt = 0; nt < 8; nt++) {
            int c0 = bn*128 + wn*64 + nt*8 + tig*2;
            float b0 = bias ? bias[c0]   : 0.f;
            float b1 = bias ? bias[c0+1] : 0.f;
            float v0 = acc[mt][nt][0] + b0, v1 = acc[mt][nt][1] + b1;
            float v2 = acc[mt][nt][2] + b0, v3 = acc[mt][nt][3] + b1;
            if (RELU) {
                v0 = fmaxf(v0, 0.f); v1 = fmaxf(v1, 0.f);
                v2 = fmaxf(v2, 0.f); v3 = fmaxf(v3, 0.f);
            }
            float2 p0; p0.x = v0; p0.y = v1;
            float2 p1; p1.x = v2; p1.y = v3;
            *(float2*)&C[(size_t)r0*Nd + c0]     = p0;
            *(float2*)&C[(size_t)(r0+8)*Nd + c0] = p1;
        }
    }
}

// ---------------- fused flash attention (fp32, online softmax) ----------------
__global__ __launch_bounds__(128) void attn_kernel(
    const float* __restrict__ Q, const float* __restrict__ Kg,
    const float* __restrict__ V, float* __restrict__ O)
{
    __shared__ float Ks[64][64];
    __shared__ float Vs[64][64];
    const int qt = blockIdx.x, head = blockIdx.y, b = blockIdx.z;
    const int tid = threadIdx.x;
    const size_t base = ((size_t)b*Nn)*Dd + head*DH;
    const int qrow = qt*128 + tid;

    float q[64];
    const float* qp = Q + base + (size_t)qrow*Dd;
#pragma unroll
    for (int d = 0; d < 64; d += 4) {
        float4 t = *(const float4*)(qp + d);
        q[d] = t.x; q[d+1] = t.y; q[d+2] = t.z; q[d+3] = t.w;
    }
    const float scale = 0.125f;   // 1/sqrt(64)
    float m = -1e30f, l = 0.f;
    float o[64];
#pragma unroll
    for (int d = 0; d < 64; d++) o[d] = 0.f;

    for (int j0 = 0; j0 < Nn; j0 += 64) {
        for (int t = tid; t < 1024; t += 128) {
            int r = t >> 4, c = (t & 15) << 2;
            *(float4*)&Ks[r][c] = *(const float4*)(Kg + base + (size_t)(j0+r)*Dd + c);
            *(float4*)&Vs[r][c] = *(const float4*)(V  + base + (size_t)(j0+r)*Dd + c);
        }
        __syncthreads();
#pragma unroll
        for (int jj = 0; jj < 64; jj += 16) {
            float s[16];
#pragma unroll
            for (int j = 0; j < 16; j++) {
                float acc = 0.f;
#pragma unroll
                for (int d = 0; d < 64; d++) acc = fmaf(q[d], Ks[jj+j][d], acc);
                s[j] = acc * scale;
            }
            float mloc = m;
#pragma unroll
            for (int j = 0; j < 16; j++) mloc = fmaxf(mloc, s[j]);
            float corr = __expf(m - mloc);
            m = mloc;
            l *= corr;
#pragma unroll
            for (int d = 0; d < 64; d++) o[d] *= corr;
#pragma unroll
            for (int j = 0; j < 16; j++) {
                float p = __expf(s[j] - m);
                l += p;
#pragma unroll
                for (int d = 0; d < 64; d++) o[d] = fmaf(p, Vs[jj+j][d], o[d]);
            }
        }
        __syncthreads();
    }
    float invl = 1.f / l;
    float* op = O + base + (size_t)qrow*Dd;
#pragma unroll
    for (int d = 0; d < 64; d += 4) {
        float4 t;
        t.x = o[d]*invl; t.y = o[d+1]*invl; t.z = o[d+2]*invl; t.w = o[d+3]*invl;
        *(float4*)(op + d) = t;
    }
}

// ---------------- LayerNorm(h + res) in place, warp-per-row ----------------
__global__ void ln_res_kernel(float* __restrict__ h, const float* __restrict__ res,
                              const float* __restrict__ g, const float* __restrict__ bta)
{
    int row = blockIdx.x*8 + (threadIdx.x >> 5);
    int lane = threadIdx.x & 31;
    size_t off = (size_t)row * Dd;
    float v[8];
    float s = 0.f;
#pragma unroll
    for (int i = 0; i < 8; i++) {
        int c = lane + i*32;
        v[i] = h[off+c] + res[off+c];
        s += v[i];
    }
#pragma unroll
    for (int o = 16; o; o >>= 1) s += __shfl_xor_sync(0xffffffffu, s, o);
    float mean = s * (1.f/256.f);
    float vs = 0.f;
#pragma unroll
    for (int i = 0; i < 8; i++) { float d = v[i]-mean; vs = fmaf(d, d, vs); }
#pragma unroll
    for (int o = 16; o; o >>= 1) vs += __shfl_xor_sync(0xffffffffu, vs, o);
    float rstd = rsqrtf(vs * (1.f/256.f) + 1e-5f);
#pragma unroll
    for (int i = 0; i < 8; i++) {
        int c = lane + i*32;
        h[off+c] = (v[i]-mean)*rstd*g[c] + bta[c];
    }
}

// ---------------- h_mean[b,d] = mean_n h[b,n,d] ----------------
__global__ void hmean_kernel(const float* __restrict__ h, float* __restrict__ hm)
{
    int b = blockIdx.x, d = threadIdx.x;
    const float* p = h + (size_t)b*Nn*Dd + d;
    float s = 0.f;
#pragma unroll 8
    for (int n = 0; n < Nn; n++) s += p[(size_t)n*Dd];
    hm[b*Dd + d] = s * (1.f/1024.f);
}

// ---------------- small row GEMM: C[b,:] = A[b,:Kd] @ W[Kd,Nd] (+bias,+relu) ----------------
template<int RELU>
__global__ void rowgemm_kernel(const float* __restrict__ A, const float* __restrict__ W,
                               const float* __restrict__ bias, float* __restrict__ C,
                               int Kd, int Nd)
{
    int b = blockIdx.x;
    __shared__ float xs[1024];
    for (int i = threadIdx.x; i < Kd; i += blockDim.x) xs[i] = A[(size_t)b*Kd + i];
    __syncthreads();
    for (int d = threadIdx.x; d < Nd; d += blockDim.x) {
        float acc = bias ? bias[d] : 0.f;
        for (int k = 0; k < Kd; k++) acc = fmaf(xs[k], W[(size_t)k*Nd + d], acc);
        if (RELU) acc = fmaxf(acc, 0.f);
        C[(size_t)b*Nd + d] = acc;
    }
}

// ---------------- scores[b,n] = dot(qv[b], kv[b,n]) / 16 ----------------
__global__ void scores_kernel(const float* __restrict__ qv, const float* __restrict__ kv,
                              float* __restrict__ scores)
{
    int b = blockIdx.y;
    int n = blockIdx.x*8 + (threadIdx.x >> 5);
    int lane = threadIdx.x & 31;
    const float* k = kv + ((size_t)b*Nn + n)*Dd;
    const float* q = qv + b*Dd;
    float s = 0.f;
#pragma unroll
    for (int i = 0; i < 8; i++) { int c = lane + i*32; s = fmaf(q[c], k[c], s); }
#pragma unroll
    for (int o = 16; o; o >>= 1) s += __shfl_xor_sync(0xffffffffu, s, o);
    if (lane == 0) scores[b*Nn + n] = s * (1.f/16.f);
}

// ---------------- finale: softmaxes + top-64 + sel, one block per batch ----------------
__global__ void finale_kernel(const float* __restrict__ scores, const float* __restrict__ gumbel,
                              const float* __restrict__ logits,
                              float* __restrict__ out_w, float* __restrict__ out_idx,
                              float* __restrict__ out_sel)
{
    int b = blockIdx.x, tid = threadIdx.x;
    __shared__ float w[1024];
    __shared__ float al[1024];
    __shared__ float red[256];
    __shared__ int   redi[256];
    __shared__ int   selidx[64];

    // ---- weights = softmax((scores+gumbel)/tau) ----
    float lm = -1e30f;
    for (int i = tid; i < 1024; i += 256) {
        float v = (scores[b*Nn+i] + gumbel[b*Nn+i]) * 2.0f;  // /tau, tau=0.5
        w[i] = v; lm = fmaxf(lm, v);
    }
    red[tid] = lm; __syncthreads();
    for (int s = 128; s; s >>= 1) { if (tid < s) red[tid] = fmaxf(red[tid], red[tid+s]); __syncthreads(); }
    float M = red[0]; __syncthreads();
    float ls = 0.f;
    for (int i = tid; i < 1024; i += 256) { float e = __expf(w[i]-M); w[i] = e; ls += e; }
    red[tid] = ls; __syncthreads();
    for (int s = 128; s; s >>= 1) { if (tid < s) red[tid] += red[tid+s]; __syncthreads(); }
    float invS = 1.f / red[0]; __syncthreads();
    for (int i = tid; i < 1024; i += 256) {
        float wi = w[i]*invS; w[i] = wi; out_w[b*Nn+i] = wi;
    }

    // ---- alloc = softmax(logits) ----
    lm = -1e30f;
    for (int i = tid; i < 1024; i += 256) { float v = logits[b*Nn+i]; al[i] = v; lm = fmaxf(lm, v); }
    __syncthreads();
    red[tid] = lm; __syncthreads();
    for (int s = 128; s; s >>= 1) { if (tid < s) red[tid] = fmaxf(red[tid], red[tid+s]); __syncthreads(); }
    M = red[0]; __syncthreads();
    ls = 0.f;
    for (int i = tid; i < 1024; i += 256) { float e = __expf(al[i]-M); al[i] = e; ls += e; }
    red[tid] = ls; __syncthreads();
    for (int s = 128; s; s >>= 1) { if (tid < s) red[tid] += red[tid+s]; __syncthreads(); }
    invS = 1.f / red[0]; __syncthreads();
    for (int i = tid; i < 1024; i += 256) al[i] *= invS;
    __syncthreads();

    // ---- top-64 iterative argmax (ties -> lowest index, matching lax.top_k) ----
    for (int kk = 0; kk < 64; kk++) {
        float bv = -1e30f; int bi = 0x7fffffff;
        for (int i = tid; i < 1024; i += 256) {
            float v = w[i];
            if (v > bv) { bv = v; bi = i; }      // strict > keeps lowest index on tie
        }
        red[tid] = bv; redi[tid] = bi; __syncthreads();
        for (int s = 128; s; s >>= 1) {
            if (tid < s) {
                float ov = red[tid+s]; int oi = redi[tid+s];
                if (ov > red[tid] || (ov == red[tid] && oi < redi[tid])) { red[tid] = ov; redi[tid] = oi; }
            }
            __syncthreads();
        }
        if (tid == 0) { selidx[kk] = redi[0]; w[redi[0]] = -2e30f; }
        __syncthreads();
    }

    // ---- sel = normalize(alloc[topk_idx]) ----
    float sv = 0.f;
    if (tid < 64) sv = al[selidx[tid]];
    red[tid] = (tid < 64) ? sv : 0.f; __syncthreads();
    for (int s = 128; s; s >>= 1) { if (tid < s) red[tid] += red[tid+s]; __syncthreads(); }
    float inv = 1.f / (red[0] + 1e-12f);
    if (tid < 64) {
        out_idx[b*64 + tid] = (float)selidx[tid];
        out_sel[b*64 + tid] = sv * inv;
    }
}

// ---------------- launch ----------------
extern "C" void kernel_launch(void* const* d_in, const int* in_sizes, int n_in,
                              void* d_out, int out_size)
{
    const float* x       = (const float*)d_in[0];
    const float* gumbel  = (const float*)d_in[1];
    const float* emb_W   = (const float*)d_in[2];
    const float* emb_b   = (const float*)d_in[3];
    const float* Wq      = (const float*)d_in[4];
    const float* Wk      = (const float*)d_in[5];
    const float* Wv      = (const float*)d_in[6];
    const float* Wo      = (const float*)d_in[7];
    const float* ln1_g   = (const float*)d_in[8];
    const float* ln1_b   = (const float*)d_in[9];
    const float* ln2_g   = (const float*)d_in[10];
    const float* ln2_b   = (const float*)d_in[11];
    const float* ffn_W1  = (const float*)d_in[12];
    const float* ffn_b1  = (const float*)d_in[13];
    const float* ffn_W2  = (const float*)d_in[14];
    const float* ffn_b2  = (const float*)d_in[15];
    const float* sha_Wq  = (const float*)d_in[16];
    const float* sha_Wk  = (const float*)d_in[17];
    const float* alloc_W1= (const float*)d_in[18];
    const float* alloc_b1= (const float*)d_in[19];
    const float* alloc_W2= (const float*)d_in[20];
    const float* alloc_b2= (const float*)d_in[21];

    float *h, *scr, *tmp, *hmean, *qv, *t1, *logits, *scores;
    cudaGetSymbolAddress((void**)&h,      g_h);
    cudaGetSymbolAddress((void**)&scr,    g_scr);
    cudaGetSymbolAddress((void**)&tmp,    g_tmp);
    cudaGetSymbolAddress((void**)&hmean,  g_hmean);
    cudaGetSymbolAddress((void**)&qv,     g_qv);
    cudaGetSymbolAddress((void**)&t1,     g_t1);
    cudaGetSymbolAddress((void**)&logits, g_logits);
    cudaGetSymbolAddress((void**)&scores, g_scores);

    float* q  = scr;
    float* k  = scr + (size_t)MM*Dd;
    float* v  = scr + (size_t)2*MM*Dd;
    float* ao = scr + (size_t)3*MM*Dd;

    // embedding
    embed_kernel<<<MM, 256>>>(x, emb_W, emb_b, h);

    const dim3 gP(Dd/128, MM/128);     // projection gemm grid (2,512)
    const dim3 gF1(DFF/128, MM/128);   // ffn1 grid (8,512)

    for (int i = 0; i < Ll; i++) {
        tgemm_kernel<0><<<gP, 256>>>(h, Wq + (size_t)i*Dd*Dd, nullptr, q, MM, Dd, Dd);
        tgemm_kernel<0><<<gP, 256>>>(h, Wk + (size_t)i*Dd*Dd, nullptr, k, MM, Dd, Dd);
        tgemm_kernel<0><<<gP, 256>>>(h, Wv + (size_t)i*Dd*Dd, nullptr, v, MM, Dd, Dd);
        attn_kernel<<<dim3(Nn/128, Hh, Bb), 128>>>(q, k, v, ao);
        tgemm_kernel<0><<<gP, 256>>>(ao, Wo + (size_t)i*Dd*Dd, nullptr, tmp, MM, Dd, Dd);
        ln_res_kernel<<<MM/8, 256>>>(h, tmp, ln1_g + i*Dd, ln1_b + i*Dd);
        tgemm_kernel<1><<<gF1, 256>>>(h, ffn_W1 + (size_t)i*Dd*DFF, ffn_b1 + i*DFF, scr, MM, DFF, Dd);
        tgemm_kernel<0><<<gP, 256>>>(scr, ffn_W2 + (size_t)i*DFF*Dd, ffn_b2 + i*Dd, tmp, MM, Dd, DFF);
        ln_res_kernel<<<MM/8, 256>>>(h, tmp, ln2_g + i*Dd, ln2_b + i*Dd);
    }

    // router head
    hmean_kernel<<<Bb, 256>>>(h, hmean);
    rowgemm_kernel<0><<<Bb, 256>>>(hmean, sha_Wq, nullptr, qv, Dd, Dd);
    tgemm_kernel<0><<<gP, 256>>>(h, sha_Wk, nullptr, tmp, MM, Dd, Dd);  // kv in tmp
    scores_kernel<<<dim3(Nn/8, Bb), 256>>>(qv, tmp, scores);
    rowgemm_kernel<1><<<Bb, 256>>>(hmean, alloc_W1, alloc_b1, t1, Dd, Dd);
    rowgemm_kernel<0><<<Bb, 256>>>(t1, alloc_W2, alloc_b2, logits, Dd, Nn);

    float* out = (float*)d_out;
    finale_kernel<<<Bb, 256>>>(scores, gumbel, logits,
                               out,                 // weights  [64*1024]
                               out + Bb*Nn,         // topk_idx [64*64] (as float)
                               out + Bb*Nn + Bb*Kk  // sel      [64*64]
                               );
}

// round 3
// speedup vs baseline: 4.1079x; 3.1723x over previous
#include <cuda_runtime.h>
#include <cstdint>

// ---------------- problem dims ----------------
#define Bb 64
#define Nn 1024
#define Din 16
#define Dd 256
#define Hh 4
#define DH 64
#define Ll 3
#define DFF 1024
#define Kk 64
#define MM (Bb*Nn)          // 65536 rows

// ---------------- scratch (static device memory; no allocs allowed) ----------------
__device__ float g_h[MM*Dd];
__device__ float g_scr[MM*DFF];
__device__ float g_tmp[MM*Dd];
__device__ float g_hmean[Bb*Dd];
__device__ float g_qv[Bb*Dd];
__device__ float g_t1[Bb*Dd];
__device__ float g_logits[Bb*Nn];
__device__ float g_scores[Bb*Nn];

__device__ __forceinline__ uint32_t f2tf32(float f) {
    uint32_t r;
    asm("cvt.rna.tf32.f32 %0, %1;" : "=r"(r) : "f"(f));
    return r;
}

__device__ __forceinline__ void mma_tf32(float* c, const uint32_t* a, const uint32_t* b) {
    asm volatile(
        "mma.sync.aligned.m16n8k8.row.col.f32.tf32.tf32.f32 "
        "{%0,%1,%2,%3}, {%4,%5,%6,%7}, {%8,%9}, {%0,%1,%2,%3};"
        : "+f"(c[0]), "+f"(c[1]), "+f"(c[2]), "+f"(c[3])
        : "r"(a[0]), "r"(a[1]), "r"(a[2]), "r"(a[3]), "r"(b[0]), "r"(b[1]));
}

// ---------------- embedding ----------------
__global__ void embed_kernel(const float* __restrict__ x, const float* __restrict__ W,
                             const float* __restrict__ b, float* __restrict__ h)
{
    int m = blockIdx.x;
    int d = threadIdx.x;
    __shared__ float xs[Din];
    if (threadIdx.x < Din) xs[threadIdx.x] = x[m*Din + threadIdx.x];
    __syncthreads();
    float acc = b[d];
#pragma unroll
    for (int k = 0; k < Din; k++) acc = fmaf(xs[k], W[k*Dd + d], acc);
    h[(size_t)m*Dd + d] = acc;
}

// ---------------- TF32 tensor-core GEMM, double-buffered ----------------
#define AS_STRIDE 20
#define BS_STRIDE 136

template<int RELU>
__global__ __launch_bounds__(256, 2) void tgemm_kernel(
    const float* __restrict__ A, const float* __restrict__ W,
    const float* __restrict__ bias, float* __restrict__ C,
    int M, int Nd, int Kd)
{
    __shared__ __align__(16) float As[2][128*AS_STRIDE];
    __shared__ __align__(16) float Bs[2][16*BS_STRIDE];

    const int tid = threadIdx.x;
    const int warp = tid >> 5;
    const int lane = tid & 31;
    const int bm = blockIdx.y, bn = blockIdx.x;
    const int wm = warp & 3;
    const int wn = warp >> 2;
    const int qid = lane >> 2;
    const int tig = lane & 3;

    const int a_r0 = tid >> 2,  a_c0 = (tid & 3) << 2;
    const int a_r1 = a_r0 + 64;
    const int b_r0 = tid >> 5,  b_c0 = (tid & 31) << 2;
    const int b_r1 = b_r0 + 8;

    const float* Ap = A + (size_t)(bm*128)*Kd;
    const float* Wp = W + (size_t)bn*128;

    float acc[2][8][4];
#pragma unroll
    for (int mt = 0; mt < 2; mt++)
#pragma unroll
        for (int nt = 0; nt < 8; nt++)
#pragma unroll
            for (int i = 0; i < 4; i++) acc[mt][nt][i] = 0.f;

    float4 avr0 = *(const float4*)(Ap + (size_t)a_r0*Kd + a_c0);
    float4 avr1 = *(const float4*)(Ap + (size_t)a_r1*Kd + a_c0);
    float4 bvr0 = *(const float4*)(Wp + (size_t)b_r0*Nd + b_c0);
    float4 bvr1 = *(const float4*)(Wp + (size_t)b_r1*Nd + b_c0);

    // store tile 0 into buffer 0
    {
        uint32_t* p = (uint32_t*)&As[0][a_r0*AS_STRIDE + a_c0];
        p[0]=f2tf32(avr0.x); p[1]=f2tf32(avr0.y); p[2]=f2tf32(avr0.z); p[3]=f2tf32(avr0.w);
        p = (uint32_t*)&As[0][a_r1*AS_STRIDE + a_c0];
        p[0]=f2tf32(avr1.x); p[1]=f2tf32(avr1.y); p[2]=f2tf32(avr1.z); p[3]=f2tf32(avr1.w);
        p = (uint32_t*)&Bs[0][b_r0*BS_STRIDE + b_c0];
        p[0]=f2tf32(bvr0.x); p[1]=f2tf32(bvr0.y); p[2]=f2tf32(bvr0.z); p[3]=f2tf32(bvr0.w);
        p = (uint32_t*)&Bs[0][b_r1*BS_STRIDE + b_c0];
        p[0]=f2tf32(bvr1.x); p[1]=f2tf32(bvr1.y); p[2]=f2tf32(bvr1.z); p[3]=f2tf32(bvr1.w);
    }
    __syncthreads();

    const int niter = Kd >> 4;
    int buf = 0;
    for (int it = 0; it < niter; it++) {
        if (it + 1 < niter) {
            const float* Ap2 = Ap + (it+1)*16;
            const float* Wp2 = Wp + (size_t)(it+1)*16*Nd;
            avr0 = *(const float4*)(Ap2 + (size_t)a_r0*Kd + a_c0);
            avr1 = *(const float4*)(Ap2 + (size_t)a_r1*Kd + a_c0);
            bvr0 = *(const float4*)(Wp2 + (size_t)b_r0*Nd + b_c0);
            bvr1 = *(const float4*)(Wp2 + (size_t)b_r1*Nd + b_c0);
        }

        const uint32_t* Asu = (const uint32_t*)As[buf];
        const uint32_t* Bsu = (const uint32_t*)Bs[buf];
#pragma unroll
        for (int ks = 0; ks < 2; ks++) {
            const int ka = ks*8 + tig;
            uint32_t afrag[2][4];
#pragma unroll
            for (int mt = 0; mt < 2; mt++) {
                int r = wm*32 + mt*16 + qid;
                afrag[mt][0] = Asu[r*AS_STRIDE + ka];
                afrag[mt][1] = Asu[(r+8)*AS_STRIDE + ka];
                afrag[mt][2] = Asu[r*AS_STRIDE + ka + 4];
                afrag[mt][3] = Asu[(r+8)*AS_STRIDE + ka + 4];
            }
#pragma unroll
            for (int nt = 0; nt < 8; nt++) {
                int cn = wn*64 + nt*8 + qid;
                uint32_t bfrag[2];
                bfrag[0] = Bsu[(ks*8 + tig)*BS_STRIDE + cn];
                bfrag[1] = Bsu[(ks*8 + tig + 4)*BS_STRIDE + cn];
#pragma unroll
                for (int mt = 0; mt < 2; mt++)
                    mma_tf32(acc[mt][nt], afrag[mt], bfrag);
            }
        }

        if (it + 1 < niter) {
            int nb = buf ^ 1;
            uint32_t* p = (uint32_t*)&As[nb][a_r0*AS_STRIDE + a_c0];
            p[0]=f2tf32(avr0.x); p[1]=f2tf32(avr0.y); p[2]=f2tf32(avr0.z); p[3]=f2tf32(avr0.w);
            p = (uint32_t*)&As[nb][a_r1*AS_STRIDE + a_c0];
            p[0]=f2tf32(avr1.x); p[1]=f2tf32(avr1.y); p[2]=f2tf32(avr1.z); p[3]=f2tf32(avr1.w);
            p = (uint32_t*)&Bs[nb][b_r0*BS_STRIDE + b_c0];
            p[0]=f2tf32(bvr0.x); p[1]=f2tf32(bvr0.y); p[2]=f2tf32(bvr0.z); p[3]=f2tf32(bvr0.w);
            p = (uint32_t*)&Bs[nb][b_r1*BS_STRIDE + b_c0];
            p[0]=f2tf32(bvr1.x); p[1]=f2tf32(bvr1.y); p[2]=f2tf32(bvr1.z); p[3]=f2tf32(bvr1.w);
            __syncthreads();
            buf = nb;
        }
    }

    // epilogue
#pragma unroll
    for (int mt = 0; mt < 2; mt++) {
        int r0 = bm*128 + wm*32 + mt*16 + qid;
#pragma unroll
        for (int nt = 0; nt < 8; nt++) {
            int c0 = bn*128 + wn*64 + nt*8 + tig*2;
            float b0 = bias ? bias[c0]   : 0.f;
            float b1 = bias ? bias[c0+1] : 0.f;
            float v0 = acc[mt][nt][0] + b0, v1 = acc[mt][nt][1] + b1;
            float v2 = acc[mt][nt][2] + b0, v3 = acc[mt][nt][3] + b1;
            if (RELU) {
                v0 = fmaxf(v0, 0.f); v1 = fmaxf(v1, 0.f);
                v2 = fmaxf(v2, 0.f); v3 = fmaxf(v3, 0.f);
            }
            float2 p0; p0.x = v0; p0.y = v1;
            float2 p1; p1.x = v2; p1.y = v3;
            *(float2*)&C[(size_t)r0*Nd + c0]     = p0;
            *(float2*)&C[(size_t)(r0+8)*Nd + c0] = p1;
        }
    }
}

// ---------------- tensor-core flash attention (tf32 MMA) ----------------
// grid (8, H, B); 256 threads = 8 warps; warp owns 16 q-rows.
// smem layout (uint32 tf32): Ks[64*72] | Vs[64*72] | Ps[warp][16*72]
#define ATS 72
#define ATT_SMEM (256*ATS*4)

__global__ void __launch_bounds__(256) attn_mma_kernel(
    const float* __restrict__ Q, const float* __restrict__ Kg,
    const float* __restrict__ V, float* __restrict__ O)
{
    extern __shared__ uint32_t sm[];
    uint32_t* Ks = sm;
    uint32_t* Vs = sm + 64*ATS;
    const int tid = threadIdx.x;
    const int warp = tid >> 5, lane = tid & 31;
    const int qid = lane >> 2, tig = lane & 3;
    uint32_t* Ps = sm + 128*ATS + warp*16*ATS;

    const int qt = blockIdx.x, head = blockIdx.y, b = blockIdx.z;
    const size_t base = ((size_t)b*Nn)*Dd + head*DH;
    const int q0 = qt*128 + warp*16;

    // Q fragments, scale folded in
    uint32_t qa[8][4];
    const float scale = 0.125f;
#pragma unroll
    for (int s = 0; s < 8; s++) {
        int d0 = s*8;
        qa[s][0] = f2tf32(scale * Q[base + (size_t)(q0+qid  )*Dd + d0+tig  ]);
        qa[s][1] = f2tf32(scale * Q[base + (size_t)(q0+qid+8)*Dd + d0+tig  ]);
        qa[s][2] = f2tf32(scale * Q[base + (size_t)(q0+qid  )*Dd + d0+tig+4]);
        qa[s][3] = f2tf32(scale * Q[base + (size_t)(q0+qid+8)*Dd + d0+tig+4]);
    }

    float oacc[8][4];
#pragma unroll
    for (int dn = 0; dn < 8; dn++)
#pragma unroll
        for (int i = 0; i < 4; i++) oacc[dn][i] = 0.f;
    float m0 = -1e30f, m1 = -1e30f, l0 = 0.f, l1 = 0.f;

    const int lr = tid >> 4;           // 0..15
    const int lc = (tid & 15) << 2;    // 0..60

    for (int j0 = 0; j0 < Nn; j0 += 64) {
        // cooperative K/V tile load (64x64 each)
#pragma unroll
        for (int rr = 0; rr < 4; rr++) {
            int r = lr + rr*16;
            const float* kp = Kg + base + (size_t)(j0+r)*Dd + lc;
            const float* vp = V  + base + (size_t)(j0+r)*Dd + lc;
            float4 k4 = *(const float4*)kp;
            float4 v4 = *(const float4*)vp;
            uint32_t* kd = &Ks[r*ATS + lc];
            kd[0]=f2tf32(k4.x); kd[1]=f2tf32(k4.y); kd[2]=f2tf32(k4.z); kd[3]=f2tf32(k4.w);
            uint32_t* vd = &Vs[r*ATS + lc];
            vd[0]=f2tf32(v4.x); vd[1]=f2tf32(v4.y); vd[2]=f2tf32(v4.z); vd[3]=f2tf32(v4.w);
        }
        __syncthreads();

        // S = Q @ K^T  (scaled)
        float sacc[8][4];
#pragma unroll
        for (int nt = 0; nt < 8; nt++)
#pragma unroll
            for (int i = 0; i < 4; i++) sacc[nt][i] = 0.f;
#pragma unroll
        for (int s = 0; s < 8; s++) {
#pragma unroll
            for (int nt = 0; nt < 8; nt++) {
                uint32_t bfrag[2];
                bfrag[0] = Ks[(nt*8+qid)*ATS + s*8 + tig];
                bfrag[1] = Ks[(nt*8+qid)*ATS + s*8 + tig + 4];
                mma_tf32(sacc[nt], qa[s], bfrag);
            }
        }

        // online softmax on fragment rows (row0 = qid, row1 = qid+8)
        float tm0 = -1e30f, tm1 = -1e30f;
#pragma unroll
        for (int nt = 0; nt < 8; nt++) {
            tm0 = fmaxf(tm0, fmaxf(sacc[nt][0], sacc[nt][1]));
            tm1 = fmaxf(tm1, fmaxf(sacc[nt][2], sacc[nt][3]));
        }
        tm0 = fmaxf(tm0, __shfl_xor_sync(0xffffffffu, tm0, 1));
        tm0 = fmaxf(tm0, __shfl_xor_sync(0xffffffffu, tm0, 2));
        tm1 = fmaxf(tm1, __shfl_xor_sync(0xffffffffu, tm1, 1));
        tm1 = fmaxf(tm1, __shfl_xor_sync(0xffffffffu, tm1, 2));
        float mn0 = fmaxf(m0, tm0), mn1 = fmaxf(m1, tm1);
        float c0 = __expf(m0 - mn0), c1 = __expf(m1 - mn1);
        m0 = mn0; m1 = mn1;
        l0 *= c0; l1 *= c1;
#pragma unroll
        for (int dn = 0; dn < 8; dn++) {
            oacc[dn][0] *= c0; oacc[dn][1] *= c0;
            oacc[dn][2] *= c1; oacc[dn][3] *= c1;
        }
#pragma unroll
        for (int nt = 0; nt < 8; nt++) {
            float p0 = __expf(sacc[nt][0] - m0);
            float p1 = __expf(sacc[nt][1] - m0);
            float p2 = __expf(sacc[nt][2] - m1);
            float p3 = __expf(sacc[nt][3] - m1);
            l0 += p0 + p1; l1 += p2 + p3;
            Ps[qid*ATS     + nt*8 + 2*tig    ] = f2tf32(p0);
            Ps[qid*ATS     + nt*8 + 2*tig + 1] = f2tf32(p1);
            Ps[(qid+8)*ATS + nt*8 + 2*tig    ] = f2tf32(p2);
            Ps[(qid+8)*ATS + nt*8 + 2*tig + 1] = f2tf32(p3);
        }
        __syncwarp();

        // O += P @ V
#pragma unroll
        for (int sj = 0; sj < 8; sj++) {
            uint32_t afrag[4];
            afrag[0] = Ps[qid*ATS     + sj*8 + tig    ];
            afrag[1] = Ps[(qid+8)*ATS + sj*8 + tig    ];
            afrag[2] = Ps[qid*ATS     + sj*8 + tig + 4];
            afrag[3] = Ps[(qid+8)*ATS + sj*8 + tig + 4];
#pragma unroll
            for (int dn = 0; dn < 8; dn++) {
                uint32_t bfrag[2];
                bfrag[0] = Vs[(sj*8+tig  )*ATS + dn*8 + qid];
                bfrag[1] = Vs[(sj*8+tig+4)*ATS + dn*8 + qid];
                mma_tf32(oacc[dn], afrag, bfrag);
            }
        }
        __syncthreads();
    }

    // finalize l and write O
    l0 += __shfl_xor_sync(0xffffffffu, l0, 1);
    l0 += __shfl_xor_sync(0xffffffffu, l0, 2);
    l1 += __shfl_xor_sync(0xffffffffu, l1, 1);
    l1 += __shfl_xor_sync(0xffffffffu, l1, 2);
    float inv0 = 1.f / l0, inv1 = 1.f / l1;
    float* o0 = O + base + (size_t)(q0+qid)*Dd;
    float* o1 = O + base + (size_t)(q0+qid+8)*Dd;
#pragma unroll
    for (int dn = 0; dn < 8; dn++) {
        int c = dn*8 + 2*tig;
        float2 r0; r0.x = oacc[dn][0]*inv0; r0.y = oacc[dn][1]*inv0;
        float2 r1; r1.x = oacc[dn][2]*inv1; r1.y = oacc[dn][3]*inv1;
        *(float2*)(o0 + c) = r0;
        *(float2*)(o1 + c) = r1;
    }
}

// ---------------- LayerNorm(h + res) in place ----------------
__global__ void ln_res_kernel(float* __restrict__ h, const float* __restrict__ res,
                              const float* __restrict__ g, const float* __restrict__ bta)
{
    int row = blockIdx.x*8 + (threadIdx.x >> 5);
    int lane = threadIdx.x & 31;
    size_t off = (size_t)row * Dd;
    float v[8];
    float s = 0.f;
#pragma unroll
    for (int i = 0; i < 8; i++) {
        int c = lane + i*32;
        v[i] = h[off+c] + res[off+c];
        s += v[i];
    }
#pragma unroll
    for (int o = 16; o; o >>= 1) s += __shfl_xor_sync(0xffffffffu, s, o);
    float mean = s * (1.f/256.f);
    float vs = 0.f;
#pragma unroll
    for (int i = 0; i < 8; i++) { float d = v[i]-mean; vs = fmaf(d, d, vs); }
#pragma unroll
    for (int o = 16; o; o >>= 1) vs += __shfl_xor_sync(0xffffffffu, vs, o);
    float rstd = rsqrtf(vs * (1.f/256.f) + 1e-5f);
#pragma unroll
    for (int i = 0; i < 8; i++) {
        int c = lane + i*32;
        h[off+c] = (v[i]-mean)*rstd*g[c] + bta[c];
    }
}

// ---------------- h_mean ----------------
__global__ void hmean_kernel(const float* __restrict__ h, float* __restrict__ hm)
{
    int b = blockIdx.x, d = threadIdx.x;
    const float* p = h + (size_t)b*Nn*Dd + d;
    float s = 0.f;
#pragma unroll 8
    for (int n = 0; n < Nn; n++) s += p[(size_t)n*Dd];
    hm[b*Dd + d] = s * (1.f/1024.f);
}

// ---------------- small row GEMM ----------------
template<int RELU>
__global__ void rowgemm_kernel(const float* __restrict__ A, const float* __restrict__ W,
                               const float* __restrict__ bias, float* __restrict__ C,
                               int Kd, int Nd)
{
    int b = blockIdx.x;
    __shared__ float xs[1024];
    for (int i = threadIdx.x; i < Kd; i += blockDim.x) xs[i] = A[(size_t)b*Kd + i];
    __syncthreads();
    for (int d = threadIdx.x; d < Nd; d += blockDim.x) {
        float acc = bias ? bias[d] : 0.f;
        for (int k = 0; k < Kd; k++) acc = fmaf(xs[k], W[(size_t)k*Nd + d], acc);
        if (RELU) acc = fmaxf(acc, 0.f);
        C[(size_t)b*Nd + d] = acc;
    }
}

// ---------------- scores ----------------
__global__ void scores_kernel(const float* __restrict__ qv, const float* __restrict__ kv,
                              float* __restrict__ scores)
{
    int b = blockIdx.y;
    int n = blockIdx.x*8 + (threadIdx.x >> 5);
    int lane = threadIdx.x & 31;
    const float* k = kv + ((size_t)b*Nn + n)*Dd;
    const float* q = qv + b*Dd;
    float s = 0.f;
#pragma unroll
    for (int i = 0; i < 8; i++) { int c = lane + i*32; s = fmaf(q[c], k[c], s); }
#pragma unroll
    for (int o = 16; o; o >>= 1) s += __shfl_xor_sync(0xffffffffu, s, o);
    if (lane == 0) scores[b*Nn + n] = s * (1.f/16.f);
}

// ---------------- finale ----------------
__global__ void finale_kernel(const float* __restrict__ scores, const float* __restrict__ gumbel,
                              const float* __restrict__ logits,
                              float* __restrict__ out_w, float* __restrict__ out_idx,
                              float* __restrict__ out_sel)
{
    int b = blockIdx.x, tid = threadIdx.x;
    __shared__ float w[1024];
    __shared__ float al[1024];
    __shared__ float red[256];
    __shared__ int   redi[256];
    __shared__ int   selidx[64];

    float lm = -1e30f;
    for (int i = tid; i < 1024; i += 256) {
        float v = (scores[b*Nn+i] + gumbel[b*Nn+i]) * 2.0f;
        w[i] = v; lm = fmaxf(lm, v);
    }
    red[tid] = lm; __syncthreads();
    for (int s = 128; s; s >>= 1) { if (tid < s) red[tid] = fmaxf(red[tid], red[tid+s]); __syncthreads(); }
    float M = red[0]; __syncthreads();
    float ls = 0.f;
    for (int i = tid; i < 1024; i += 256) { float e = __expf(w[i]-M); w[i] = e; ls += e; }
    red[tid] = ls; __syncthreads();
    for (int s = 128; s; s >>= 1) { if (tid < s) red[tid] += red[tid+s]; __syncthreads(); }
    float invS = 1.f / red[0]; __syncthreads();
    for (int i = tid; i < 1024; i += 256) {
        float wi = w[i]*invS; w[i] = wi; out_w[b*Nn+i] = wi;
    }

    lm = -1e30f;
    for (int i = tid; i < 1024; i += 256) { float v = logits[b*Nn+i]; al[i] = v; lm = fmaxf(lm, v); }
    __syncthreads();
    red[tid] = lm; __syncthreads();
    for (int s = 128; s; s >>= 1) { if (tid < s) red[tid] = fmaxf(red[tid], red[tid+s]); __syncthreads(); }
    M = red[0]; __syncthreads();
    ls = 0.f;
    for (int i = tid; i < 1024; i += 256) { float e = __expf(al[i]-M); al[i] = e; ls += e; }
    red[tid] = ls; __syncthreads();
    for (int s = 128; s; s >>= 1) { if (tid < s) red[tid] += red[tid+s]; __syncthreads(); }
    invS = 1.f / red[0]; __syncthreads();
    for (int i = tid; i < 1024; i += 256) al[i] *= invS;
    __syncthreads();

    for (int kk = 0; kk < 64; kk++) {
        float bv = -1e30f; int bi = 0x7fffffff;
        for (int i = tid; i < 1024; i += 256) {
            float v = w[i];
            if (v > bv) { bv = v; bi = i; }
        }
        red[tid] = bv; redi[tid] = bi; __syncthreads();
        for (int s = 128; s; s >>= 1) {
            if (tid < s) {
                float ov = red[tid+s]; int oi = redi[tid+s];
                if (ov > red[tid] || (ov == red[tid] && oi < redi[tid])) { red[tid] = ov; redi[tid] = oi; }
            }
            __syncthreads();
        }
        if (tid == 0) { selidx[kk] = redi[0]; w[redi[0]] = -2e30f; }
        __syncthreads();
    }

    float sv = 0.f;
    if (tid < 64) sv = al[selidx[tid]];
    red[tid] = (tid < 64) ? sv : 0.f; __syncthreads();
    for (int s = 128; s; s >>= 1) { if (tid < s) red[tid] += red[tid+s]; __syncthreads(); }
    float inv = 1.f / (red[0] + 1e-12f);
    if (tid < 64) {
        out_idx[b*64 + tid] = (float)selidx[tid];
        out_sel[b*64 + tid] = sv * inv;
    }
}

// ---------------- launch ----------------
extern "C" void kernel_launch(void* const* d_in, const int* in_sizes, int n_in,
                              void* d_out, int out_size)
{
    const float* x       = (const float*)d_in[0];
    const float* gumbel  = (const float*)d_in[1];
    const float* emb_W   = (const float*)d_in[2];
    const float* emb_b   = (const float*)d_in[3];
    const float* Wq      = (const float*)d_in[4];
    const float* Wk      = (const float*)d_in[5];
    const float* Wv      = (const float*)d_in[6];
    const float* Wo      = (const float*)d_in[7];
    const float* ln1_g   = (const float*)d_in[8];
    const float* ln1_b   = (const float*)d_in[9];
    const float* ln2_g   = (const float*)d_in[10];
    const float* ln2_b   = (const float*)d_in[11];
    const float* ffn_W1  = (const float*)d_in[12];
    const float* ffn_b1  = (const float*)d_in[13];
    const float* ffn_W2  = (const float*)d_in[14];
    const float* ffn_b2  = (const float*)d_in[15];
    const float* sha_Wq  = (const float*)d_in[16];
    const float* sha_Wk  = (const float*)d_in[17];
    const float* alloc_W1= (const float*)d_in[18];
    const float* alloc_b1= (const float*)d_in[19];
    const float* alloc_W2= (const float*)d_in[20];
    const float* alloc_b2= (const float*)d_in[21];

    float *h, *scr, *tmp, *hmean, *qv, *t1, *logits, *scores;
    cudaGetSymbolAddress((void**)&h,      g_h);
    cudaGetSymbolAddress((void**)&scr,    g_scr);
    cudaGetSymbolAddress((void**)&tmp,    g_tmp);
    cudaGetSymbolAddress((void**)&hmean,  g_hmean);
    cudaGetSymbolAddress((void**)&qv,     g_qv);
    cudaGetSymbolAddress((void**)&t1,     g_t1);
    cudaGetSymbolAddress((void**)&logits, g_logits);
    cudaGetSymbolAddress((void**)&scores, g_scores);

    static int att_cfg = 0;
    if (!att_cfg) {
        cudaFuncSetAttribute(attn_mma_kernel,
                             cudaFuncAttributeMaxDynamicSharedMemorySize, ATT_SMEM);
        att_cfg = 1;
    }

    float* q  = scr;
    float* k  = scr + (size_t)MM*Dd;
    float* v  = scr + (size_t)2*MM*Dd;
    float* ao = scr + (size_t)3*MM*Dd;

    embed_kernel<<<MM, 256>>>(x, emb_W, emb_b, h);

    const dim3 gP(Dd/128, MM/128);
    const dim3 gF1(DFF/128, MM/128);

    for (int i = 0; i < Ll; i++) {
        tgemm_kernel<0><<<gP, 256>>>(h, Wq + (size_t)i*Dd*Dd, nullptr, q, MM, Dd, Dd);
        tgemm_kernel<0><<<gP, 256>>>(h, Wk + (size_t)i*Dd*Dd, nullptr, k, MM, Dd, Dd);
        tgemm_kernel<0><<<gP, 256>>>(h, Wv + (size_t)i*Dd*Dd, nullptr, v, MM, Dd, Dd);
        attn_mma_kernel<<<dim3(Nn/128, Hh, Bb), 256, ATT_SMEM>>>(q, k, v, ao);
        tgemm_kernel<0><<<gP, 256>>>(ao, Wo + (size_t)i*Dd*Dd, nullptr, tmp, MM, Dd, Dd);
        ln_res_kernel<<<MM/8, 256>>>(h, tmp, ln1_g + i*Dd, ln1_b + i*Dd);
        tgemm_kernel<1><<<gF1, 256>>>(h, ffn_W1 + (size_t)i*Dd*DFF, ffn_b1 + i*DFF, scr, MM, DFF, Dd);
        tgemm_kernel<0><<<gP, 256>>>(scr, ffn_W2 + (size_t)i*DFF*Dd, ffn_b2 + i*Dd, tmp, MM, Dd, DFF);
        ln_res_kernel<<<MM/8, 256>>>(h, tmp, ln2_g + i*Dd, ln2_b + i*Dd);
    }

    hmean_kernel<<<Bb, 256>>>(h, hmean);
    rowgemm_kernel<0><<<Bb, 256>>>(hmean, sha_Wq, nullptr, qv, Dd, Dd);
    tgemm_kernel<0><<<gP, 256>>>(h, sha_Wk, nullptr, tmp, MM, Dd, Dd);
    scores_kernel<<<dim3(Nn/8, Bb), 256>>>(qv, tmp, scores);
    rowgemm_kernel<1><<<Bb, 256>>>(hmean, alloc_W1, alloc_b1, t1, Dd, Dd);
    rowgemm_kernel<0><<<Bb, 256>>>(t1, alloc_W2, alloc_b2, logits, Dd, Nn);

    float* out = (float*)d_out;
    finale_kernel<<<Bb, 256>>>(scores, gumbel, logits,
                               out,
                               out + Bb*Nn,
                               out + Bb*Nn + Bb*Kk);
}

// round 5
// speedup vs baseline: 4.3423x; 1.0571x over previous
#include <cuda_runtime.h>
#include <cstdint>

// ---------------- problem dims ----------------
#define Bb 64
#define Nn 1024
#define Din 16
#define Dd 256
#define Hh 4
#define DH 64
#define Ll 3
#define DFF 1024
#define Kk 64
#define MM (Bb*Nn)          // 65536 rows

// ---------------- scratch (static device memory) ----------------
__device__ float g_h[MM*Dd];            // 64 MB   hidden state
__device__ float g_scr[MM*DFF];         // 256 MB  qkv|ao or ffn hidden
__device__ float g_tmp[MM*Dd];          // 64 MB   proj/ffn out / kv
__device__ uint32_t g_wpk[2424832];     // tf32-packed weights (~9.7MB)
__device__ float g_hmean[Bb*Dd];
__device__ float g_qv[Bb*Dd];
__device__ float g_t1[Bb*Dd];
__device__ float g_logits[Bb*Nn];
__device__ float g_scores[Bb*Nn];

// packed-weight offsets (uint32 units)
#define OFF_QKV  0            // 3 layers x [256][768]
#define OFF_WO   589824       // 3 x [256][256]
#define OFF_W1   786432       // 3 x [256][1024]
#define OFF_W2   1572864      // 3 x [1024][256]
#define OFF_SHA  2359296      // [256][256]

__device__ __forceinline__ uint32_t f2tf32(float f) {
    uint32_t r;
    asm("cvt.rna.tf32.f32 %0, %1;" : "=r"(r) : "f"(f));
    return r;
}

__device__ __forceinline__ void mma_tf32(float* c, const uint32_t* a, const uint32_t* b) {
    asm volatile(
        "mma.sync.aligned.m16n8k8.row.col.f32.tf32.tf32.f32 "
        "{%0,%1,%2,%3}, {%4,%5,%6,%7}, {%8,%9}, {%0,%1,%2,%3};"
        : "+f"(c[0]), "+f"(c[1]), "+f"(c[2]), "+f"(c[3])
        : "r"(a[0]), "r"(a[1]), "r"(a[2]), "r"(a[3]), "r"(b[0]), "r"(b[1]));
}

// ---------------- weight pack: fp32 [L][K][N] -> tf32 u32 into dst with col offset ----------------
__global__ void packt_kernel(const float* __restrict__ src, uint32_t* __restrict__ dst,
                             int Nsrc, int dstStride, int colOff, int KN, int layerDstStride,
                             int total)
{
    int i = blockIdx.x*256 + threadIdx.x;
    if (i >= total) return;
    int l = i / KN;
    int rem = i - l*KN;
    int k = rem / Nsrc, n = rem - k*Nsrc;
    dst[(size_t)l*layerDstStride + (size_t)k*dstStride + colOff + n] = f2tf32(src[i]);
}

// ---------------- embedding ----------------
__global__ void embed_kernel(const float* __restrict__ x, const float* __restrict__ W,
                             const float* __restrict__ b, float* __restrict__ h)
{
    int m = blockIdx.x;
    int d = threadIdx.x;
    __shared__ float xs[Din];
    if (threadIdx.x < Din) xs[threadIdx.x] = x[m*Din + threadIdx.x];
    __syncthreads();
    float acc = b[d];
#pragma unroll
    for (int k = 0; k < Din; k++) acc = fmaf(xs[k], W[k*Dd + d], acc);
    h[(size_t)m*Dd + d] = acc;
}

// ---------------- TF32 tensor-core GEMM, double-buffered, pre-packed B ----------------
#define AST 20
#define BST 136

template<int RELU>
__global__ __launch_bounds__(256, 2) void tgemm_kernel(
    const float* __restrict__ A, const uint32_t* __restrict__ Wp,
    const float* __restrict__ bias, float* __restrict__ C,
    int M, int Nd, int Kd)
{
    __shared__ __align__(16) uint32_t As[2][128*AST];
    __shared__ __align__(16) uint32_t Bs[2][16*BST];

    const int tid = threadIdx.x;
    const int warp = tid >> 5;
    const int lane = tid & 31;
    const int bm = blockIdx.y, bn = blockIdx.x;
    const int wm = warp & 3;
    const int wn = warp >> 2;
    const int qid = lane >> 2;
    const int tig = lane & 3;

    const int a_r0 = tid >> 2,  a_c0 = (tid & 3) << 2;
    const int a_r1 = a_r0 + 64;
    const int b_r0 = tid >> 5,  b_c0 = (tid & 31) << 2;
    const int b_r1 = b_r0 + 8;

    const float*    Ap = A  + (size_t)(bm*128)*Kd;
    const uint32_t* Bp = Wp + (size_t)bn*128;

    float acc[2][8][4];
#pragma unroll
    for (int mt = 0; mt < 2; mt++)
#pragma unroll
        for (int nt = 0; nt < 8; nt++)
#pragma unroll
            for (int i = 0; i < 4; i++) acc[mt][nt][i] = 0.f;

    float4 avr0 = *(const float4*)(Ap + (size_t)a_r0*Kd + a_c0);
    float4 avr1 = *(const float4*)(Ap + (size_t)a_r1*Kd + a_c0);
    uint4  bv0  = *(const uint4*)(Bp + (size_t)b_r0*Nd + b_c0);
    uint4  bv1  = *(const uint4*)(Bp + (size_t)b_r1*Nd + b_c0);

    {
        uint32_t* p = &As[0][a_r0*AST + a_c0];
        p[0]=f2tf32(avr0.x); p[1]=f2tf32(avr0.y); p[2]=f2tf32(avr0.z); p[3]=f2tf32(avr0.w);
        p = &As[0][a_r1*AST + a_c0];
        p[0]=f2tf32(avr1.x); p[1]=f2tf32(avr1.y); p[2]=f2tf32(avr1.z); p[3]=f2tf32(avr1.w);
        *(uint4*)&Bs[0][b_r0*BST + b_c0] = bv0;
        *(uint4*)&Bs[0][b_r1*BST + b_c0] = bv1;
    }
    __syncthreads();

    const int niter = Kd >> 4;
    int buf = 0;
    for (int it = 0; it < niter; it++) {
        if (it + 1 < niter) {
            const float*    Ap2 = Ap + (it+1)*16;
            const uint32_t* Bp2 = Bp + (size_t)((it+1)*16)*Nd;
            avr0 = *(const float4*)(Ap2 + (size_t)a_r0*Kd + a_c0);
            avr1 = *(const float4*)(Ap2 + (size_t)a_r1*Kd + a_c0);
            bv0  = *(const uint4*)(Bp2 + (size_t)b_r0*Nd + b_c0);
            bv1  = *(const uint4*)(Bp2 + (size_t)b_r1*Nd + b_c0);
        }

        const uint32_t* Asu = As[buf];
        const uint32_t* Bsu = Bs[buf];
#pragma unroll
        for (int ks = 0; ks < 2; ks++) {
            const int ka = ks*8 + tig;
            uint32_t afrag[2][4];
#pragma unroll
            for (int mt = 0; mt < 2; mt++) {
                int r = wm*32 + mt*16 + qid;
                afrag[mt][0] = Asu[r*AST + ka];
                afrag[mt][1] = Asu[(r+8)*AST + ka];
                afrag[mt][2] = Asu[r*AST + ka + 4];
                afrag[mt][3] = Asu[(r+8)*AST + ka + 4];
            }
#pragma unroll
            for (int nt = 0; nt < 8; nt++) {
                int cn = wn*64 + nt*8 + qid;
                uint32_t bfrag[2];
                bfrag[0] = Bsu[(ks*8 + tig)*BST + cn];
                bfrag[1] = Bsu[(ks*8 + tig + 4)*BST + cn];
#pragma unroll
                for (int mt = 0; mt < 2; mt++)
                    mma_tf32(acc[mt][nt], afrag[mt], bfrag);
            }
        }

        if (it + 1 < niter) {
            int nb = buf ^ 1;
            uint32_t* p = &As[nb][a_r0*AST + a_c0];
            p[0]=f2tf32(avr0.x); p[1]=f2tf32(avr0.y); p[2]=f2tf32(avr0.z); p[3]=f2tf32(avr0.w);
            p = &As[nb][a_r1*AST + a_c0];
            p[0]=f2tf32(avr1.x); p[1]=f2tf32(avr1.y); p[2]=f2tf32(avr1.z); p[3]=f2tf32(avr1.w);
            *(uint4*)&Bs[nb][b_r0*BST + b_c0] = bv0;
            *(uint4*)&Bs[nb][b_r1*BST + b_c0] = bv1;
            __syncthreads();
            buf = nb;
        }
    }

    // epilogue
#pragma unroll
    for (int mt = 0; mt < 2; mt++) {
        int r0 = bm*128 + wm*32 + mt*16 + qid;
#pragma unroll
        for (int nt = 0; nt < 8; nt++) {
            int c0 = bn*128 + wn*64 + nt*8 + tig*2;
            float b0 = bias ? bias[c0]   : 0.f;
            float b1 = bias ? bias[c0+1] : 0.f;
            float v0 = acc[mt][nt][0] + b0, v1 = acc[mt][nt][1] + b1;
            float v2 = acc[mt][nt][2] + b0, v3 = acc[mt][nt][3] + b1;
            if (RELU) {
                v0 = fmaxf(v0, 0.f); v1 = fmaxf(v1, 0.f);
                v2 = fmaxf(v2, 0.f); v3 = fmaxf(v3, 0.f);
            }
            float2 p0; p0.x = v0; p0.y = v1;
            float2 p1; p1.x = v2; p1.y = v3;
            *(float2*)&C[(size_t)r0*Nd + c0]     = p0;
            *(float2*)&C[(size_t)(r0+8)*Nd + c0] = p1;
        }
    }
}

// ---------------- tensor-core flash attention (tf32 MMA, fused QKV input) ----------------
// Q/K/V live in one [M][768] buffer (cols 0/256/512). O is [M][256].
#define QKV_RS 768
#define O_RS   256
#define KST 76
#define VST 72
#define PST 72
#define ATT_SMEM ((64*KST + 64*VST + 8*16*PST)*4)

__global__ void __launch_bounds__(256) attn_mma_kernel(
    const float* __restrict__ QKV, float* __restrict__ O)
{
    extern __shared__ uint32_t sm[];
    uint32_t* Ks = sm;
    uint32_t* Vs = sm + 64*KST;
    const int tid = threadIdx.x;
    const int warp = tid >> 5, lane = tid & 31;
    const int qid = lane >> 2, tig = lane & 3;
    uint32_t* Ps = sm + 64*KST + 64*VST + warp*16*PST;

    const int qt = blockIdx.x, head = blockIdx.y, b = blockIdx.z;
    const size_t qbase = ((size_t)b*Nn)*QKV_RS + head*DH;
    const size_t kbase = qbase + 256;
    const size_t vbase = qbase + 512;
    const size_t obase = ((size_t)b*Nn)*O_RS + head*DH;
    const int q0 = qt*128 + warp*16;

    // Q fragments, scale folded in
    uint32_t qa[8][4];
    const float scale = 0.125f;
#pragma unroll
    for (int s = 0; s < 8; s++) {
        int d0 = s*8;
        qa[s][0] = f2tf32(scale * QKV[qbase + (size_t)(q0+qid  )*QKV_RS + d0+tig  ]);
        qa[s][1] = f2tf32(scale * QKV[qbase + (size_t)(q0+qid+8)*QKV_RS + d0+tig  ]);
        qa[s][2] = f2tf32(scale * QKV[qbase + (size_t)(q0+qid  )*QKV_RS + d0+tig+4]);
        qa[s][3] = f2tf32(scale * QKV[qbase + (size_t)(q0+qid+8)*QKV_RS + d0+tig+4]);
    }

    float oacc[8][4];
#pragma unroll
    for (int dn = 0; dn < 8; dn++)
#pragma unroll
        for (int i = 0; i < 4; i++) oacc[dn][i] = 0.f;
    float m0 = -1e30f, m1 = -1e30f, l0 = 0.f, l1 = 0.f;

    const int lr = tid >> 4;           // 0..15
    const int lc = (tid & 15) << 2;    // 0..60

    for (int j0 = 0; j0 < Nn; j0 += 64) {
#pragma unroll
        for (int rr = 0; rr < 4; rr++) {
            int r = lr + rr*16;
            float4 k4 = *(const float4*)(QKV + kbase + (size_t)(j0+r)*QKV_RS + lc);
            float4 v4 = *(const float4*)(QKV + vbase + (size_t)(j0+r)*QKV_RS + lc);
            uint32_t* kd = &Ks[r*KST + lc];
            kd[0]=f2tf32(k4.x); kd[1]=f2tf32(k4.y); kd[2]=f2tf32(k4.z); kd[3]=f2tf32(k4.w);
            uint32_t* vd = &Vs[r*VST + lc];
            vd[0]=f2tf32(v4.x); vd[1]=f2tf32(v4.y); vd[2]=f2tf32(v4.z); vd[3]=f2tf32(v4.w);
        }
        __syncthreads();

        // S = Q @ K^T (scaled)
        float sacc[8][4];
#pragma unroll
        for (int nt = 0; nt < 8; nt++)
#pragma unroll
            for (int i = 0; i < 4; i++) sacc[nt][i] = 0.f;
#pragma unroll
        for (int s = 0; s < 8; s++) {
#pragma unroll
            for (int nt = 0; nt < 8; nt++) {
                uint32_t bfrag[2];
                bfrag[0] = Ks[(nt*8+qid)*KST + s*8 + tig];
                bfrag[1] = Ks[(nt*8+qid)*KST + s*8 + tig + 4];
                mma_tf32(sacc[nt], qa[s], bfrag);
            }
        }

        // online softmax
        float tm0 = -1e30f, tm1 = -1e30f;
#pragma unroll
        for (int nt = 0; nt < 8; nt++) {
            tm0 = fmaxf(tm0, fmaxf(sacc[nt][0], sacc[nt][1]));
            tm1 = fmaxf(tm1, fmaxf(sacc[nt][2], sacc[nt][3]));
        }
        tm0 = fmaxf(tm0, __shfl_xor_sync(0xffffffffu, tm0, 1));
        tm0 = fmaxf(tm0, __shfl_xor_sync(0xffffffffu, tm0, 2));
        tm1 = fmaxf(tm1, __shfl_xor_sync(0xffffffffu, tm1, 1));
        tm1 = fmaxf(tm1, __shfl_xor_sync(0xffffffffu, tm1, 2));
        float mn0 = fmaxf(m0, tm0), mn1 = fmaxf(m1, tm1);
        float c0 = __expf(m0 - mn0), c1 = __expf(m1 - mn1);
        m0 = mn0; m1 = mn1;
        l0 *= c0; l1 *= c1;
#pragma unroll
        for (int dn = 0; dn < 8; dn++) {
            oacc[dn][0] *= c0; oacc[dn][1] *= c0;
            oacc[dn][2] *= c1; oacc[dn][3] *= c1;
        }
#pragma unroll
        for (int nt = 0; nt < 8; nt++) {
            float p0 = __expf(sacc[nt][0] - m0);
            float p1 = __expf(sacc[nt][1] - m0);
            float p2 = __expf(sacc[nt][2] - m1);
            float p3 = __expf(sacc[nt][3] - m1);
            l0 += p0 + p1; l1 += p2 + p3;
            Ps[qid*PST     + nt*8 + 2*tig    ] = f2tf32(p0);
            Ps[qid*PST     + nt*8 + 2*tig + 1] = f2tf32(p1);
            Ps[(qid+8)*PST + nt*8 + 2*tig    ] = f2tf32(p2);
            Ps[(qid+8)*PST + nt*8 + 2*tig + 1] = f2tf32(p3);
        }
        __syncwarp();

        // O += P @ V
#pragma unroll
        for (int sj = 0; sj < 8; sj++) {
            uint32_t afrag[4];
            afrag[0] = Ps[qid*PST     + sj*8 + tig    ];
            afrag[1] = Ps[(qid+8)*PST + sj*8 + tig    ];
            afrag[2] = Ps[qid*PST     + sj*8 + tig + 4];
            afrag[3] = Ps[(qid+8)*PST + sj*8 + tig + 4];
#pragma unroll
            for (int dn = 0; dn < 8; dn++) {
                uint32_t bfrag[2];
                bfrag[0] = Vs[(sj*8+tig  )*VST + dn*8 + qid];
                bfrag[1] = Vs[(sj*8+tig+4)*VST + dn*8 + qid];
                mma_tf32(oacc[dn], afrag, bfrag);
            }
        }
        __syncthreads();
    }

    l0 += __shfl_xor_sync(0xffffffffu, l0, 1);
    l0 += __shfl_xor_sync(0xffffffffu, l0, 2);
    l1 += __shfl_xor_sync(0xffffffffu, l1, 1);
    l1 += __shfl_xor_sync(0xffffffffu, l1, 2);
    float inv0 = 1.f / l0, inv1 = 1.f / l1;
    float* o0 = O + obase + (size_t)(q0+qid)*O_RS;
    float* o1 = O + obase + (size_t)(q0+qid+8)*O_RS;
#pragma unroll
    for (int dn = 0; dn < 8; dn++) {
        int c = dn*8 + 2*tig;
        float2 r0; r0.x = oacc[dn][0]*inv0; r0.y = oacc[dn][1]*inv0;
        float2 r1; r1.x = oacc[dn][2]*inv1; r1.y = oacc[dn][3]*inv1;
        *(float2*)(o0 + c) = r0;
        *(float2*)(o1 + c) = r1;
    }
}

// ---------------- LayerNorm(h + res) in place ----------------
__global__ void ln_res_kernel(float* __restrict__ h, const float* __restrict__ res,
                              const float* __restrict__ g, const float* __restrict__ bta)
{
    int row = blockIdx.x*8 + (threadIdx.x >> 5);
    int lane = threadIdx.x & 31;
    size_t off = (size_t)row * Dd;
    float v[8];
    float s = 0.f;
#pragma unroll
    for (int i = 0; i < 8; i++) {
        int c = lane + i*32;
        v[i] = h[off+c] + res[off+c];
        s += v[i];
    }
#pragma unroll
    for (int o = 16; o; o >>= 1) s += __shfl_xor_sync(0xffffffffu, s, o);
    float mean = s * (1.f/256.f);
    float vs = 0.f;
#pragma unroll
    for (int i = 0; i < 8; i++) { float d = v[i]-mean; vs = fmaf(d, d, vs); }
#pragma unroll
    for (int o = 16; o; o >>= 1) vs += __shfl_xor_sync(0xffffffffu, vs, o);
    float rstd = rsqrtf(vs * (1.f/256.f) + 1e-5f);
#pragma unroll
    for (int i = 0; i < 8; i++) {
        int c = lane + i*32;
        h[off+c] = (v[i]-mean)*rstd*g[c] + bta[c];
    }
}

// ---------------- h_mean ----------------
__global__ void hmean_kernel(const float* __restrict__ h, float* __restrict__ hm)
{
    int b = blockIdx.x, d = threadIdx.x;
    const float* p = h + (size_t)b*Nn*Dd + d;
    float s = 0.f;
#pragma unroll 8
    for (int n = 0; n < Nn; n++) s += p[(size_t)n*Dd];
    hm[b*Dd + d] = s * (1.f/1024.f);
}

// ---------------- small row GEMM ----------------
template<int RELU>
__global__ void rowgemm_kernel(const float* __restrict__ A, const float* __restrict__ W,
                               const float* __restrict__ bias, float* __restrict__ C,
                               int Kd, int Nd)
{
    int b = blockIdx.x;
    __shared__ float xs[1024];
    for (int i = threadIdx.x; i < Kd; i += blockDim.x) xs[i] = A[(size_t)b*Kd + i];
    __syncthreads();
    for (int d = threadIdx.x; d < Nd; d += blockDim.x) {
        float acc = bias ? bias[d] : 0.f;
        for (int k = 0; k < Kd; k++) acc = fmaf(xs[k], W[(size_t)k*Nd + d], acc);
        if (RELU) acc = fmaxf(acc, 0.f);
        C[(size_t)b*Nd + d] = acc;
    }
}

// ---------------- scores ----------------
__global__ void scores_kernel(const float* __restrict__ qv, const float* __restrict__ kv,
                              float* __restrict__ scores)
{
    int b = blockIdx.y;
    int n = blockIdx.x*8 + (threadIdx.x >> 5);
    int lane = threadIdx.x & 31;
    const float* k = kv + ((size_t)b*Nn + n)*Dd;
    const float* q = qv + b*Dd;
    float s = 0.f;
#pragma unroll
    for (int i = 0; i < 8; i++) { int c = lane + i*32; s = fmaf(q[c], k[c], s); }
#pragma unroll
    for (int o = 16; o; o >>= 1) s += __shfl_xor_sync(0xffffffffu, s, o);
    if (lane == 0) scores[b*Nn + n] = s * (1.f/16.f);
}

// ---------------- finale ----------------
__global__ void finale_kernel(const float* __restrict__ scores, const float* __restrict__ gumbel,
                              const float* __restrict__ logits,
                              float* __restrict__ out_w, float* __restrict__ out_idx,
                              float* __restrict__ out_sel)
{
    int b = blockIdx.x, tid = threadIdx.x;
    __shared__ float w[1024];
    __shared__ float al[1024];
    __shared__ float red[256];
    __shared__ int   redi[256];
    __shared__ int   selidx[64];

    float lm = -1e30f;
    for (int i = tid; i < 1024; i += 256) {
        float v = (scores[b*Nn+i] + gumbel[b*Nn+i]) * 2.0f;
        w[i] = v; lm = fmaxf(lm, v);
    }
    red[tid] = lm; __syncthreads();
    for (int s = 128; s; s >>= 1) { if (tid < s) red[tid] = fmaxf(red[tid], red[tid+s]); __syncthreads(); }
    float M = red[0]; __syncthreads();
    float ls = 0.f;
    for (int i = tid; i < 1024; i += 256) { float e = __expf(w[i]-M); w[i] = e; ls += e; }
    red[tid] = ls; __syncthreads();
    for (int s = 128; s; s >>= 1) { if (tid < s) red[tid] += red[tid+s]; __syncthreads(); }
    float invS = 1.f / red[0]; __syncthreads();
    for (int i = tid; i < 1024; i += 256) {
        float wi = w[i]*invS; w[i] = wi; out_w[b*Nn+i] = wi;
    }

    lm = -1e30f;
    for (int i = tid; i < 1024; i += 256) { float v = logits[b*Nn+i]; al[i] = v; lm = fmaxf(lm, v); }
    __syncthreads();
    red[tid] = lm; __syncthreads();
    for (int s = 128; s; s >>= 1) { if (tid < s) red[tid] = fmaxf(red[tid], red[tid+s]); __syncthreads(); }
    M = red[0]; __syncthreads();
    ls = 0.f;
    for (int i = tid; i < 1024; i += 256) { float e = __expf(al[i]-M); al[i] = e; ls += e; }
    red[tid] = ls; __syncthreads();
    for (int s = 128; s; s >>= 1) { if (tid < s) red[tid] += red[tid+s]; __syncthreads(); }
    invS = 1.f / red[0]; __syncthreads();
    for (int i = tid; i < 1024; i += 256) al[i] *= invS;
    __syncthreads();

    for (int kk = 0; kk < 64; kk++) {
        float bv = -1e30f; int bi = 0x7fffffff;
        for (int i = tid; i < 1024; i += 256) {
            float v = w[i];
            if (v > bv) { bv = v; bi = i; }
        }
        red[tid] = bv; redi[tid] = bi; __syncthreads();
        for (int s = 128; s; s >>= 1) {
            if (tid < s) {
                float ov = red[tid+s]; int oi = redi[tid+s];
                if (ov > red[tid] || (ov == red[tid] && oi < redi[tid])) { red[tid] = ov; redi[tid] = oi; }
            }
            __syncthreads();
        }
        if (tid == 0) { selidx[kk] = redi[0]; w[redi[0]] = -2e30f; }
        __syncthreads();
    }

    float sv = 0.f;
    if (tid < 64) sv = al[selidx[tid]];
    red[tid] = (tid < 64) ? sv : 0.f; __syncthreads();
    for (int s = 128; s; s >>= 1) { if (tid < s) red[tid] += red[tid+s]; __syncthreads(); }
    float inv = 1.f / (red[0] + 1e-12f);
    if (tid < 64) {
        out_idx[b*64 + tid] = (float)selidx[tid];
        out_sel[b*64 + tid] = sv * inv;
    }
}

// ---------------- launch ----------------
extern "C" void kernel_launch(void* const* d_in, const int* in_sizes, int n_in,
                              void* d_out, int out_size)
{
    const float* x       = (const float*)d_in[0];
    const float* gumbel  = (const float*)d_in[1];
    const float* emb_W   = (const float*)d_in[2];
    const float* emb_b   = (const float*)d_in[3];
    const float* Wq      = (const float*)d_in[4];
    const float* Wk      = (const float*)d_in[5];
    const float* Wv      = (const float*)d_in[6];
    const float* Wo      = (const float*)d_in[7];
    const float* ln1_g   = (const float*)d_in[8];
    const float* ln1_b   = (const float*)d_in[9];
    const float* ln2_g   = (const float*)d_in[10];
    const float* ln2_b   = (const float*)d_in[11];
    const float* ffn_W1  = (const float*)d_in[12];
    const float* ffn_b1  = (const float*)d_in[13];
    const float* ffn_W2  = (const float*)d_in[14];
    const float* ffn_b2  = (const float*)d_in[15];
    const float* sha_Wq  = (const float*)d_in[16];
    const float* sha_Wk  = (const float*)d_in[17];
    const float* alloc_W1= (const float*)d_in[18];
    const float* alloc_b1= (const float*)d_in[19];
    const float* alloc_W2= (const float*)d_in[20];
    const float* alloc_b2= (const float*)d_in[21];

    float *h, *scr, *tmp, *hmean, *qv, *t1, *logits, *scores;
    uint32_t* wpk;
    cudaGetSymbolAddress((void**)&h,      g_h);
    cudaGetSymbolAddress((void**)&scr,    g_scr);
    cudaGetSymbolAddress((void**)&tmp,    g_tmp);
    cudaGetSymbolAddress((void**)&wpk,    g_wpk);
    cudaGetSymbolAddress((void**)&hmean,  g_hmean);
    cudaGetSymbolAddress((void**)&qv,     g_qv);
    cudaGetSymbolAddress((void**)&t1,     g_t1);
    cudaGetSymbolAddress((void**)&logits, g_logits);
    cudaGetSymbolAddress((void**)&scores, g_scores);

    static int att_cfg = 0;
    if (!att_cfg) {
        cudaFuncSetAttribute(attn_mma_kernel,
                             cudaFuncAttributeMaxDynamicSharedMemorySize, ATT_SMEM);
        att_cfg = 1;
    }

    // pack weights -> tf32 u32 (QKV fused side-by-side into [256][768])
    {
        int t;
        t = 3*256*256;
        packt_kernel<<<(t+255)/256, 256>>>(Wq, wpk + OFF_QKV, 256, 768, 0,   256*256, 256*768, t);
        packt_kernel<<<(t+255)/256, 256>>>(Wk, wpk + OFF_QKV, 256, 768, 256, 256*256, 256*768, t);
        packt_kernel<<<(t+255)/256, 256>>>(Wv, wpk + OFF_QKV, 256, 768, 512, 256*256, 256*768, t);
        packt_kernel<<<(t+255)/256, 256>>>(Wo, wpk + OFF_WO, 256, 256, 0, 256*256, 256*256, t);
        t = 3*256*1024;
        packt_kernel<<<(t+255)/256, 256>>>(ffn_W1, wpk + OFF_W1, 1024, 1024, 0, 256*1024, 256*1024, t);
        packt_kernel<<<(t+255)/256, 256>>>(ffn_W2, wpk + OFF_W2, 256, 256, 0, 1024*256, 1024*256, t);
        t = 256*256;
        packt_kernel<<<(t+255)/256, 256>>>(sha_Wk, wpk + OFF_SHA, 256, 256, 0, 256*256, 256*256, t);
    }

    float* qkv = scr;                           // [M][768]
    float* ao  = scr + (size_t)MM*768;          // [M][256]

    embed_kernel<<<MM, 256>>>(x, emb_W, emb_b, h);

    const dim3 gQKV(768/128, MM/128);  // (6,512)
    const dim3 gP(Dd/128, MM/128);     // (2,512)
    const dim3 gF1(DFF/128, MM/128);   // (8,512)

    for (int i = 0; i < Ll; i++) {
        tgemm_kernel<0><<<gQKV, 256>>>(h, wpk + OFF_QKV + (size_t)i*256*768, nullptr, qkv, MM, 768, Dd);
        attn_mma_kernel<<<dim3(Nn/128, Hh, Bb), 256, ATT_SMEM>>>(qkv, ao);
        tgemm_kernel<0><<<gP, 256>>>(ao, wpk + OFF_WO + (size_t)i*256*256, nullptr, tmp, MM, Dd, Dd);
        ln_res_kernel<<<MM/8, 256>>>(h, tmp, ln1_g + i*Dd, ln1_b + i*Dd);
        tgemm_kernel<1><<<gF1, 256>>>(h, wpk + OFF_W1 + (size_t)i*256*1024, ffn_b1 + i*DFF, scr, MM, DFF, Dd);
        tgemm_kernel<0><<<gP, 256>>>(scr, wpk + OFF_W2 + (size_t)i*1024*256, ffn_b2 + i*Dd, tmp, MM, Dd, DFF);
        ln_res_kernel<<<MM/8, 256>>>(h, tmp, ln2_g + i*Dd, ln2_b + i*Dd);
    }

    hmean_kernel<<<Bb, 256>>>(h, hmean);
    rowgemm_kernel<0><<<Bb, 256>>>(hmean, sha_Wq, nullptr, qv, Dd, Dd);
    tgemm_kernel<0><<<gP, 256>>>(h, wpk + OFF_SHA, nullptr, tmp, MM, Dd, Dd);
    scores_kernel<<<dim3(Nn/8, Bb), 256>>>(qv, tmp, scores);
    rowgemm_kernel<1><<<Bb, 256>>>(hmean, alloc_W1, alloc_b1, t1, Dd, Dd);
    rowgemm_kernel<0><<<Bb, 256>>>(t1, alloc_W2, alloc_b2, logits, Dd, Nn);

    float* out = (float*)d_out;
    finale_kernel<<<Bb, 256>>>(scores, gumbel, logits,
                               out,
                               out + Bb*Nn,
                               out + Bb*Nn + Bb*Kk);
}

// round 6
// speedup vs baseline: 4.5455x; 1.0468x over previous
#include <cuda_runtime.h>
#include <cstdint>

// ---------------- problem dims ----------------
#define Bb 64
#define Nn 1024
#define Din 16
#define Dd 256
#define Hh 4
#define DH 64
#define Ll 3
#define DFF 1024
#define Kk 64
#define MM (Bb*Nn)          // 65536 rows

// ---------------- scratch (static device memory) ----------------
__device__ float g_h[MM*Dd];            // hidden state (tf32-rounded fp32)
__device__ float g_scr[MM*DFF];         // qkv|ao or ffn hidden
__device__ float g_tmp[MM*Dd];          // proj/ffn out / kv
__device__ uint32_t g_wpk[2424832];     // tf32-packed weights
__device__ float g_hmean[Bb*Dd];
__device__ float g_qv[Bb*Dd];
__device__ float g_t1[Bb*Dd];
__device__ float g_logits[Bb*Nn];
__device__ float g_scores[Bb*Nn];

// packed-weight offsets (uint32 units)
#define OFF_QKV  0            // 3 layers x [256][768]
#define OFF_WO   589824       // 3 x [256][256]
#define OFF_W1   786432       // 3 x [256][1024]
#define OFF_W2   1572864      // 3 x [1024][256]
#define OFF_SHA  2359296      // [256][256]

__device__ __forceinline__ uint32_t f2tf32(float f) {
    uint32_t r;
    asm("cvt.rna.tf32.f32 %0, %1;" : "=r"(r) : "f"(f));
    return r;
}
__device__ __forceinline__ float rtf(float f) {   // round fp32 -> tf32-valid fp32
    return __uint_as_float(f2tf32(f));
}

__device__ __forceinline__ void mma_tf32(float* c, const uint32_t* a, const uint32_t* b) {
    asm volatile(
        "mma.sync.aligned.m16n8k8.row.col.f32.tf32.tf32.f32 "
        "{%0,%1,%2,%3}, {%4,%5,%6,%7}, {%8,%9}, {%0,%1,%2,%3};"
        : "+f"(c[0]), "+f"(c[1]), "+f"(c[2]), "+f"(c[3])
        : "r"(a[0]), "r"(a[1]), "r"(a[2]), "r"(a[3]), "r"(b[0]), "r"(b[1]));
}

__device__ __forceinline__ void cp16(void* smem, const void* gmem) {
    uint32_t s = (uint32_t)__cvta_generic_to_shared(smem);
    asm volatile("cp.async.cg.shared.global [%0], [%1], 16;" :: "r"(s), "l"(gmem));
}
#define CP_COMMIT() asm volatile("cp.async.commit_group;")
#define CP_WAIT0()  asm volatile("cp.async.wait_group 0;")

// ---------------- weight pack: fp32 [L][K][N] -> tf32 u32 with col offset ----------------
__global__ void packt_kernel(const float* __restrict__ src, uint32_t* __restrict__ dst,
                             int Nsrc, int dstStride, int colOff, int KN, int layerDstStride,
                             int total)
{
    int i = blockIdx.x*256 + threadIdx.x;
    if (i >= total) return;
    int l = i / KN;
    int rem = i - l*KN;
    int k = rem / Nsrc, n = rem - k*Nsrc;
    dst[(size_t)l*layerDstStride + (size_t)k*dstStride + colOff + n] = f2tf32(src[i]);
}

// ---------------- embedding (tf32-rounded output) ----------------
__global__ void embed_kernel(const float* __restrict__ x, const float* __restrict__ W,
                             const float* __restrict__ b, float* __restrict__ h)
{
    int m = blockIdx.x;
    int d = threadIdx.x;
    __shared__ float xs[Din];
    if (threadIdx.x < Din) xs[threadIdx.x] = x[m*Din + threadIdx.x];
    __syncthreads();
    float acc = b[d];
#pragma unroll
    for (int k = 0; k < Din; k++) acc = fmaf(xs[k], W[k*Dd + d], acc);
    h[(size_t)m*Dd + d] = rtf(acc);
}

// ---------------- TF32 tensor-core GEMM: cp.async, double-buffered, zero-cvt mainloop ----------------
// A: tf32-rounded fp32 (read as u32), Wp: tf32 u32, C: fp32 (optionally tf32-rounded)
#define AST 20
#define BST 136

template<int RELU, int ROUND>
__global__ __launch_bounds__(256, 2) void tgemm_kernel(
    const uint32_t* __restrict__ A, const uint32_t* __restrict__ Wp,
    const float* __restrict__ bias, float* __restrict__ C,
    int M, int Nd, int Kd)
{
    __shared__ __align__(16) uint32_t As[2][128*AST];
    __shared__ __align__(16) uint32_t Bs[2][16*BST];

    const int tid = threadIdx.x;
    const int warp = tid >> 5;
    const int lane = tid & 31;
    const int bm = blockIdx.y, bn = blockIdx.x;
    const int wm = warp & 3;
    const int wn = warp >> 2;
    const int qid = lane >> 2;
    const int tig = lane & 3;

    const int a_r0 = tid >> 2,  a_c0 = (tid & 3) << 2;
    const int a_r1 = a_r0 + 64;
    const int b_r0 = tid >> 5,  b_c0 = (tid & 31) << 2;
    const int b_r1 = b_r0 + 8;

    const uint32_t* Ap = A  + (size_t)(bm*128)*Kd;
    const uint32_t* Bp = Wp + (size_t)bn*128;

    float acc[2][8][4];
#pragma unroll
    for (int mt = 0; mt < 2; mt++)
#pragma unroll
        for (int nt = 0; nt < 8; nt++)
#pragma unroll
            for (int i = 0; i < 4; i++) acc[mt][nt][i] = 0.f;

    // prologue: async-load tile 0
    cp16(&As[0][a_r0*AST + a_c0], Ap + (size_t)a_r0*Kd + a_c0);
    cp16(&As[0][a_r1*AST + a_c0], Ap + (size_t)a_r1*Kd + a_c0);
    cp16(&Bs[0][b_r0*BST + b_c0], Bp + (size_t)b_r0*Nd + b_c0);
    cp16(&Bs[0][b_r1*BST + b_c0], Bp + (size_t)b_r1*Nd + b_c0);
    CP_COMMIT();
    CP_WAIT0();
    __syncthreads();

    const int niter = Kd >> 4;
    int buf = 0;
    for (int it = 0; it < niter; it++) {
        if (it + 1 < niter) {
            int nb = buf ^ 1;
            const uint32_t* Ap2 = Ap + (it+1)*16;
            const uint32_t* Bp2 = Bp + (size_t)((it+1)*16)*Nd;
            cp16(&As[nb][a_r0*AST + a_c0], Ap2 + (size_t)a_r0*Kd + a_c0);
            cp16(&As[nb][a_r1*AST + a_c0], Ap2 + (size_t)a_r1*Kd + a_c0);
            cp16(&Bs[nb][b_r0*BST + b_c0], Bp2 + (size_t)b_r0*Nd + b_c0);
            cp16(&Bs[nb][b_r1*BST + b_c0], Bp2 + (size_t)b_r1*Nd + b_c0);
            CP_COMMIT();
        }

        const uint32_t* Asu = As[buf];
        const uint32_t* Bsu = Bs[buf];
#pragma unroll
        for (int ks = 0; ks < 2; ks++) {
            const int ka = ks*8 + tig;
            uint32_t afrag[2][4];
#pragma unroll
            for (int mt = 0; mt < 2; mt++) {
                int r = wm*32 + mt*16 + qid;
                afrag[mt][0] = Asu[r*AST + ka];
                afrag[mt][1] = Asu[(r+8)*AST + ka];
                afrag[mt][2] = Asu[r*AST + ka + 4];
                afrag[mt][3] = Asu[(r+8)*AST + ka + 4];
            }
#pragma unroll
            for (int nt = 0; nt < 8; nt++) {
                int cn = wn*64 + nt*8 + qid;
                uint32_t bfrag[2];
                bfrag[0] = Bsu[(ks*8 + tig)*BST + cn];
                bfrag[1] = Bsu[(ks*8 + tig + 4)*BST + cn];
#pragma unroll
                for (int mt = 0; mt < 2; mt++)
                    mma_tf32(acc[mt][nt], afrag[mt], bfrag);
            }
        }

        if (it + 1 < niter) {
            CP_WAIT0();
            __syncthreads();
            buf ^= 1;
        }
    }

    // epilogue
#pragma unroll
    for (int mt = 0; mt < 2; mt++) {
        int r0 = bm*128 + wm*32 + mt*16 + qid;
#pragma unroll
        for (int nt = 0; nt < 8; nt++) {
            int c0 = bn*128 + wn*64 + nt*8 + tig*2;
            float b0 = bias ? bias[c0]   : 0.f;
            float b1 = bias ? bias[c0+1] : 0.f;
            float v0 = acc[mt][nt][0] + b0, v1 = acc[mt][nt][1] + b1;
            float v2 = acc[mt][nt][2] + b0, v3 = acc[mt][nt][3] + b1;
            if (RELU) {
                v0 = fmaxf(v0, 0.f); v1 = fmaxf(v1, 0.f);
                v2 = fmaxf(v2, 0.f); v3 = fmaxf(v3, 0.f);
            }
            if (ROUND) {
                v0 = rtf(v0); v1 = rtf(v1); v2 = rtf(v2); v3 = rtf(v3);
            }
            float2 p0; p0.x = v0; p0.y = v1;
            float2 p1; p1.x = v2; p1.y = v3;
            *(float2*)&C[(size_t)r0*Nd + c0]     = p0;
            *(float2*)&C[(size_t)(r0+8)*Nd + c0] = p1;
        }
    }
}

// ---------------- tensor-core flash attention (tf32, cp.async, zero-cvt loads) ----------------
// QKV buffer [M][768] already tf32-rounded; O [M][256] written tf32-rounded.
#define QKV_RS 768
#define O_RS   256
#define KST 76
#define VST 72
#define PST 72
#define ATT_SMEM ((64*KST + 64*VST + 8*16*PST)*4)

__global__ void __launch_bounds__(256) attn_mma_kernel(
    const float* __restrict__ QKV, float* __restrict__ O)
{
    extern __shared__ uint32_t sm[];
    uint32_t* Ks = sm;
    uint32_t* Vs = sm + 64*KST;
    const int tid = threadIdx.x;
    const int warp = tid >> 5, lane = tid & 31;
    const int qid = lane >> 2, tig = lane & 3;
    uint32_t* Ps = sm + 64*KST + 64*VST + warp*16*PST;

    const int qt = blockIdx.x, head = blockIdx.y, b = blockIdx.z;
    const size_t qbase = ((size_t)b*Nn)*QKV_RS + head*DH;
    const size_t kbase = qbase + 256;
    const size_t vbase = qbase + 512;
    const size_t obase = ((size_t)b*Nn)*O_RS + head*DH;
    const int q0 = qt*128 + warp*16;

    // Q fragments: scale = 0.125 = 2^-3, preserves tf32-validity -> no cvt
    uint32_t qa[8][4];
    const float scale = 0.125f;
#pragma unroll
    for (int s = 0; s < 8; s++) {
        int d0 = s*8;
        qa[s][0] = __float_as_uint(scale * QKV[qbase + (size_t)(q0+qid  )*QKV_RS + d0+tig  ]);
        qa[s][1] = __float_as_uint(scale * QKV[qbase + (size_t)(q0+qid+8)*QKV_RS + d0+tig  ]);
        qa[s][2] = __float_as_uint(scale * QKV[qbase + (size_t)(q0+qid  )*QKV_RS + d0+tig+4]);
        qa[s][3] = __float_as_uint(scale * QKV[qbase + (size_t)(q0+qid+8)*QKV_RS + d0+tig+4]);
    }

    float oacc[8][4];
#pragma unroll
    for (int dn = 0; dn < 8; dn++)
#pragma unroll
        for (int i = 0; i < 4; i++) oacc[dn][i] = 0.f;
    float m0 = -1e30f, m1 = -1e30f, l0 = 0.f, l1 = 0.f;

    const int lr = tid >> 4;           // 0..15
    const int lc = (tid & 15) << 2;    // 0..60

    for (int j0 = 0; j0 < Nn; j0 += 64) {
        // async K/V tile load (raw 16B copies; data already tf32-valid)
#pragma unroll
        for (int rr = 0; rr < 4; rr++) {
            int r = lr + rr*16;
            cp16(&Ks[r*KST + lc], QKV + kbase + (size_t)(j0+r)*QKV_RS + lc);
            cp16(&Vs[r*VST + lc], QKV + vbase + (size_t)(j0+r)*QKV_RS + lc);
        }
        CP_COMMIT();
        CP_WAIT0();
        __syncthreads();

        // S = Q @ K^T (scaled)
        float sacc[8][4];
#pragma unroll
        for (int nt = 0; nt < 8; nt++)
#pragma unroll
            for (int i = 0; i < 4; i++) sacc[nt][i] = 0.f;
#pragma unroll
        for (int s = 0; s < 8; s++) {
#pragma unroll
            for (int nt = 0; nt < 8; nt++) {
                uint32_t bfrag[2];
                bfrag[0] = Ks[(nt*8+qid)*KST + s*8 + tig];
                bfrag[1] = Ks[(nt*8+qid)*KST + s*8 + tig + 4];
                mma_tf32(sacc[nt], qa[s], bfrag);
            }
        }

        // online softmax
        float tm0 = -1e30f, tm1 = -1e30f;
#pragma unroll
        for (int nt = 0; nt < 8; nt++) {
            tm0 = fmaxf(tm0, fmaxf(sacc[nt][0], sacc[nt][1]));
            tm1 = fmaxf(tm1, fmaxf(sacc[nt][2], sacc[nt][3]));
        }
        tm0 = fmaxf(tm0, __shfl_xor_sync(0xffffffffu, tm0, 1));
        tm0 = fmaxf(tm0, __shfl_xor_sync(0xffffffffu, tm0, 2));
        tm1 = fmaxf(tm1, __shfl_xor_sync(0xffffffffu, tm1, 1));
        tm1 = fmaxf(tm1, __shfl_xor_sync(0xffffffffu, tm1, 2));
        float mn0 = fmaxf(m0, tm0), mn1 = fmaxf(m1, tm1);
        float c0 = __expf(m0 - mn0), c1 = __expf(m1 - mn1);
        m0 = mn0; m1 = mn1;
        l0 *= c0; l1 *= c1;
#pragma unroll
        for (int dn = 0; dn < 8; dn++) {
            oacc[dn][0] *= c0; oacc[dn][1] *= c0;
            oacc[dn][2] *= c1; oacc[dn][3] *= c1;
        }
#pragma unroll
        for (int nt = 0; nt < 8; nt++) {
            float p0 = __expf(sacc[nt][0] - m0);
            float p1 = __expf(sacc[nt][1] - m0);
            float p2 = __expf(sacc[nt][2] - m1);
            float p3 = __expf(sacc[nt][3] - m1);
            l0 += p0 + p1; l1 += p2 + p3;
            Ps[qid*PST     + nt*8 + 2*tig    ] = f2tf32(p0);
            Ps[qid*PST     + nt*8 + 2*tig + 1] = f2tf32(p1);
            Ps[(qid+8)*PST + nt*8 + 2*tig    ] = f2tf32(p2);
            Ps[(qid+8)*PST + nt*8 + 2*tig + 1] = f2tf32(p3);
        }
        __syncwarp();

        // O += P @ V
#pragma unroll
        for (int sj = 0; sj < 8; sj++) {
            uint32_t afrag[4];
            afrag[0] = Ps[qid*PST     + sj*8 + tig    ];
            afrag[1] = Ps[(qid+8)*PST + sj*8 + tig    ];
            afrag[2] = Ps[qid*PST     + sj*8 + tig + 4];
            afrag[3] = Ps[(qid+8)*PST + sj*8 + tig + 4];
#pragma unroll
            for (int dn = 0; dn < 8; dn++) {
                uint32_t bfrag[2];
                bfrag[0] = Vs[(sj*8+tig  )*VST + dn*8 + qid];
                bfrag[1] = Vs[(sj*8+tig+4)*VST + dn*8 + qid];
                mma_tf32(oacc[dn], afrag, bfrag);
            }
        }
        __syncthreads();
    }

    l0 += __shfl_xor_sync(0xffffffffu, l0, 1);
    l0 += __shfl_xor_sync(0xffffffffu, l0, 2);
    l1 += __shfl_xor_sync(0xffffffffu, l1, 1);
    l1 += __shfl_xor_sync(0xffffffffu, l1, 2);
    float inv0 = 1.f / l0, inv1 = 1.f / l1;
    float* o0 = O + obase + (size_t)(q0+qid)*O_RS;
    float* o1 = O + obase + (size_t)(q0+qid+8)*O_RS;
#pragma unroll
    for (int dn = 0; dn < 8; dn++) {
        int c = dn*8 + 2*tig;
        float2 r0; r0.x = rtf(oacc[dn][0]*inv0); r0.y = rtf(oacc[dn][1]*inv0);
        float2 r1; r1.x = rtf(oacc[dn][2]*inv1); r1.y = rtf(oacc[dn][3]*inv1);
        *(float2*)(o0 + c) = r0;
        *(float2*)(o1 + c) = r1;
    }
}

// ---------------- LayerNorm(h + res) in place (tf32-rounded store) ----------------
__global__ void ln_res_kernel(float* __restrict__ h, const float* __restrict__ res,
                              const float* __restrict__ g, const float* __restrict__ bta)
{
    int row = blockIdx.x*8 + (threadIdx.x >> 5);
    int lane = threadIdx.x & 31;
    size_t off = (size_t)row * Dd;
    float v[8];
    float s = 0.f;
#pragma unroll
    for (int i = 0; i < 8; i++) {
        int c = lane + i*32;
        v[i] = h[off+c] + res[off+c];
        s += v[i];
    }
#pragma unroll
    for (int o = 16; o; o >>= 1) s += __shfl_xor_sync(0xffffffffu, s, o);
    float mean = s * (1.f/256.f);
    float vs = 0.f;
#pragma unroll
    for (int i = 0; i < 8; i++) { float d = v[i]-mean; vs = fmaf(d, d, vs); }
#pragma unroll
    for (int o = 16; o; o >>= 1) vs += __shfl_xor_sync(0xffffffffu, vs, o);
    float rstd = rsqrtf(vs * (1.f/256.f) + 1e-5f);
#pragma unroll
    for (int i = 0; i < 8; i++) {
        int c = lane + i*32;
        h[off+c] = rtf((v[i]-mean)*rstd*g[c] + bta[c]);
    }
}

// ---------------- h_mean ----------------
__global__ void hmean_kernel(const float* __restrict__ h, float* __restrict__ hm)
{
    int b = blockIdx.x, d = threadIdx.x;
    const float* p = h + (size_t)b*Nn*Dd + d;
    float s = 0.f;
#pragma unroll 8
    for (int n = 0; n < Nn; n++) s += p[(size_t)n*Dd];
    hm[b*Dd + d] = s * (1.f/1024.f);
}

// ---------------- small row GEMM ----------------
template<int RELU>
__global__ void rowgemm_kernel(const float* __restrict__ A, const float* __restrict__ W,
                               const float* __restrict__ bias, float* __restrict__ C,
                               int Kd, int Nd)
{
    int b = blockIdx.x;
    __shared__ float xs[1024];
    for (int i = threadIdx.x; i < Kd; i += blockDim.x) xs[i] = A[(size_t)b*Kd + i];
    __syncthreads();
    for (int d = threadIdx.x; d < Nd; d += blockDim.x) {
        float acc = bias ? bias[d] : 0.f;
        for (int k = 0; k < Kd; k++) acc = fmaf(xs[k], W[(size_t)k*Nd + d], acc);
        if (RELU) acc = fmaxf(acc, 0.f);
        C[(size_t)b*Nd + d] = acc;
    }
}

// ---------------- scores ----------------
__global__ void scores_kernel(const float* __restrict__ qv, const float* __restrict__ kv,
                              float* __restrict__ scores)
{
    int b = blockIdx.y;
    int n = blockIdx.x*8 + (threadIdx.x >> 5);
    int lane = threadIdx.x & 31;
    const float* k = kv + ((size_t)b*Nn + n)*Dd;
    const float* q = qv + b*Dd;
    float s = 0.f;
#pragma unroll
    for (int i = 0; i < 8; i++) { int c = lane + i*32; s = fmaf(q[c], k[c], s); }
#pragma unroll
    for (int o = 16; o; o >>= 1) s += __shfl_xor_sync(0xffffffffu, s, o);
    if (lane == 0) scores[b*Nn + n] = s * (1.f/16.f);
}

// ---------------- finale: softmaxes + top-64 + sel ----------------
__global__ void finale_kernel(const float* __restrict__ scores, const float* __restrict__ gumbel,
                              const float* __restrict__ logits,
                              float* __restrict__ out_w, float* __restrict__ out_idx,
                              float* __restrict__ out_sel)
{
    int b = blockIdx.x, tid = threadIdx.x;
    __shared__ float w[1024];
    __shared__ float al[1024];
    __shared__ float red[256];
    __shared__ int   redi[256];
    __shared__ int   selidx[64];

    float lm = -1e30f;
    for (int i = tid; i < 1024; i += 256) {
        float v = (scores[b*Nn+i] + gumbel[b*Nn+i]) * 2.0f;
        w[i] = v; lm = fmaxf(lm, v);
    }
    red[tid] = lm; __syncthreads();
    for (int s = 128; s; s >>= 1) { if (tid < s) red[tid] = fmaxf(red[tid], red[tid+s]); __syncthreads(); }
    float M = red[0]; __syncthreads();
    float ls = 0.f;
    for (int i = tid; i < 1024; i += 256) { float e = __expf(w[i]-M); w[i] = e; ls += e; }
    red[tid] = ls; __syncthreads();
    for (int s = 128; s; s >>= 1) { if (tid < s) red[tid] += red[tid+s]; __syncthreads(); }
    float invS = 1.f / red[0]; __syncthreads();
    for (int i = tid; i < 1024; i += 256) {
        float wi = w[i]*invS; w[i] = wi; out_w[b*Nn+i] = wi;
    }

    lm = -1e30f;
    for (int i = tid; i < 1024; i += 256) { float v = logits[b*Nn+i]; al[i] = v; lm = fmaxf(lm, v); }
    __syncthreads();
    red[tid] = lm; __syncthreads();
    for (int s = 128; s; s >>= 1) { if (tid < s) red[tid] = fmaxf(red[tid], red[tid+s]); __syncthreads(); }
    M = red[0]; __syncthreads();
    ls = 0.f;
    for (int i = tid; i < 1024; i += 256) { float e = __expf(al[i]-M); al[i] = e; ls += e; }
    red[tid] = ls; __syncthreads();
    for (int s = 128; s; s >>= 1) { if (tid < s) red[tid] += red[tid+s]; __syncthreads(); }
    invS = 1.f / red[0]; __syncthreads();
    for (int i = tid; i < 1024; i += 256) al[i] *= invS;
    __syncthreads();

    for (int kk = 0; kk < 64; kk++) {
        float bv = -1e30f; int bi = 0x7fffffff;
        for (int i = tid; i < 1024; i += 256) {
            float v = w[i];
            if (v > bv) { bv = v; bi = i; }
        }
        red[tid] = bv; redi[tid] = bi; __syncthreads();
        for (int s = 128; s; s >>= 1) {
            if (tid < s) {
                float ov = red[tid+s]; int oi = redi[tid+s];
                if (ov > red[tid] || (ov == red[tid] && oi < redi[tid])) { red[tid] = ov; redi[tid] = oi; }
            }
            __syncthreads();
        }
        if (tid == 0) { selidx[kk] = redi[0]; w[redi[0]] = -2e30f; }
        __syncthreads();
    }

    float sv = 0.f;
    if (tid < 64) sv = al[selidx[tid]];
    red[tid] = (tid < 64) ? sv : 0.f; __syncthreads();
    for (int s = 128; s; s >>= 1) { if (tid < s) red[tid] += red[tid+s]; __syncthreads(); }
    float inv = 1.f / (red[0] + 1e-12f);
    if (tid < 64) {
        out_idx[b*64 + tid] = (float)selidx[tid];
        out_sel[b*64 + tid] = sv * inv;
    }
}

// ---------------- launch ----------------
extern "C" void kernel_launch(void* const* d_in, const int* in_sizes, int n_in,
                              void* d_out, int out_size)
{
    const float* x       = (const float*)d_in[0];
    const float* gumbel  = (const float*)d_in[1];
    const float* emb_W   = (const float*)d_in[2];
    const float* emb_b   = (const float*)d_in[3];
    const float* Wq      = (const float*)d_in[4];
    const float* Wk      = (const float*)d_in[5];
    const float* Wv      = (const float*)d_in[6];
    const float* Wo      = (const float*)d_in[7];
    const float* ln1_g   = (const float*)d_in[8];
    const float* ln1_b   = (const float*)d_in[9];
    const float* ln2_g   = (const float*)d_in[10];
    const float* ln2_b   = (const float*)d_in[11];
    const float* ffn_W1  = (const float*)d_in[12];
    const float* ffn_b1  = (const float*)d_in[13];
    const float* ffn_W2  = (const float*)d_in[14];
    const float* ffn_b2  = (const float*)d_in[15];
    const float* sha_Wq  = (const float*)d_in[16];
    const float* sha_Wk  = (const float*)d_in[17];
    const float* alloc_W1= (const float*)d_in[18];
    const float* alloc_b1= (const float*)d_in[19];
    const float* alloc_W2= (const float*)d_in[20];
    const float* alloc_b2= (const float*)d_in[21];

    float *h, *scr, *tmp, *hmean, *qv, *t1, *logits, *scores;
    uint32_t* wpk;
    cudaGetSymbolAddress((void**)&h,      g_h);
    cudaGetSymbolAddress((void**)&scr,    g_scr);
    cudaGetSymbolAddress((void**)&tmp,    g_tmp);
    cudaGetSymbolAddress((void**)&wpk,    g_wpk);
    cudaGetSymbolAddress((void**)&hmean,  g_hmean);
    cudaGetSymbolAddress((void**)&qv,     g_qv);
    cudaGetSymbolAddress((void**)&t1,     g_t1);
    cudaGetSymbolAddress((void**)&logits, g_logits);
    cudaGetSymbolAddress((void**)&scores, g_scores);

    static int att_cfg = 0;
    if (!att_cfg) {
        cudaFuncSetAttribute(attn_mma_kernel,
                             cudaFuncAttributeMaxDynamicSharedMemorySize, ATT_SMEM);
        att_cfg = 1;
    }

    // pack weights -> tf32 u32 (QKV fused side-by-side into [256][768])
    {
        int t;
        t = 3*256*256;
        packt_kernel<<<(t+255)/256, 256>>>(Wq, wpk + OFF_QKV, 256, 768, 0,   256*256, 256*768, t);
        packt_kernel<<<(t+255)/256, 256>>>(Wk, wpk + OFF_QKV, 256, 768, 256, 256*256, 256*768, t);
        packt_kernel<<<(t+255)/256, 256>>>(Wv, wpk + OFF_QKV, 256, 768, 512, 256*256, 256*768, t);
        packt_kernel<<<(t+255)/256, 256>>>(Wo, wpk + OFF_WO, 256, 256, 0, 256*256, 256*256, t);
        t = 3*256*1024;
        packt_kernel<<<(t+255)/256, 256>>>(ffn_W1, wpk + OFF_W1, 1024, 1024, 0, 256*1024, 256*1024, t);
        packt_kernel<<<(t+255)/256, 256>>>(ffn_W2, wpk + OFF_W2, 256, 256, 0, 1024*256, 1024*256, t);
        t = 256*256;
        packt_kernel<<<(t+255)/256, 256>>>(sha_Wk, wpk + OFF_SHA, 256, 256, 0, 256*256, 256*256, t);
    }

    float* qkv = scr;                           // [M][768]
    float* ao  = scr + (size_t)MM*768;          // [M][256]

    embed_kernel<<<MM, 256>>>(x, emb_W, emb_b, h);

    const dim3 gQKV(768/128, MM/128);  // (6,512)
    const dim3 gP(Dd/128, MM/128);     // (2,512)
    const dim3 gF1(DFF/128, MM/128);   // (8,512)

    for (int i = 0; i < Ll; i++) {
        tgemm_kernel<0,1><<<gQKV, 256>>>((const uint32_t*)h, wpk + OFF_QKV + (size_t)i*256*768, nullptr, qkv, MM, 768, Dd);
        attn_mma_kernel<<<dim3(Nn/128, Hh, Bb), 256, ATT_SMEM>>>(qkv, ao);
        tgemm_kernel<0,0><<<gP, 256>>>((const uint32_t*)ao, wpk + OFF_WO + (size_t)i*256*256, nullptr, tmp, MM, Dd, Dd);
        ln_res_kernel<<<MM/8, 256>>>(h, tmp, ln1_g + i*Dd, ln1_b + i*Dd);
        tgemm_kernel<1,1><<<gF1, 256>>>((const uint32_t*)h, wpk + OFF_W1 + (size_t)i*256*1024, ffn_b1 + i*DFF, scr, MM, DFF, Dd);
        tgemm_kernel<0,0><<<gP, 256>>>((const uint32_t*)scr, wpk + OFF_W2 + (size_t)i*1024*256, ffn_b2 + i*Dd, tmp, MM, Dd, DFF);
        ln_res_kernel<<<MM/8, 256>>>(h, tmp, ln2_g + i*Dd, ln2_b + i*Dd);
    }

    hmean_kernel<<<Bb, 256>>>(h, hmean);
    rowgemm_kernel<0><<<Bb, 256>>>(hmean, sha_Wq, nullptr, qv, Dd, Dd);
    tgemm_kernel<0,0><<<gP, 256>>>((const uint32_t*)h, wpk + OFF_SHA, nullptr, tmp, MM, Dd, Dd);
    scores_kernel<<<dim3(Nn/8, Bb), 256>>>(qv, tmp, scores);
    rowgemm_kernel<1><<<Bb, 256>>>(hmean, alloc_W1, alloc_b1, t1, Dd, Dd);
    rowgemm_kernel<0><<<Bb, 256>>>(t1, alloc_W2, alloc_b2, logits, Dd, Nn);

    float* out = (float*)d_out;
    finale_kernel<<<Bb, 256>>>(scores, gumbel, logits,
                               out,
                               out + Bb*Nn,
                               out + Bb*Nn + Bb*Kk);
}

// round 7
// speedup vs baseline: 4.6529x; 1.0236x over previous
#include <cuda_runtime.h>
#include <cstdint>

// ---------------- problem dims ----------------
#define Bb 64
#define Nn 1024
#define Din 16
#define Dd 256
#define Hh 4
#define DH 64
#define Ll 3
#define DFF 1024
#define Kk 64
#define MM (Bb*Nn)          // 65536 rows

// ---------------- scratch (static device memory) ----------------
__device__ float g_h[MM*Dd];            // hidden state (tf32-rounded fp32)
__device__ float g_scr[MM*DFF];         // qkv|ao or ffn hidden
__device__ float g_tmp[MM*Dd];          // proj/ffn out / kv
__device__ uint32_t g_wpk[2424832];     // tf32-packed weights
__device__ float g_hmean[Bb*Dd];
__device__ float g_qv[Bb*Dd];
__device__ float g_t1[Bb*Dd];
__device__ float g_logits[Bb*Nn];
__device__ float g_scores[Bb*Nn];

// packed-weight offsets (uint32 units)
#define OFF_QKV  0            // 3 layers x [256][768]
#define OFF_WO   589824       // 3 x [256][256]
#define OFF_W1   786432       // 3 x [256][1024]
#define OFF_W2   1572864      // 3 x [1024][256]
#define OFF_SHA  2359296      // [256][256]

__device__ __forceinline__ uint32_t f2tf32(float f) {
    uint32_t r;
    asm("cvt.rna.tf32.f32 %0, %1;" : "=r"(r) : "f"(f));
    return r;
}
__device__ __forceinline__ float rtf(float f) {
    return __uint_as_float(f2tf32(f));
}

__device__ __forceinline__ void mma_tf32(float* c, const uint32_t* a, const uint32_t* b) {
    asm volatile(
        "mma.sync.aligned.m16n8k8.row.col.f32.tf32.tf32.f32 "
        "{%0,%1,%2,%3}, {%4,%5,%6,%7}, {%8,%9}, {%0,%1,%2,%3};"
        : "+f"(c[0]), "+f"(c[1]), "+f"(c[2]), "+f"(c[3])
        : "r"(a[0]), "r"(a[1]), "r"(a[2]), "r"(a[3]), "r"(b[0]), "r"(b[1]));
}

__device__ __forceinline__ void cp16(void* smem, const void* gmem) {
    uint32_t s = (uint32_t)__cvta_generic_to_shared(smem);
    asm volatile("cp.async.cg.shared.global [%0], [%1], 16;" :: "r"(s), "l"(gmem));
}
#define CP_COMMIT() asm volatile("cp.async.commit_group;")
#define CP_WAIT(n)  asm volatile("cp.async.wait_group %0;" :: "n"(n))

// ---------------- weight pack ----------------
__global__ void packt_kernel(const float* __restrict__ src, uint32_t* __restrict__ dst,
                             int Nsrc, int dstStride, int colOff, int KN, int layerDstStride,
                             int total)
{
    int i = blockIdx.x*256 + threadIdx.x;
    if (i >= total) return;
    int l = i / KN;
    int rem = i - l*KN;
    int k = rem / Nsrc, n = rem - k*Nsrc;
    dst[(size_t)l*layerDstStride + (size_t)k*dstStride + colOff + n] = f2tf32(src[i]);
}

// ---------------- embedding ----------------
__global__ void embed_kernel(const float* __restrict__ x, const float* __restrict__ W,
                             const float* __restrict__ b, float* __restrict__ h)
{
    int m = blockIdx.x;
    int d = threadIdx.x;
    __shared__ float xs[Din];
    if (threadIdx.x < Din) xs[threadIdx.x] = x[m*Din + threadIdx.x];
    __syncthreads();
    float acc = b[d];
#pragma unroll
    for (int k = 0; k < Din; k++) acc = fmaf(xs[k], W[k*Dd + d], acc);
    h[(size_t)m*Dd + d] = rtf(acc);
}

// ---------------- TF32 GEMM: 4-stage cp.async pipeline ----------------
#define AST 20
#define BST 136
#define A_SZ (128*AST)        // 2560 u32 per stage
#define B_SZ (16*BST)         // 2176 u32 per stage
#define TG_SMEM (4*(A_SZ + B_SZ)*4)   // 75776 bytes

template<int RELU, int ROUND>
__global__ __launch_bounds__(256, 2) void tgemm_kernel(
    const uint32_t* __restrict__ A, const uint32_t* __restrict__ Wp,
    const float* __restrict__ bias, float* __restrict__ C,
    int M, int Nd, int Kd)
{
    extern __shared__ uint32_t dsm[];
    uint32_t* Asm = dsm;               // [4][A_SZ]
    uint32_t* Bsm = dsm + 4*A_SZ;      // [4][B_SZ]

    const int tid = threadIdx.x;
    const int warp = tid >> 5;
    const int lane = tid & 31;
    const int bm = blockIdx.y, bn = blockIdx.x;
    const int wm = warp & 3;
    const int wn = warp >> 2;
    const int qid = lane >> 2;
    const int tig = lane & 3;

    const int a_r0 = tid >> 2,  a_c0 = (tid & 3) << 2;
    const int a_r1 = a_r0 + 64;
    const int b_r0 = tid >> 5,  b_c0 = (tid & 31) << 2;
    const int b_r1 = b_r0 + 8;

    const uint32_t* Ap = A  + (size_t)(bm*128)*Kd;
    const uint32_t* Bp = Wp + (size_t)bn*128;

    float acc[2][8][4];
#pragma unroll
    for (int mt = 0; mt < 2; mt++)
#pragma unroll
        for (int nt = 0; nt < 8; nt++)
#pragma unroll
            for (int i = 0; i < 4; i++) acc[mt][nt][i] = 0.f;

    const int niter = Kd >> 4;   // >= 16 always

    // prologue: preload tiles 0..2
#pragma unroll
    for (int s = 0; s < 3; s++) {
        const uint32_t* Ap2 = Ap + s*16;
        const uint32_t* Bp2 = Bp + (size_t)(s*16)*Nd;
        cp16(&Asm[s*A_SZ + a_r0*AST + a_c0], Ap2 + (size_t)a_r0*Kd + a_c0);
        cp16(&Asm[s*A_SZ + a_r1*AST + a_c0], Ap2 + (size_t)a_r1*Kd + a_c0);
        cp16(&Bsm[s*B_SZ + b_r0*BST + b_c0], Bp2 + (size_t)b_r0*Nd + b_c0);
        cp16(&Bsm[s*B_SZ + b_r1*BST + b_c0], Bp2 + (size_t)b_r1*Nd + b_c0);
        CP_COMMIT();
    }

    for (int it = 0; it < niter; it++) {
        CP_WAIT(2);            // tile 'it' resident
        __syncthreads();

        int pf = it + 3;
        if (pf < niter) {
            int sb = pf & 3;
            const uint32_t* Ap2 = Ap + pf*16;
            const uint32_t* Bp2 = Bp + (size_t)(pf*16)*Nd;
            cp16(&Asm[sb*A_SZ + a_r0*AST + a_c0], Ap2 + (size_t)a_r0*Kd + a_c0);
            cp16(&Asm[sb*A_SZ + a_r1*AST + a_c0], Ap2 + (size_t)a_r1*Kd + a_c0);
            cp16(&Bsm[sb*B_SZ + b_r0*BST + b_c0], Bp2 + (size_t)b_r0*Nd + b_c0);
            cp16(&Bsm[sb*B_SZ + b_r1*BST + b_c0], Bp2 + (size_t)b_r1*Nd + b_c0);
        }
        CP_COMMIT();           // empty commit near tail keeps group count exact

        const uint32_t* Asu = &Asm[(it & 3)*A_SZ];
        const uint32_t* Bsu = &Bsm[(it & 3)*B_SZ];
#pragma unroll
        for (int ks = 0; ks < 2; ks++) {
            const int ka = ks*8 + tig;
            uint32_t afrag[2][4];
#pragma unroll
            for (int mt = 0; mt < 2; mt++) {
                int r = wm*32 + mt*16 + qid;
                afrag[mt][0] = Asu[r*AST + ka];
                afrag[mt][1] = Asu[(r+8)*AST + ka];
                afrag[mt][2] = Asu[r*AST + ka + 4];
                afrag[mt][3] = Asu[(r+8)*AST + ka + 4];
            }
#pragma unroll
            for (int nt = 0; nt < 8; nt++) {
                int cn = wn*64 + nt*8 + qid;
                uint32_t bfrag[2];
                bfrag[0] = Bsu[(ks*8 + tig)*BST + cn];
                bfrag[1] = Bsu[(ks*8 + tig + 4)*BST + cn];
#pragma unroll
                for (int mt = 0; mt < 2; mt++)
                    mma_tf32(acc[mt][nt], afrag[mt], bfrag);
            }
        }
    }

    // epilogue
#pragma unroll
    for (int mt = 0; mt < 2; mt++) {
        int r0 = bm*128 + wm*32 + mt*16 + qid;
#pragma unroll
        for (int nt = 0; nt < 8; nt++) {
            int c0 = bn*128 + wn*64 + nt*8 + tig*2;
            float b0 = bias ? bias[c0]   : 0.f;
            float b1 = bias ? bias[c0+1] : 0.f;
            float v0 = acc[mt][nt][0] + b0, v1 = acc[mt][nt][1] + b1;
            float v2 = acc[mt][nt][2] + b0, v3 = acc[mt][nt][3] + b1;
            if (RELU) {
                v0 = fmaxf(v0, 0.f); v1 = fmaxf(v1, 0.f);
                v2 = fmaxf(v2, 0.f); v3 = fmaxf(v3, 0.f);
            }
            if (ROUND) {
                v0 = rtf(v0); v1 = rtf(v1); v2 = rtf(v2); v3 = rtf(v3);
            }
            float2 p0; p0.x = v0; p0.y = v1;
            float2 p1; p1.x = v2; p1.y = v3;
            *(float2*)&C[(size_t)r0*Nd + c0]     = p0;
            *(float2*)&C[(size_t)(r0+8)*Nd + c0] = p1;
        }
    }
}

// ---------------- flash attention: tf32 MMA, double-buffered K/V ----------------
#define QKV_RS 768
#define O_RS   256
#define KST 76
#define VST 72
#define PST 72
#define K_SZ (64*KST)
#define V_SZ (64*VST)
#define ATT_SMEM ((2*K_SZ + 2*V_SZ + 8*16*PST)*4)

__global__ void __launch_bounds__(256) attn_mma_kernel(
    const float* __restrict__ QKV, float* __restrict__ O)
{
    extern __shared__ uint32_t sm[];
    uint32_t* KsB = sm;                     // [2][K_SZ]
    uint32_t* VsB = sm + 2*K_SZ;            // [2][V_SZ]
    const int tid = threadIdx.x;
    const int warp = tid >> 5, lane = tid & 31;
    const int qid = lane >> 2, tig = lane & 3;
    uint32_t* Ps = sm + 2*K_SZ + 2*V_SZ + warp*16*PST;

    const int qt = blockIdx.x, head = blockIdx.y, b = blockIdx.z;
    const size_t qbase = ((size_t)b*Nn)*QKV_RS + head*DH;
    const size_t kbase = qbase + 256;
    const size_t vbase = qbase + 512;
    const size_t obase = ((size_t)b*Nn)*O_RS + head*DH;
    const int q0 = qt*128 + warp*16;

    // Q fragments: scale = 2^-3 preserves tf32-validity
    uint32_t qa[8][4];
    const float scale = 0.125f;
#pragma unroll
    for (int s = 0; s < 8; s++) {
        int d0 = s*8;
        qa[s][0] = __float_as_uint(scale * QKV[qbase + (size_t)(q0+qid  )*QKV_RS + d0+tig  ]);
        qa[s][1] = __float_as_uint(scale * QKV[qbase + (size_t)(q0+qid+8)*QKV_RS + d0+tig  ]);
        qa[s][2] = __float_as_uint(scale * QKV[qbase + (size_t)(q0+qid  )*QKV_RS + d0+tig+4]);
        qa[s][3] = __float_as_uint(scale * QKV[qbase + (size_t)(q0+qid+8)*QKV_RS + d0+tig+4]);
    }

    float oacc[8][4];
#pragma unroll
    for (int dn = 0; dn < 8; dn++)
#pragma unroll
        for (int i = 0; i < 4; i++) oacc[dn][i] = 0.f;
    float m0 = -1e30f, m1 = -1e30f, l0 = 0.f, l1 = 0.f;

    const int lr = tid >> 4;           // 0..15
    const int lc = (tid & 15) << 2;    // 0..60

    // prologue: async-load tile 0 into stage 0
#pragma unroll
    for (int rr = 0; rr < 4; rr++) {
        int r = lr + rr*16;
        cp16(&KsB[r*KST + lc], QKV + kbase + (size_t)r*QKV_RS + lc);
        cp16(&VsB[r*VST + lc], QKV + vbase + (size_t)r*QKV_RS + lc);
    }
    CP_COMMIT();

    int buf = 0;
    const int ntile = Nn/64;
    for (int jt = 0; jt < ntile; jt++) {
        // prefetch next tile into the other stage
        if (jt + 1 < ntile) {
            int j1 = (jt+1)*64;
            int nb = buf ^ 1;
#pragma unroll
            for (int rr = 0; rr < 4; rr++) {
                int r = lr + rr*16;
                cp16(&KsB[nb*K_SZ + r*KST + lc], QKV + kbase + (size_t)(j1+r)*QKV_RS + lc);
                cp16(&VsB[nb*V_SZ + r*VST + lc], QKV + vbase + (size_t)(j1+r)*QKV_RS + lc);
            }
        }
        CP_COMMIT();
        CP_WAIT(1);            // current tile resident
        __syncthreads();

        const uint32_t* Ks = &KsB[buf*K_SZ];
        const uint32_t* Vs = &VsB[buf*V_SZ];

        // S = Q @ K^T (scaled)
        float sacc[8][4];
#pragma unroll
        for (int nt = 0; nt < 8; nt++)
#pragma unroll
            for (int i = 0; i < 4; i++) sacc[nt][i] = 0.f;
#pragma unroll
        for (int s = 0; s < 8; s++) {
#pragma unroll
            for (int nt = 0; nt < 8; nt++) {
                uint32_t bfrag[2];
                bfrag[0] = Ks[(nt*8+qid)*KST + s*8 + tig];
                bfrag[1] = Ks[(nt*8+qid)*KST + s*8 + tig + 4];
                mma_tf32(sacc[nt], qa[s], bfrag);
            }
        }

        // online softmax
        float tm0 = -1e30f, tm1 = -1e30f;
#pragma unroll
        for (int nt = 0; nt < 8; nt++) {
            tm0 = fmaxf(tm0, fmaxf(sacc[nt][0], sacc[nt][1]));
            tm1 = fmaxf(tm1, fmaxf(sacc[nt][2], sacc[nt][3]));
        }
        tm0 = fmaxf(tm0, __shfl_xor_sync(0xffffffffu, tm0, 1));
        tm0 = fmaxf(tm0, __shfl_xor_sync(0xffffffffu, tm0, 2));
        tm1 = fmaxf(tm1, __shfl_xor_sync(0xffffffffu, tm1, 1));
        tm1 = fmaxf(tm1, __shfl_xor_sync(0xffffffffu, tm1, 2));
        float mn0 = fmaxf(m0, tm0), mn1 = fmaxf(m1, tm1);
        float c0 = __expf(m0 - mn0), c1 = __expf(m1 - mn1);
        m0 = mn0; m1 = mn1;
        l0 *= c0; l1 *= c1;
#pragma unroll
        for (int dn = 0; dn < 8; dn++) {
            oacc[dn][0] *= c0; oacc[dn][1] *= c0;
            oacc[dn][2] *= c1; oacc[dn][3] *= c1;
        }
#pragma unroll
        for (int nt = 0; nt < 8; nt++) {
            float p0 = __expf(sacc[nt][0] - m0);
            float p1 = __expf(sacc[nt][1] - m0);
            float p2 = __expf(sacc[nt][2] - m1);
            float p3 = __expf(sacc[nt][3] - m1);
            l0 += p0 + p1; l1 += p2 + p3;
            Ps[qid*PST     + nt*8 + 2*tig    ] = f2tf32(p0);
            Ps[qid*PST     + nt*8 + 2*tig + 1] = f2tf32(p1);
            Ps[(qid+8)*PST + nt*8 + 2*tig    ] = f2tf32(p2);
            Ps[(qid+8)*PST + nt*8 + 2*tig + 1] = f2tf32(p3);
        }
        __syncwarp();

        // O += P @ V
#pragma unroll
        for (int sj = 0; sj < 8; sj++) {
            uint32_t afrag[4];
            afrag[0] = Ps[qid*PST     + sj*8 + tig    ];
            afrag[1] = Ps[(qid+8)*PST + sj*8 + tig    ];
            afrag[2] = Ps[qid*PST     + sj*8 + tig + 4];
            afrag[3] = Ps[(qid+8)*PST + sj*8 + tig + 4];
#pragma unroll
            for (int dn = 0; dn < 8; dn++) {
                uint32_t bfrag[2];
                bfrag[0] = Vs[(sj*8+tig  )*VST + dn*8 + qid];
                bfrag[1] = Vs[(sj*8+tig+4)*VST + dn*8 + qid];
                mma_tf32(oacc[dn], afrag, bfrag);
            }
        }
        __syncthreads();       // all reads of 'buf' done before it is overwritten
        buf ^= 1;
    }

    l0 += __shfl_xor_sync(0xffffffffu, l0, 1);
    l0 += __shfl_xor_sync(0xffffffffu, l0, 2);
    l1 += __shfl_xor_sync(0xffffffffu, l1, 1);
    l1 += __shfl_xor_sync(0xffffffffu, l1, 2);
    float inv0 = 1.f / l0, inv1 = 1.f / l1;
    float* o0 = O + obase + (size_t)(q0+qid)*O_RS;
    float* o1 = O + obase + (size_t)(q0+qid+8)*O_RS;
#pragma unroll
    for (int dn = 0; dn < 8; dn++) {
        int c = dn*8 + 2*tig;
        float2 r0; r0.x = rtf(oacc[dn][0]*inv0); r0.y = rtf(oacc[dn][1]*inv0);
        float2 r1; r1.x = rtf(oacc[dn][2]*inv1); r1.y = rtf(oacc[dn][3]*inv1);
        *(float2*)(o0 + c) = r0;
        *(float2*)(o1 + c) = r1;
    }
}

// ---------------- LayerNorm(h + res), float4 vectorized ----------------
__global__ void ln_res_kernel(float* __restrict__ h, const float* __restrict__ res,
                              const float* __restrict__ g, const float* __restrict__ bta)
{
    int row = blockIdx.x*8 + (threadIdx.x >> 5);
    int lane = threadIdx.x & 31;
    size_t off = (size_t)row * Dd;
    float4 a0 = *(const float4*)&h[off + lane*4];
    float4 a1 = *(const float4*)&h[off + 128 + lane*4];
    float4 r0 = *(const float4*)&res[off + lane*4];
    float4 r1 = *(const float4*)&res[off + 128 + lane*4];
    float v[8];
    v[0] = a0.x + r0.x; v[1] = a0.y + r0.y; v[2] = a0.z + r0.z; v[3] = a0.w + r0.w;
    v[4] = a1.x + r1.x; v[5] = a1.y + r1.y; v[6] = a1.z + r1.z; v[7] = a1.w + r1.w;
    float s = 0.f;
#pragma unroll
    for (int i = 0; i < 8; i++) s += v[i];
#pragma unroll
    for (int o = 16; o; o >>= 1) s += __shfl_xor_sync(0xffffffffu, s, o);
    float mean = s * (1.f/256.f);
    float vs = 0.f;
#pragma unroll
    for (int i = 0; i < 8; i++) { float d = v[i]-mean; vs = fmaf(d, d, vs); }
#pragma unroll
    for (int o = 16; o; o >>= 1) vs += __shfl_xor_sync(0xffffffffu, vs, o);
    float rstd = rsqrtf(vs * (1.f/256.f) + 1e-5f);
    float4 g0 = *(const float4*)&g[lane*4];
    float4 g1 = *(const float4*)&g[128 + lane*4];
    float4 b0 = *(const float4*)&bta[lane*4];
    float4 b1 = *(const float4*)&bta[128 + lane*4];
    float4 o0, o1;
    o0.x = rtf((v[0]-mean)*rstd*g0.x + b0.x);
    o0.y = rtf((v[1]-mean)*rstd*g0.y + b0.y);
    o0.z = rtf((v[2]-mean)*rstd*g0.z + b0.z);
    o0.w = rtf((v[3]-mean)*rstd*g0.w + b0.w);
    o1.x = rtf((v[4]-mean)*rstd*g1.x + b1.x);
    o1.y = rtf((v[5]-mean)*rstd*g1.y + b1.y);
    o1.z = rtf((v[6]-mean)*rstd*g1.z + b1.z);
    o1.w = rtf((v[7]-mean)*rstd*g1.w + b1.w);
    *(float4*)&h[off + lane*4]       = o0;
    *(float4*)&h[off + 128 + lane*4] = o1;
}

// ---------------- h_mean ----------------
__global__ void hmean_kernel(const float* __restrict__ h, float* __restrict__ hm)
{
    int b = blockIdx.x, d = threadIdx.x;
    const float* p = h + (size_t)b*Nn*Dd + d;
    float s = 0.f;
#pragma unroll 8
    for (int n = 0; n < Nn; n++) s += p[(size_t)n*Dd];
    hm[b*Dd + d] = s * (1.f/1024.f);
}

// ---------------- small row GEMM ----------------
template<int RELU>
__global__ void rowgemm_kernel(const float* __restrict__ A, const float* __restrict__ W,
                               const float* __restrict__ bias, float* __restrict__ C,
                               int Kd, int Nd)
{
    int b = blockIdx.x;
    __shared__ float xs[1024];
    for (int i = threadIdx.x; i < Kd; i += blockDim.x) xs[i] = A[(size_t)b*Kd + i];
    __syncthreads();
    for (int d = threadIdx.x; d < Nd; d += blockDim.x) {
        float acc = bias ? bias[d] : 0.f;
        for (int k = 0; k < Kd; k++) acc = fmaf(xs[k], W[(size_t)k*Nd + d], acc);
        if (RELU) acc = fmaxf(acc, 0.f);
        C[(size_t)b*Nd + d] = acc;
    }
}

// ---------------- scores ----------------
__global__ void scores_kernel(const float* __restrict__ qv, const float* __restrict__ kv,
                              float* __restrict__ scores)
{
    int b = blockIdx.y;
    int n = blockIdx.x*8 + (threadIdx.x >> 5);
    int lane = threadIdx.x & 31;
    const float* k = kv + ((size_t)b*Nn + n)*Dd;
    const float* q = qv + b*Dd;
    float s = 0.f;
#pragma unroll
    for (int i = 0; i < 8; i++) { int c = lane + i*32; s = fmaf(q[c], k[c], s); }
#pragma unroll
    for (int o = 16; o; o >>= 1) s += __shfl_xor_sync(0xffffffffu, s, o);
    if (lane == 0) scores[b*Nn + n] = s * (1.f/16.f);
}

// ---------------- finale ----------------
__global__ void finale_kernel(const float* __restrict__ scores, const float* __restrict__ gumbel,
                              const float* __restrict__ logits,
                              float* __restrict__ out_w, float* __restrict__ out_idx,
                              float* __restrict__ out_sel)
{
    int b = blockIdx.x, tid = threadIdx.x;
    __shared__ float w[1024];
    __shared__ float al[1024];
    __shared__ float red[256];
    __shared__ int   redi[256];
    __shared__ int   selidx[64];

    float lm = -1e30f;
    for (int i = tid; i < 1024; i += 256) {
        float v = (scores[b*Nn+i] + gumbel[b*Nn+i]) * 2.0f;
        w[i] = v; lm = fmaxf(lm, v);
    }
    red[tid] = lm; __syncthreads();
    for (int s = 128; s; s >>= 1) { if (tid < s) red[tid] = fmaxf(red[tid], red[tid+s]); __syncthreads(); }
    float M = red[0]; __syncthreads();
    float ls = 0.f;
    for (int i = tid; i < 1024; i += 256) { float e = __expf(w[i]-M); w[i] = e; ls += e; }
    red[tid] = ls; __syncthreads();
    for (int s = 128; s; s >>= 1) { if (tid < s) red[tid] += red[tid+s]; __syncthreads(); }
    float invS = 1.f / red[0]; __syncthreads();
    for (int i = tid; i < 1024; i += 256) {
        float wi = w[i]*invS; w[i] = wi; out_w[b*Nn+i] = wi;
    }

    lm = -1e30f;
    for (int i = tid; i < 1024; i += 256) { float v = logits[b*Nn+i]; al[i] = v; lm = fmaxf(lm, v); }
    __syncthreads();
    red[tid] = lm; __syncthreads();
    for (int s = 128; s; s >>= 1) { if (tid < s) red[tid] = fmaxf(red[tid], red[tid+s]); __syncthreads(); }
    M = red[0]; __syncthreads();
    ls = 0.f;
    for (int i = tid; i < 1024; i += 256) { float e = __expf(al[i]-M); al[i] = e; ls += e; }
    red[tid] = ls; __syncthreads();
    for (int s = 128; s; s >>= 1) { if (tid < s) red[tid] += red[tid+s]; __syncthreads(); }
    invS = 1.f / red[0]; __syncthreads();
    for (int i = tid; i < 1024; i += 256) al[i] *= invS;
    __syncthreads();

    for (int kk = 0; kk < 64; kk++) {
        float bv = -1e30f; int bi = 0x7fffffff;
        for (int i = tid; i < 1024; i += 256) {
            float v = w[i];
            if (v > bv) { bv = v; bi = i; }
        }
        red[tid] = bv; redi[tid] = bi; __syncthreads();
        for (int s = 128; s; s >>= 1) {
            if (tid < s) {
                float ov = red[tid+s]; int oi = redi[tid+s];
                if (ov > red[tid] || (ov == red[tid] && oi < redi[tid])) { red[tid] = ov; redi[tid] = oi; }
            }
            __syncthreads();
        }
        if (tid == 0) { selidx[kk] = redi[0]; w[redi[0]] = -2e30f; }
        __syncthreads();
    }

    float sv = 0.f;
    if (tid < 64) sv = al[selidx[tid]];
    red[tid] = (tid < 64) ? sv : 0.f; __syncthreads();
    for (int s = 128; s; s >>= 1) { if (tid < s) red[tid] += red[tid+s]; __syncthreads(); }
    float inv = 1.f / (red[0] + 1e-12f);
    if (tid < 64) {
        out_idx[b*64 + tid] = (float)selidx[tid];
        out_sel[b*64 + tid] = sv * inv;
    }
}

// ---------------- launch ----------------
extern "C" void kernel_launch(void* const* d_in, const int* in_sizes, int n_in,
                              void* d_out, int out_size)
{
    const float* x       = (const float*)d_in[0];
    const float* gumbel  = (const float*)d_in[1];
    const float* emb_W   = (const float*)d_in[2];
    const float* emb_b   = (const float*)d_in[3];
    const float* Wq      = (const float*)d_in[4];
    const float* Wk      = (const float*)d_in[5];
    const float* Wv      = (const float*)d_in[6];
    const float* Wo      = (const float*)d_in[7];
    const float* ln1_g   = (const float*)d_in[8];
    const float* ln1_b   = (const float*)d_in[9];
    const float* ln2_g   = (const float*)d_in[10];
    const float* ln2_b   = (const float*)d_in[11];
    const float* ffn_W1  = (const float*)d_in[12];
    const float* ffn_b1  = (const float*)d_in[13];
    const float* ffn_W2  = (const float*)d_in[14];
    const float* ffn_b2  = (const float*)d_in[15];
    const float* sha_Wq  = (const float*)d_in[16];
    const float* sha_Wk  = (const float*)d_in[17];
    const float* alloc_W1= (const float*)d_in[18];
    const float* alloc_b1= (const float*)d_in[19];
    const float* alloc_W2= (const float*)d_in[20];
    const float* alloc_b2= (const float*)d_in[21];

    float *h, *scr, *tmp, *hmean, *qv, *t1, *logits, *scores;
    uint32_t* wpk;
    cudaGetSymbolAddress((void**)&h,      g_h);
    cudaGetSymbolAddress((void**)&scr,    g_scr);
    cudaGetSymbolAddress((void**)&tmp,    g_tmp);
    cudaGetSymbolAddress((void**)&wpk,    g_wpk);
    cudaGetSymbolAddress((void**)&hmean,  g_hmean);
    cudaGetSymbolAddress((void**)&qv,     g_qv);
    cudaGetSymbolAddress((void**)&t1,     g_t1);
    cudaGetSymbolAddress((void**)&logits, g_logits);
    cudaGetSymbolAddress((void**)&scores, g_scores);

    static int cfg_done = 0;
    if (!cfg_done) {
        cudaFuncSetAttribute(attn_mma_kernel,
                             cudaFuncAttributeMaxDynamicSharedMemorySize, ATT_SMEM);
        cudaFuncSetAttribute(tgemm_kernel<0,1>,
                             cudaFuncAttributeMaxDynamicSharedMemorySize, TG_SMEM);
        cudaFuncSetAttribute(tgemm_kernel<0,0>,
                             cudaFuncAttributeMaxDynamicSharedMemorySize, TG_SMEM);
        cudaFuncSetAttribute(tgemm_kernel<1,1>,
                             cudaFuncAttributeMaxDynamicSharedMemorySize, TG_SMEM);
        cfg_done = 1;
    }

    // pack weights -> tf32 u32 (QKV fused into [256][768])
    {
        int t;
        t = 3*256*256;
        packt_kernel<<<(t+255)/256, 256>>>(Wq, wpk + OFF_QKV, 256, 768, 0,   256*256, 256*768, t);
        packt_kernel<<<(t+255)/256, 256>>>(Wk, wpk + OFF_QKV, 256, 768, 256, 256*256, 256*768, t);
        packt_kernel<<<(t+255)/256, 256>>>(Wv, wpk + OFF_QKV, 256, 768, 512, 256*256, 256*768, t);
        packt_kernel<<<(t+255)/256, 256>>>(Wo, wpk + OFF_WO, 256, 256, 0, 256*256, 256*256, t);
        t = 3*256*1024;
        packt_kernel<<<(t+255)/256, 256>>>(ffn_W1, wpk + OFF_W1, 1024, 1024, 0, 256*1024, 256*1024, t);
        packt_kernel<<<(t+255)/256, 256>>>(ffn_W2, wpk + OFF_W2, 256, 256, 0, 1024*256, 1024*256, t);
        t = 256*256;
        packt_kernel<<<(t+255)/256, 256>>>(sha_Wk, wpk + OFF_SHA, 256, 256, 0, 256*256, 256*256, t);
    }

    float* qkv = scr;                           // [M][768]
    float* ao  = scr + (size_t)MM*768;          // [M][256]

    embed_kernel<<<MM, 256>>>(x, emb_W, emb_b, h);

    const dim3 gQKV(768/128, MM/128);  // (6,512)
    const dim3 gP(Dd/128, MM/128);     // (2,512)
    const dim3 gF1(DFF/128, MM/128);   // (8,512)

    for (int i = 0; i < Ll; i++) {
        tgemm_kernel<0,1><<<gQKV, 256, TG_SMEM>>>((const uint32_t*)h, wpk + OFF_QKV + (size_t)i*256*768, nullptr, qkv, MM, 768, Dd);
        attn_mma_kernel<<<dim3(Nn/128, Hh, Bb), 256, ATT_SMEM>>>(qkv, ao);
        tgemm_kernel<0,0><<<gP, 256, TG_SMEM>>>((const uint32_t*)ao, wpk + OFF_WO + (size_t)i*256*256, nullptr, tmp, MM, Dd, Dd);
        ln_res_kernel<<<MM/8, 256>>>(h, tmp, ln1_g + i*Dd, ln1_b + i*Dd);
        tgemm_kernel<1,1><<<gF1, 256, TG_SMEM>>>((const uint32_t*)h, wpk + OFF_W1 + (size_t)i*256*1024, ffn_b1 + i*DFF, scr, MM, DFF, Dd);
        tgemm_kernel<0,0><<<gP, 256, TG_SMEM>>>((const uint32_t*)scr, wpk + OFF_W2 + (size_t)i*1024*256, ffn_b2 + i*Dd, tmp, MM, Dd, DFF);
        ln_res_kernel<<<MM/8, 256>>>(h, tmp, ln2_g + i*Dd, ln2_b + i*Dd);
    }

    hmean_kernel<<<Bb, 256>>>(h, hmean);
    rowgemm_kernel<0><<<Bb, 256>>>(hmean, sha_Wq, nullptr, qv, Dd, Dd);
    tgemm_kernel<0,0><<<gP, 256, TG_SMEM>>>((const uint32_t*)h, wpk + OFF_SHA, nullptr, tmp, MM, Dd, Dd);
    scores_kernel<<<dim3(Nn/8, Bb), 256>>>(qv, tmp, scores);
    rowgemm_kernel<1><<<Bb, 256>>>(hmean, alloc_W1, alloc_b1, t1, Dd, Dd);
    rowgemm_kernel<0><<<Bb, 256>>>(t1, alloc_W2, alloc_b2, logits, Dd, Nn);

    float* out = (float*)d_out;
    finale_kernel<<<Bb, 256>>>(scores, gumbel, logits,
                               out,
                               out + Bb*Nn,
                               out + Bb*Nn + Bb*Kk);
}

// round 8
// speedup vs baseline: 7.2601x; 1.5603x over previous
#include <cuda_runtime.h>
#include <cuda_fp16.h>
#include <cstdint>

// ---------------- problem dims ----------------
#define Bb 64
#define Nn 1024
#define Din 16
#define Dd 256
#define Hh 4
#define DH 64
#define Ll 3
#define DFF 1024
#define Kk 64
#define MM (Bb*Nn)          // 65536 rows

// ---------------- scratch (static device memory) ----------------
__device__ __half g_h[MM*Dd];           // 32 MB hidden state (fp16)
__device__ __half g_scr[MM*DFF];        // 128 MB qkv|ao or ffn hidden
__device__ __half g_tmp[MM*Dd];         // 32 MB proj/ffn out / kv
__device__ uint32_t g_wpk[1212416];     // packed fp16x2 weights
__device__ float g_hmean[Bb*Dd];
__device__ float g_qv[Bb*Dd];
__device__ float g_t1[Bb*Dd];
__device__ float g_logits[Bb*Nn];
__device__ float g_scores[Bb*Nn];

// packed-weight offsets (uint32 units)
#define OFF_QKV  0            // 3 x [128][768]
#define OFF_WO   294912       // 3 x [128][256]
#define OFF_W1   393216       // 3 x [128][1024]
#define OFF_W2   786432       // 3 x [512][256]
#define OFF_SHA  1179648      // [128][256]

__device__ __forceinline__ uint32_t pkhf(float lo, float hi) {
    uint32_t r;
    asm("cvt.rn.f16x2.f32 %0, %1, %2;" : "=r"(r) : "f"(hi), "f"(lo));
    return r;
}

__device__ __forceinline__ void mma_f16(float* c, const uint32_t* a, const uint32_t* b) {
    asm volatile(
        "mma.sync.aligned.m16n8k16.row.col.f32.f16.f16.f32 "
        "{%0,%1,%2,%3}, {%4,%5,%6,%7}, {%8,%9}, {%0,%1,%2,%3};"
        : "+f"(c[0]), "+f"(c[1]), "+f"(c[2]), "+f"(c[3])
        : "r"(a[0]), "r"(a[1]), "r"(a[2]), "r"(a[3]), "r"(b[0]), "r"(b[1]));
}

__device__ __forceinline__ void cp16(void* smem, const void* gmem) {
    uint32_t s = (uint32_t)__cvta_generic_to_shared(smem);
    asm volatile("cp.async.cg.shared.global [%0], [%1], 16;" :: "r"(s), "l"(gmem));
}
#define CP_COMMIT() asm volatile("cp.async.commit_group;")
#define CP_WAIT(n)  asm volatile("cp.async.wait_group %0;" :: "n"(n))

// ---------------- weight pack: fp32 [L][K][N] -> fp16x2 [L][K/2][dstStride] ----------------
__global__ void packh_kernel(const float* __restrict__ src, uint32_t* __restrict__ dst,
                             int Nsrc, int dstStride, int colOff, int KN, int KNh,
                             int layerDstStride, int total)
{
    int i = blockIdx.x*256 + threadIdx.x;
    if (i >= total) return;
    int l = i / KNh;
    int rem = i - l*KNh;
    int kp = rem / Nsrc, n = rem - kp*Nsrc;
    const float* s = src + (size_t)l*KN;
    dst[(size_t)l*layerDstStride + (size_t)kp*dstStride + colOff + n] =
        pkhf(s[(size_t)(2*kp)*Nsrc + n], s[(size_t)(2*kp+1)*Nsrc + n]);
}

// ---------------- embedding (fp16 out) ----------------
__global__ void embed_kernel(const float* __restrict__ x, const float* __restrict__ W,
                             const float* __restrict__ b, __half* __restrict__ h)
{
    int m = blockIdx.x;
    int d = threadIdx.x;
    __shared__ float xs[Din];
    if (threadIdx.x < Din) xs[threadIdx.x] = x[m*Din + threadIdx.x];
    __syncthreads();
    float acc = b[d];
#pragma unroll
    for (int k = 0; k < Din; k++) acc = fmaf(xs[k], W[k*Dd + d], acc);
    h[(size_t)m*Dd + d] = __float2half(acc);
}

// ---------------- FP16 tensor-core GEMM: 4-stage cp.async pipeline ----------------
// A: fp16 [M][Kd] read as u32 pairs (Kd/2 per row); Wp: packed [Kd/2][Nd] u32;
// C: fp16 [M][Nd] written as u32 pairs. 128x128 tile, BK=32, m16n8k16.
#define AST 20
#define BST 136
#define A_SZ (128*AST)
#define B_SZ (16*BST)
#define TG_SMEM (4*(A_SZ + B_SZ)*4)   // 75776 bytes

template<int RELU>
__global__ __launch_bounds__(256, 2) void tgemm_kernel(
    const uint32_t* __restrict__ A, const uint32_t* __restrict__ Wp,
    const float* __restrict__ bias, uint32_t* __restrict__ C,
    int M, int Nd, int Kd)
{
    const int Kd2 = Kd >> 1, Nd2 = Nd >> 1;
    extern __shared__ uint32_t dsm[];
    uint32_t* Asm = dsm;               // [4][A_SZ]
    uint32_t* Bsm = dsm + 4*A_SZ;      // [4][B_SZ]

    const int tid = threadIdx.x;
    const int warp = tid >> 5;
    const int lane = tid & 31;
    const int bm = blockIdx.y, bn = blockIdx.x;
    const int wm = warp & 3;
    const int wn = warp >> 2;
    const int qid = lane >> 2;
    const int tig = lane & 3;

    const int a_r0 = tid >> 1, a_c0 = (tid & 1) << 3;   // u32 col 0 or 8
    const int b_r0 = tid >> 5, b_c0 = (tid & 31) << 2;

    const uint32_t* Ap = A  + (size_t)(bm*128)*Kd2;
    const uint32_t* Bp = Wp + (size_t)bn*128;

    float acc[2][8][4];
#pragma unroll
    for (int mt = 0; mt < 2; mt++)
#pragma unroll
        for (int nt = 0; nt < 8; nt++)
#pragma unroll
            for (int i = 0; i < 4; i++) acc[mt][nt][i] = 0.f;

    const int niter = Kd >> 5;   // 8 (K=256) or 32 (K=1024)

    // prologue: preload K-tiles 0..2
#pragma unroll
    for (int s = 0; s < 3; s++) {
        const uint32_t* Ap2 = Ap + s*16;
        const uint32_t* Bp2 = Bp + (size_t)(s*16)*Nd;
        cp16(&Asm[s*A_SZ + a_r0*AST + a_c0],     Ap2 + (size_t)a_r0*Kd2 + a_c0);
        cp16(&Asm[s*A_SZ + a_r0*AST + a_c0 + 4], Ap2 + (size_t)a_r0*Kd2 + a_c0 + 4);
        cp16(&Bsm[s*B_SZ + b_r0*BST + b_c0],       Bp2 + (size_t)b_r0*Nd + b_c0);
        cp16(&Bsm[s*B_SZ + (b_r0+8)*BST + b_c0],   Bp2 + (size_t)(b_r0+8)*Nd + b_c0);
        CP_COMMIT();
    }

    for (int it = 0; it < niter; it++) {
        CP_WAIT(2);
        __syncthreads();

        int pf = it + 3;
        if (pf < niter) {
            int sb = pf & 3;
            const uint32_t* Ap2 = Ap + pf*16;
            const uint32_t* Bp2 = Bp + (size_t)(pf*16)*Nd;
            cp16(&Asm[sb*A_SZ + a_r0*AST + a_c0],     Ap2 + (size_t)a_r0*Kd2 + a_c0);
            cp16(&Asm[sb*A_SZ + a_r0*AST + a_c0 + 4], Ap2 + (size_t)a_r0*Kd2 + a_c0 + 4);
            cp16(&Bsm[sb*B_SZ + b_r0*BST + b_c0],     Bp2 + (size_t)b_r0*Nd + b_c0);
            cp16(&Bsm[sb*B_SZ + (b_r0+8)*BST + b_c0], Bp2 + (size_t)(b_r0+8)*Nd + b_c0);
        }
        CP_COMMIT();

        const uint32_t* Asu = &Asm[(it & 3)*A_SZ];
        const uint32_t* Bsu = &Bsm[(it & 3)*B_SZ];
#pragma unroll
        for (int ks = 0; ks < 2; ks++) {
            uint32_t afrag[2][4];
#pragma unroll
            for (int mt = 0; mt < 2; mt++) {
                int r = wm*32 + mt*16 + qid;
                afrag[mt][0] = Asu[r*AST + ks*8 + tig];
                afrag[mt][1] = Asu[(r+8)*AST + ks*8 + tig];
                afrag[mt][2] = Asu[r*AST + ks*8 + tig + 4];
                afrag[mt][3] = Asu[(r+8)*AST + ks*8 + tig + 4];
            }
#pragma unroll
            for (int nt = 0; nt < 8; nt++) {
                int cn = wn*64 + nt*8 + qid;
                uint32_t bfrag[2];
                bfrag[0] = Bsu[(ks*8 + tig)*BST + cn];
                bfrag[1] = Bsu[(ks*8 + tig + 4)*BST + cn];
#pragma unroll
                for (int mt = 0; mt < 2; mt++)
                    mma_f16(acc[mt][nt], afrag[mt], bfrag);
            }
        }
    }

    // epilogue: bias + relu + fp16 pack
#pragma unroll
    for (int mt = 0; mt < 2; mt++) {
        int r0 = bm*128 + wm*32 + mt*16 + qid;
#pragma unroll
        for (int nt = 0; nt < 8; nt++) {
            int c0 = bn*128 + wn*64 + nt*8 + 2*tig;
            float b0 = bias ? bias[c0]   : 0.f;
            float b1 = bias ? bias[c0+1] : 0.f;
            float v0 = acc[mt][nt][0] + b0, v1 = acc[mt][nt][1] + b1;
            float v2 = acc[mt][nt][2] + b0, v3 = acc[mt][nt][3] + b1;
            if (RELU) {
                v0 = fmaxf(v0, 0.f); v1 = fmaxf(v1, 0.f);
                v2 = fmaxf(v2, 0.f); v3 = fmaxf(v3, 0.f);
            }
            int cu = c0 >> 1;
            C[(size_t)r0*Nd2 + cu]     = pkhf(v0, v1);
            C[(size_t)(r0+8)*Nd2 + cu] = pkhf(v2, v3);
        }
    }
}

// ---------------- fp16 tensor-core flash attention (fused QKV input) ----------------
// QKV [M][768] fp16 (u32 row stride 384): Q cols 0-255, K 256-511, V 512-767.
// O = ao [M][256] fp16 (u32 stride 128).
#define QKV_RS 384
#define O_RS   128
#define KST 36
#define VST 72
#define PST 36

__global__ void __launch_bounds__(256) attn_mma_kernel(
    const uint32_t* __restrict__ QKV, uint32_t* __restrict__ O)
{
    __shared__ __align__(16) uint32_t Ks[64*KST];
    __shared__ __align__(16) uint32_t Vs[32*VST];
    __shared__ __align__(16) uint32_t Ps[8][16*PST];

    const int tid = threadIdx.x;
    const int warp = tid >> 5, lane = tid & 31;
    const int qid = lane >> 2, tig = lane & 3;
    uint32_t* Psw = Ps[warp];

    const int qt = blockIdx.x, head = blockIdx.y, b = blockIdx.z;
    const size_t qbase = ((size_t)b*Nn)*QKV_RS + head*(DH/2);
    const size_t kbase = qbase + 128;
    const size_t vbase = qbase + 256;
    const size_t obase = ((size_t)b*Nn)*O_RS + head*(DH/2);
    const int q0 = qt*128 + warp*16;

    // Q fragments (4 k16 steps over DH=64)
    uint32_t qa[4][4];
#pragma unroll
    for (int s = 0; s < 4; s++) {
        qa[s][0] = QKV[qbase + (size_t)(q0+qid  )*QKV_RS + s*8 + tig];
        qa[s][1] = QKV[qbase + (size_t)(q0+qid+8)*QKV_RS + s*8 + tig];
        qa[s][2] = QKV[qbase + (size_t)(q0+qid  )*QKV_RS + s*8 + tig + 4];
        qa[s][3] = QKV[qbase + (size_t)(q0+qid+8)*QKV_RS + s*8 + tig + 4];
    }

    float oacc[8][4];
#pragma unroll
    for (int dn = 0; dn < 8; dn++)
#pragma unroll
        for (int i = 0; i < 4; i++) oacc[dn][i] = 0.f;
    float m0 = -1e30f, m1 = -1e30f, l0 = 0.f, l1 = 0.f;
    const float scale = 0.125f;

    const int kr = tid >> 3, kq = (tid & 7) << 2;   // K loader
    const int np = tid >> 3, dq = tid & 7;          // V loader

    for (int j0 = 0; j0 < Nn; j0 += 64) {
        // K tile: natural fp16 pairs [64][32] u32
#pragma unroll
        for (int p = 0; p < 2; p++) {
            int r = kr + 32*p;
            uint4 t = *(const uint4*)(QKV + kbase + (size_t)(j0+r)*QKV_RS + kq);
            *(uint4*)&Ks[r*KST + kq] = t;
        }
        // V tile: n-pair interleaved [32][64] u32 via byte_perm
        {
            uint4 r0 = *(const uint4*)(QKV + vbase + (size_t)(j0+2*np  )*QKV_RS + dq*4);
            uint4 r1 = *(const uint4*)(QKV + vbase + (size_t)(j0+2*np+1)*QKV_RS + dq*4);
            uint4 o0, o1;
            o0.x = __byte_perm(r0.x, r1.x, 0x5410); o0.y = __byte_perm(r0.x, r1.x, 0x7632);
            o0.z = __byte_perm(r0.y, r1.y, 0x5410); o0.w = __byte_perm(r0.y, r1.y, 0x7632);
            o1.x = __byte_perm(r0.z, r1.z, 0x5410); o1.y = __byte_perm(r0.z, r1.z, 0x7632);
            o1.z = __byte_perm(r0.w, r1.w, 0x5410); o1.w = __byte_perm(r0.w, r1.w, 0x7632);
            *(uint4*)&Vs[np*VST + dq*8]     = o0;
            *(uint4*)&Vs[np*VST + dq*8 + 4] = o1;
        }
        __syncthreads();

        // S = Q @ K^T
        float sacc[8][4];
#pragma unroll
        for (int nt = 0; nt < 8; nt++)
#pragma unroll
            for (int i = 0; i < 4; i++) sacc[nt][i] = 0.f;
#pragma unroll
        for (int s = 0; s < 4; s++) {
#pragma unroll
            for (int nt = 0; nt < 8; nt++) {
                uint32_t bfrag[2];
                bfrag[0] = Ks[(nt*8+qid)*KST + s*8 + tig];
                bfrag[1] = Ks[(nt*8+qid)*KST + s*8 + tig + 4];
                mma_f16(sacc[nt], qa[s], bfrag);
            }
        }
#pragma unroll
        for (int nt = 0; nt < 8; nt++)
#pragma unroll
            for (int i = 0; i < 4; i++) sacc[nt][i] *= scale;

        // online softmax (rows qid, qid+8)
        float tm0 = -1e30f, tm1 = -1e30f;
#pragma unroll
        for (int nt = 0; nt < 8; nt++) {
            tm0 = fmaxf(tm0, fmaxf(sacc[nt][0], sacc[nt][1]));
            tm1 = fmaxf(tm1, fmaxf(sacc[nt][2], sacc[nt][3]));
        }
        tm0 = fmaxf(tm0, __shfl_xor_sync(0xffffffffu, tm0, 1));
        tm0 = fmaxf(tm0, __shfl_xor_sync(0xffffffffu, tm0, 2));
        tm1 = fmaxf(tm1, __shfl_xor_sync(0xffffffffu, tm1, 1));
        tm1 = fmaxf(tm1, __shfl_xor_sync(0xffffffffu, tm1, 2));
        float mn0 = fmaxf(m0, tm0), mn1 = fmaxf(m1, tm1);
        float c0 = __expf(m0 - mn0), c1 = __expf(m1 - mn1);
        m0 = mn0; m1 = mn1;
        l0 *= c0; l1 *= c1;
#pragma unroll
        for (int dn = 0; dn < 8; dn++) {
            oacc[dn][0] *= c0; oacc[dn][1] *= c0;
            oacc[dn][2] *= c1; oacc[dn][3] *= c1;
        }
#pragma unroll
        for (int nt = 0; nt < 8; nt++) {
            float p0 = __expf(sacc[nt][0] - m0);
            float p1 = __expf(sacc[nt][1] - m0);
            float p2 = __expf(sacc[nt][2] - m1);
            float p3 = __expf(sacc[nt][3] - m1);
            l0 += p0 + p1; l1 += p2 + p3;
            Psw[qid*PST     + nt*4 + tig] = pkhf(p0, p1);
            Psw[(qid+8)*PST + nt*4 + tig] = pkhf(p2, p3);
        }
        __syncwarp();

        // O += P @ V
#pragma unroll
        for (int sj = 0; sj < 4; sj++) {
            uint32_t afrag[4];
            afrag[0] = Psw[qid*PST     + sj*8 + tig];
            afrag[1] = Psw[(qid+8)*PST + sj*8 + tig];
            afrag[2] = Psw[qid*PST     + sj*8 + tig + 4];
            afrag[3] = Psw[(qid+8)*PST + sj*8 + tig + 4];
#pragma unroll
            for (int dn = 0; dn < 8; dn++) {
                uint32_t bfrag[2];
                bfrag[0] = Vs[(sj*8+tig  )*VST + dn*8 + qid];
                bfrag[1] = Vs[(sj*8+tig+4)*VST + dn*8 + qid];
                mma_f16(oacc[dn], afrag, bfrag);
            }
        }
        __syncthreads();
    }

    l0 += __shfl_xor_sync(0xffffffffu, l0, 1);
    l0 += __shfl_xor_sync(0xffffffffu, l0, 2);
    l1 += __shfl_xor_sync(0xffffffffu, l1, 1);
    l1 += __shfl_xor_sync(0xffffffffu, l1, 2);
    float inv0 = 1.f / l0, inv1 = 1.f / l1;
#pragma unroll
    for (int dn = 0; dn < 8; dn++) {
        int cu = dn*4 + tig;
        O[obase + (size_t)(q0+qid  )*O_RS + cu] = pkhf(oacc[dn][0]*inv0, oacc[dn][1]*inv0);
        O[obase + (size_t)(q0+qid+8)*O_RS + cu] = pkhf(oacc[dn][2]*inv1, oacc[dn][3]*inv1);
    }
}

// ---------------- LayerNorm(h + res) in place (fp16) ----------------
__global__ void ln_res_kernel(uint32_t* __restrict__ h, const uint32_t* __restrict__ res,
                              const float* __restrict__ g, const float* __restrict__ bta)
{
    int row = blockIdx.x*8 + (threadIdx.x >> 5);
    int lane = threadIdx.x & 31;
    size_t off = (size_t)row * (Dd/2);
    float v[8];
    float s = 0.f;
#pragma unroll
    for (int i = 0; i < 4; i++) {
        uint32_t hu = h[off + lane + i*32];
        uint32_t ru = res[off + lane + i*32];
        __half2 hb = *(__half2*)&hu;
        __half2 rb = *(__half2*)&ru;
        v[2*i]   = __half2float(hb.x) + __half2float(rb.x);
        v[2*i+1] = __half2float(hb.y) + __half2float(rb.y);
        s += v[2*i] + v[2*i+1];
    }
#pragma unroll
    for (int o = 16; o; o >>= 1) s += __shfl_xor_sync(0xffffffffu, s, o);
    float mean = s * (1.f/256.f);
    float vs = 0.f;
#pragma unroll
    for (int i = 0; i < 8; i++) { float d = v[i]-mean; vs = fmaf(d, d, vs); }
#pragma unroll
    for (int o = 16; o; o >>= 1) vs += __shfl_xor_sync(0xffffffffu, vs, o);
    float rstd = rsqrtf(vs * (1.f/256.f) + 1e-5f);
#pragma unroll
    for (int i = 0; i < 4; i++) {
        int c = 2*(lane + i*32);
        float o0 = (v[2*i]  -mean)*rstd*g[c]   + bta[c];
        float o1 = (v[2*i+1]-mean)*rstd*g[c+1] + bta[c+1];
        h[off + lane + i*32] = pkhf(o0, o1);
    }
}

// ---------------- h_mean (fp16 in, fp32 out) ----------------
__global__ void hmean_kernel(const __half* __restrict__ h, float* __restrict__ hm)
{
    int b = blockIdx.x, d = threadIdx.x;
    const __half* p = h + (size_t)b*Nn*Dd + d;
    float s = 0.f;
#pragma unroll 8
    for (int n = 0; n < Nn; n++) s += __half2float(p[(size_t)n*Dd]);
    hm[b*Dd + d] = s * (1.f/1024.f);
}

// ---------------- small row GEMM (fp32) ----------------
template<int RELU>
__global__ void rowgemm_kernel(const float* __restrict__ A, const float* __restrict__ W,
                               const float* __restrict__ bias, float* __restrict__ C,
                               int Kd, int Nd)
{
    int b = blockIdx.x;
    __shared__ float xs[1024];
    for (int i = threadIdx.x; i < Kd; i += blockDim.x) xs[i] = A[(size_t)b*Kd + i];
    __syncthreads();
    for (int d = threadIdx.x; d < Nd; d += blockDim.x) {
        float acc = bias ? bias[d] : 0.f;
        for (int k = 0; k < Kd; k++) acc = fmaf(xs[k], W[(size_t)k*Nd + d], acc);
        if (RELU) acc = fmaxf(acc, 0.f);
        C[(size_t)b*Nd + d] = acc;
    }
}

// ---------------- scores (qv fp32, kv fp16) ----------------
__global__ void scores_kernel(const float* __restrict__ qv, const __half* __restrict__ kv,
                              float* __restrict__ scores)
{
    int b = blockIdx.y;
    int n = blockIdx.x*8 + (threadIdx.x >> 5);
    int lane = threadIdx.x & 31;
    const __half* k = kv + ((size_t)b*Nn + n)*Dd;
    const float* q = qv + b*Dd;
    float s = 0.f;
#pragma unroll
    for (int i = 0; i < 8; i++) {
        int c = lane + i*32;
        s = fmaf(q[c], __half2float(k[c]), s);
    }
#pragma unroll
    for (int o = 16; o; o >>= 1) s += __shfl_xor_sync(0xffffffffu, s, o);
    if (lane == 0) scores[b*Nn + n] = s * (1.f/16.f);
}

// ---------------- finale: softmaxes + top-64 + sel ----------------
__global__ void finale_kernel(const float* __restrict__ scores, const float* __restrict__ gumbel,
                              const float* __restrict__ logits,
                              float* __restrict__ out_w, float* __restrict__ out_idx,
                              float* __restrict__ out_sel)
{
    int b = blockIdx.x, tid = threadIdx.x;
    __shared__ float w[1024];
    __shared__ float al[1024];
    __shared__ float red[256];
    __shared__ int   redi[256];
    __shared__ int   selidx[64];

    float lm = -1e30f;
    for (int i = tid; i < 1024; i += 256) {
        float v = (scores[b*Nn+i] + gumbel[b*Nn+i]) * 2.0f;
        w[i] = v; lm = fmaxf(lm, v);
    }
    red[tid] = lm; __syncthreads();
    for (int s = 128; s; s >>= 1) { if (tid < s) red[tid] = fmaxf(red[tid], red[tid+s]); __syncthreads(); }
    float M = red[0]; __syncthreads();
    float ls = 0.f;
    for (int i = tid; i < 1024; i += 256) { float e = __expf(w[i]-M); w[i] = e; ls += e; }
    red[tid] = ls; __syncthreads();
    for (int s = 128; s; s >>= 1) { if (tid < s) red[tid] += red[tid+s]; __syncthreads(); }
    float invS = 1.f / red[0]; __syncthreads();
    for (int i = tid; i < 1024; i += 256) {
        float wi = w[i]*invS; w[i] = wi; out_w[b*Nn+i] = wi;
    }

    lm = -1e30f;
    for (int i = tid; i < 1024; i += 256) { float v = logits[b*Nn+i]; al[i] = v; lm = fmaxf(lm, v); }
    __syncthreads();
    red[tid] = lm; __syncthreads();
    for (int s = 128; s; s >>= 1) { if (tid < s) red[tid] = fmaxf(red[tid], red[tid+s]); __syncthreads(); }
    M = red[0]; __syncthreads();
    ls = 0.f;
    for (int i = tid; i < 1024; i += 256) { float e = __expf(al[i]-M); al[i] = e; ls += e; }
    red[tid] = ls; __syncthreads();
    for (int s = 128; s; s >>= 1) { if (tid < s) red[tid] += red[tid+s]; __syncthreads(); }
    invS = 1.f / red[0]; __syncthreads();
    for (int i = tid; i < 1024; i += 256) al[i] *= invS;
    __syncthreads();

    for (int kk = 0; kk < 64; kk++) {
        float bv = -1e30f; int bi = 0x7fffffff;
        for (int i = tid; i < 1024; i += 256) {
            float v = w[i];
            if (v > bv) { bv = v; bi = i; }
        }
        red[tid] = bv; redi[tid] = bi; __syncthreads();
        for (int s = 128; s; s >>= 1) {
            if (tid < s) {
                float ov = red[tid+s]; int oi = redi[tid+s];
                if (ov > red[tid] || (ov == red[tid] && oi < redi[tid])) { red[tid] = ov; redi[tid] = oi; }
            }
            __syncthreads();
        }
        if (tid == 0) { selidx[kk] = redi[0]; w[redi[0]] = -2e30f; }
        __syncthreads();
    }

    float sv = 0.f;
    if (tid < 64) sv = al[selidx[tid]];
    red[tid] = (tid < 64) ? sv : 0.f; __syncthreads();
    for (int s = 128; s; s >>= 1) { if (tid < s) red[tid] += red[tid+s]; __syncthreads(); }
    float inv = 1.f / (red[0] + 1e-12f);
    if (tid < 64) {
        out_idx[b*64 + tid] = (float)selidx[tid];
        out_sel[b*64 + tid] = sv * inv;
    }
}

// ---------------- launch ----------------
extern "C" void kernel_launch(void* const* d_in, const int* in_sizes, int n_in,
                              void* d_out, int out_size)
{
    const float* x       = (const float*)d_in[0];
    const float* gumbel  = (const float*)d_in[1];
    const float* emb_W   = (const float*)d_in[2];
    const float* emb_b   = (const float*)d_in[3];
    const float* Wq      = (const float*)d_in[4];
    const float* Wk      = (const float*)d_in[5];
    const float* Wv      = (const float*)d_in[6];
    const float* Wo      = (const float*)d_in[7];
    const float* ln1_g   = (const float*)d_in[8];
    const float* ln1_b   = (const float*)d_in[9];
    const float* ln2_g   = (const float*)d_in[10];
    const float* ln2_b   = (const float*)d_in[11];
    const float* ffn_W1  = (const float*)d_in[12];
    const float* ffn_b1  = (const float*)d_in[13];
    const float* ffn_W2  = (const float*)d_in[14];
    const float* ffn_b2  = (const float*)d_in[15];
    const float* sha_Wq  = (const float*)d_in[16];
    const float* sha_Wk  = (const float*)d_in[17];
    const float* alloc_W1= (const float*)d_in[18];
    const float* alloc_b1= (const float*)d_in[19];
    const float* alloc_W2= (const float*)d_in[20];
    const float* alloc_b2= (const float*)d_in[21];

    __half *h, *scr, *tmp;
    uint32_t* wpk;
    float *hmean, *qv, *t1, *logits, *scores;
    cudaGetSymbolAddress((void**)&h,      g_h);
    cudaGetSymbolAddress((void**)&scr,    g_scr);
    cudaGetSymbolAddress((void**)&tmp,    g_tmp);
    cudaGetSymbolAddress((void**)&wpk,    g_wpk);
    cudaGetSymbolAddress((void**)&hmean,  g_hmean);
    cudaGetSymbolAddress((void**)&qv,     g_qv);
    cudaGetSymbolAddress((void**)&t1,     g_t1);
    cudaGetSymbolAddress((void**)&logits, g_logits);
    cudaGetSymbolAddress((void**)&scores, g_scores);

    static int cfg_done = 0;
    if (!cfg_done) {
        cudaFuncSetAttribute(tgemm_kernel<0>,
                             cudaFuncAttributeMaxDynamicSharedMemorySize, TG_SMEM);
        cudaFuncSetAttribute(tgemm_kernel<1>,
                             cudaFuncAttributeMaxDynamicSharedMemorySize, TG_SMEM);
        cfg_done = 1;
    }

    // pack weights -> fp16x2 [K/2][cols]; QKV fused side-by-side into [128][768]
    {
        int t;
        t = 3*128*256;
        packh_kernel<<<(t+255)/256, 256>>>(Wq, wpk + OFF_QKV, 256, 768, 0,   256*256, 128*256, 128*768, t);
        packh_kernel<<<(t+255)/256, 256>>>(Wk, wpk + OFF_QKV, 256, 768, 256, 256*256, 128*256, 128*768, t);
        packh_kernel<<<(t+255)/256, 256>>>(Wv, wpk + OFF_QKV, 256, 768, 512, 256*256, 128*256, 128*768, t);
        packh_kernel<<<(t+255)/256, 256>>>(Wo, wpk + OFF_WO, 256, 256, 0, 256*256, 128*256, 128*256, t);
        t = 3*128*1024;
        packh_kernel<<<(t+255)/256, 256>>>(ffn_W1, wpk + OFF_W1, 1024, 1024, 0, 256*1024, 128*1024, 128*1024, t);
        t = 3*512*256;
        packh_kernel<<<(t+255)/256, 256>>>(ffn_W2, wpk + OFF_W2, 256, 256, 0, 1024*256, 512*256, 512*256, t);
        t = 128*256;
        packh_kernel<<<(t+255)/256, 256>>>(sha_Wk, wpk + OFF_SHA, 256, 256, 0, 256*256, 128*256, 128*256, t);
    }

    __half* qkv = scr;                          // [M][768]
    __half* ao  = scr + (size_t)MM*768;         // [M][256]

    embed_kernel<<<MM, 256>>>(x, emb_W, emb_b, h);

    const dim3 gQKV(768/128, MM/128);  // (6,512)
    const dim3 gP(Dd/128, MM/128);     // (2,512)
    const dim3 gF1(DFF/128, MM/128);   // (8,512)

    for (int i = 0; i < Ll; i++) {
        tgemm_kernel<0><<<gQKV, 256, TG_SMEM>>>((const uint32_t*)h, wpk + OFF_QKV + (size_t)i*128*768, nullptr, (uint32_t*)qkv, MM, 768, Dd);
        attn_mma_kernel<<<dim3(Nn/128, Hh, Bb), 256>>>((const uint32_t*)qkv, (uint32_t*)ao);
        tgemm_kernel<0><<<gP, 256, TG_SMEM>>>((const uint32_t*)ao, wpk + OFF_WO + (size_t)i*128*256, nullptr, (uint32_t*)tmp, MM, Dd, Dd);
        ln_res_kernel<<<MM/8, 256>>>((uint32_t*)h, (const uint32_t*)tmp, ln1_g + i*Dd, ln1_b + i*Dd);
        tgemm_kernel<1><<<gF1, 256, TG_SMEM>>>((const uint32_t*)h, wpk + OFF_W1 + (size_t)i*128*1024, ffn_b1 + i*DFF, (uint32_t*)scr, MM, DFF, Dd);
        tgemm_kernel<0><<<gP, 256, TG_SMEM>>>((const uint32_t*)scr, wpk + OFF_W2 + (size_t)i*512*256, ffn_b2 + i*Dd, (uint32_t*)tmp, MM, Dd, DFF);
        ln_res_kernel<<<MM/8, 256>>>((uint32_t*)h, (const uint32_t*)tmp, ln2_g + i*Dd, ln2_b + i*Dd);
    }

    hmean_kernel<<<Bb, 256>>>(h, hmean);
    rowgemm_kernel<0><<<Bb, 256>>>(hmean, sha_Wq, nullptr, qv, Dd, Dd);
    tgemm_kernel<0><<<gP, 256, TG_SMEM>>>((const uint32_t*)h, wpk + OFF_SHA, nullptr, (uint32_t*)tmp, MM, Dd, Dd);
    scores_kernel<<<dim3(Nn/8, Bb), 256>>>(qv, tmp, scores);
    rowgemm_kernel<1><<<Bb, 256>>>(hmean, alloc_W1, alloc_b1, t1, Dd, Dd);
    rowgemm_kernel<0><<<Bb, 256>>>(t1, alloc_W2, alloc_b2, logits, Dd, Nn);

    float* out = (float*)d_out;
    finale_kernel<<<Bb, 256>>>(scores, gumbel, logits,
                               out,
                               out + Bb*Nn,
                               out + Bb*Nn + Bb*Kk);
}

// round 9
// speedup vs baseline: 7.5198x; 1.0358x over previous
#include <cuda_runtime.h>
#include <cuda_fp16.h>
#include <cstdint>

// ---------------- problem dims ----------------
#define Bb 64
#define Nn 1024
#define Din 16
#define Dd 256
#define Hh 4
#define DH 64
#define Ll 3
#define DFF 1024
#define Kk 64
#define MM (Bb*Nn)          // 65536 rows

// ---------------- scratch (static device memory) ----------------
__device__ __half g_h[MM*Dd];           // 32 MB hidden state (fp16)
__device__ __half g_scr[MM*DFF];        // 128 MB qkv|ao or ffn hidden
__device__ __half g_tmp[MM*Dd];         // 32 MB proj/ffn out
__device__ uint32_t g_wpk[1212416];     // packed fp16x2 weights
__device__ float g_hmean[Bb*Dd];
__device__ float g_qv[Bb*Dd];
__device__ float g_t1[Bb*Dd];
__device__ float g_logits[Bb*Nn];
__device__ float g_scores[Bb*Nn];

// packed-weight offsets (uint32 units)
#define OFF_QKV  0            // 3 x [128][768]
#define OFF_WO   294912       // 3 x [128][256]
#define OFF_W1   393216       // 3 x [128][1024]
#define OFF_W2   786432       // 3 x [512][256]
#define OFF_SHA  1179648      // [128][256]

__device__ __forceinline__ uint32_t pkhf(float lo, float hi) {
    uint32_t r;
    asm("cvt.rn.f16x2.f32 %0, %1, %2;" : "=r"(r) : "f"(hi), "f"(lo));
    return r;
}

__device__ __forceinline__ void mma_f16(float* c, const uint32_t* a, const uint32_t* b) {
    asm volatile(
        "mma.sync.aligned.m16n8k16.row.col.f32.f16.f16.f32 "
        "{%0,%1,%2,%3}, {%4,%5,%6,%7}, {%8,%9}, {%0,%1,%2,%3};"
        : "+f"(c[0]), "+f"(c[1]), "+f"(c[2]), "+f"(c[3])
        : "r"(a[0]), "r"(a[1]), "r"(a[2]), "r"(a[3]), "r"(b[0]), "r"(b[1]));
}

__device__ __forceinline__ void ldmx4(uint32_t* r, uint32_t saddr) {
    asm volatile("ldmatrix.sync.aligned.m8n8.x4.shared.b16 {%0,%1,%2,%3}, [%4];"
        : "=r"(r[0]), "=r"(r[1]), "=r"(r[2]), "=r"(r[3]) : "r"(saddr));
}

__device__ __forceinline__ void cp16(void* smem, const void* gmem) {
    uint32_t s = (uint32_t)__cvta_generic_to_shared(smem);
    asm volatile("cp.async.cg.shared.global [%0], [%1], 16;" :: "r"(s), "l"(gmem));
}
#define CP_COMMIT() asm volatile("cp.async.commit_group;")
#define CP_WAIT(n)  asm volatile("cp.async.wait_group %0;" :: "n"(n))

// ---------------- weight pack: fp32 [L][K][N] -> fp16x2 [L][K/2][dstStride] ----------------
__global__ void packh_kernel(const float* __restrict__ src, uint32_t* __restrict__ dst,
                             int Nsrc, int dstStride, int colOff, int KN, int KNh,
                             int layerDstStride, int total)
{
    int i = blockIdx.x*256 + threadIdx.x;
    if (i >= total) return;
    int l = i / KNh;
    int rem = i - l*KNh;
    int kp = rem / Nsrc, n = rem - kp*Nsrc;
    const float* s = src + (size_t)l*KN;
    dst[(size_t)l*layerDstStride + (size_t)kp*dstStride + colOff + n] =
        pkhf(s[(size_t)(2*kp)*Nsrc + n], s[(size_t)(2*kp+1)*Nsrc + n]);
}

// ---------------- zero kernel ----------------
__global__ void zero_kernel(float* __restrict__ p)
{
    p[blockIdx.x*256 + threadIdx.x] = 0.f;
}

// ---------------- embedding: 16 rows/block, W staged in smem ----------------
__global__ void embed_kernel(const float* __restrict__ x, const float* __restrict__ W,
                             const float* __restrict__ bb, __half* __restrict__ h)
{
    __shared__ float Ws[Din*Dd];
    __shared__ float xs[16*Din];
    __shared__ float bsm[Dd];
    const int tid = threadIdx.x;
    const int m0 = blockIdx.x*16;
#pragma unroll
    for (int i = tid; i < Din*Dd; i += 256) Ws[i] = W[i];
    xs[tid] = x[m0*Din + tid];
    bsm[tid] = bb[tid];
    __syncthreads();
    const int d = tid;
#pragma unroll
    for (int r = 0; r < 16; r++) {
        float a = bsm[d];
#pragma unroll
        for (int k = 0; k < Din; k++) a = fmaf(xs[r*Din + k], Ws[k*Dd + d], a);
        h[(size_t)(m0+r)*Dd + d] = __float2half(a);
    }
}

// ---------------- FP16 tensor-core GEMM: 4-stage cp.async, ldmatrix A ----------------
#define AST 20
#define BST 136
#define A_SZ (128*AST)
#define B_SZ (16*BST)
#define TG_SMEM (4*(A_SZ + B_SZ)*4)   // 75776 bytes

template<int RELU, int SCORES>
__global__ __launch_bounds__(256, 2) void tgemm_kernel(
    const uint32_t* __restrict__ A, const uint32_t* __restrict__ Wp,
    const float* __restrict__ bias, uint32_t* __restrict__ C,
    int M, int Nd, int Kd,
    const float* __restrict__ qvv, float* __restrict__ sc)
{
    const int Kd2 = Kd >> 1, Nd2 = Nd >> 1;
    extern __shared__ uint32_t dsm[];
    uint32_t* Asm = dsm;               // [4][A_SZ]
    uint32_t* Bsm = dsm + 4*A_SZ;      // [4][B_SZ]

    const int tid = threadIdx.x;
    const int warp = tid >> 5;
    const int lane = tid & 31;
    const int bm = blockIdx.y, bn = blockIdx.x;
    const int wm = warp & 3;
    const int wn = warp >> 2;
    const int qid = lane >> 2;
    const int tig = lane & 3;

    const int a_r0 = tid >> 1, a_c0 = (tid & 1) << 3;
    const int b_r0 = tid >> 5, b_c0 = (tid & 31) << 2;

    // ldmatrix lane addressing for A fragments
    const int row_sel = (lane & 7) + ((lane >> 3) & 1) * 8;
    const int col_sel = (lane >> 4) * 4;
    const uint32_t a_lm_off = (uint32_t)(((wm*32 + row_sel)*AST + col_sel) * 4);
    const uint32_t asm_base = (uint32_t)__cvta_generic_to_shared(Asm);

    const uint32_t* Ap = A  + (size_t)(bm*128)*Kd2;
    const uint32_t* Bp = Wp + (size_t)bn*128;

    float acc[2][8][4];
#pragma unroll
    for (int mt = 0; mt < 2; mt++)
#pragma unroll
        for (int nt = 0; nt < 8; nt++)
#pragma unroll
            for (int i = 0; i < 4; i++) acc[mt][nt][i] = 0.f;

    const int niter = Kd >> 5;

    // prologue: preload K-tiles 0..2
#pragma unroll
    for (int s = 0; s < 3; s++) {
        const uint32_t* Ap2 = Ap + s*16;
        const uint32_t* Bp2 = Bp + (size_t)(s*16)*Nd;
        cp16(&Asm[s*A_SZ + a_r0*AST + a_c0],     Ap2 + (size_t)a_r0*Kd2 + a_c0);
        cp16(&Asm[s*A_SZ + a_r0*AST + a_c0 + 4], Ap2 + (size_t)a_r0*Kd2 + a_c0 + 4);
        cp16(&Bsm[s*B_SZ + b_r0*BST + b_c0],       Bp2 + (size_t)b_r0*Nd + b_c0);
        cp16(&Bsm[s*B_SZ + (b_r0+8)*BST + b_c0],   Bp2 + (size_t)(b_r0+8)*Nd + b_c0);
        CP_COMMIT();
    }

    for (int it = 0; it < niter; it++) {
        CP_WAIT(2);
        __syncthreads();

        int pf = it + 3;
        if (pf < niter) {
            int sb = pf & 3;
            const uint32_t* Ap2 = Ap + pf*16;
            const uint32_t* Bp2 = Bp + (size_t)(pf*16)*Nd;
            cp16(&Asm[sb*A_SZ + a_r0*AST + a_c0],     Ap2 + (size_t)a_r0*Kd2 + a_c0);
            cp16(&Asm[sb*A_SZ + a_r0*AST + a_c0 + 4], Ap2 + (size_t)a_r0*Kd2 + a_c0 + 4);
            cp16(&Bsm[sb*B_SZ + b_r0*BST + b_c0],     Bp2 + (size_t)b_r0*Nd + b_c0);
            cp16(&Bsm[sb*B_SZ + (b_r0+8)*BST + b_c0], Bp2 + (size_t)(b_r0+8)*Nd + b_c0);
        }
        CP_COMMIT();

        const uint32_t stage_base = asm_base + (uint32_t)((it & 3)*A_SZ)*4;
        const uint32_t* Bsu = &Bsm[(it & 3)*B_SZ];
#pragma unroll
        for (int ks = 0; ks < 2; ks++) {
            uint32_t afrag[2][4];
#pragma unroll
            for (int mt = 0; mt < 2; mt++)
                ldmx4(afrag[mt], stage_base + a_lm_off + (uint32_t)((mt*16*AST + ks*8)*4));
#pragma unroll
            for (int nt = 0; nt < 8; nt++) {
                int cn = wn*64 + nt*8 + qid;
                uint32_t bfrag[2];
                bfrag[0] = Bsu[(ks*8 + tig)*BST + cn];
                bfrag[1] = Bsu[(ks*8 + tig + 4)*BST + cn];
#pragma unroll
                for (int mt = 0; mt < 2; mt++)
                    mma_f16(acc[mt][nt], afrag[mt], bfrag);
            }
        }
    }

    if (SCORES) {
        // fused scores: sc[m] += dot(acc_row, qv[b]) / 16  over this block's 128 cols
        int b = bm >> 3;  // 128 rows per bm, 1024 rows per batch
        const float* qrow = qvv + b*Dd;
#pragma unroll
        for (int mt = 0; mt < 2; mt++) {
            float p0 = 0.f, p1 = 0.f;
#pragma unroll
            for (int nt = 0; nt < 8; nt++) {
                int c0 = bn*128 + wn*64 + nt*8 + 2*tig;
                float q0 = qrow[c0], q1 = qrow[c0+1];
                p0 += acc[mt][nt][0]*q0 + acc[mt][nt][1]*q1;
                p1 += acc[mt][nt][2]*q0 + acc[mt][nt][3]*q1;
            }
            p0 += __shfl_xor_sync(0xffffffffu, p0, 1);
            p0 += __shfl_xor_sync(0xffffffffu, p0, 2);
            p1 += __shfl_xor_sync(0xffffffffu, p1, 1);
            p1 += __shfl_xor_sync(0xffffffffu, p1, 2);
            if (tig == 0) {
                int r0 = bm*128 + wm*32 + mt*16 + qid;
                atomicAdd(&sc[r0],     p0 * 0.0625f);
                atomicAdd(&sc[r0 + 8], p1 * 0.0625f);
            }
        }
        return;
    }

    // epilogue: bias + relu + fp16 pack
#pragma unroll
    for (int mt = 0; mt < 2; mt++) {
        int r0 = bm*128 + wm*32 + mt*16 + qid;
#pragma unroll
        for (int nt = 0; nt < 8; nt++) {
            int c0 = bn*128 + wn*64 + nt*8 + 2*tig;
            float b0 = bias ? bias[c0]   : 0.f;
            float b1 = bias ? bias[c0+1] : 0.f;
            float v0 = acc[mt][nt][0] + b0, v1 = acc[mt][nt][1] + b1;
            float v2 = acc[mt][nt][2] + b0, v3 = acc[mt][nt][3] + b1;
            if (RELU) {
                v0 = fmaxf(v0, 0.f); v1 = fmaxf(v1, 0.f);
                v2 = fmaxf(v2, 0.f); v3 = fmaxf(v3, 0.f);
            }
            int cu = c0 >> 1;
            C[(size_t)r0*Nd2 + cu]     = pkhf(v0, v1);
            C[(size_t)(r0+8)*Nd2 + cu] = pkhf(v2, v3);
        }
    }
}

// ---------------- fp16 flash attention: cp.async double-buffered K + raw V ----------------
#define QKV_RS 384
#define O_RS   128
#define KST 36
#define VRS 32
#define VST 72
#define PST 36
#define K_SZ (64*KST)
#define VR_SZ (64*VRS)
#define ATT_SMEM ((2*K_SZ + 2*VR_SZ + 32*VST + 8*16*PST)*4)   // 62464 bytes

__global__ void __launch_bounds__(256) attn_mma_kernel(
    const uint32_t* __restrict__ QKV, uint32_t* __restrict__ O)
{
    extern __shared__ uint32_t sm[];
    uint32_t* Kst  = sm;                         // [2][K_SZ]
    uint32_t* Vraw = sm + 2*K_SZ;                // [2][VR_SZ]
    uint32_t* Vs   = sm + 2*K_SZ + 2*VR_SZ;      // [32*VST] permuted
    const int tid = threadIdx.x;
    const int warp = tid >> 5, lane = tid & 31;
    const int qid = lane >> 2, tig = lane & 3;
    uint32_t* Psw = sm + 2*K_SZ + 2*VR_SZ + 32*VST + warp*16*PST;

    const int qt = blockIdx.x, head = blockIdx.y, b = blockIdx.z;
    const size_t qbase = ((size_t)b*Nn)*QKV_RS + head*(DH/2);
    const size_t kbase = qbase + 128;
    const size_t vbase = qbase + 256;
    const size_t obase = ((size_t)b*Nn)*O_RS + head*(DH/2);
    const int q0 = qt*128 + warp*16;

    // Q fragments (4 k16 steps over DH=64)
    uint32_t qa[4][4];
#pragma unroll
    for (int s = 0; s < 4; s++) {
        qa[s][0] = QKV[qbase + (size_t)(q0+qid  )*QKV_RS + s*8 + tig];
        qa[s][1] = QKV[qbase + (size_t)(q0+qid+8)*QKV_RS + s*8 + tig];
        qa[s][2] = QKV[qbase + (size_t)(q0+qid  )*QKV_RS + s*8 + tig + 4];
        qa[s][3] = QKV[qbase + (size_t)(q0+qid+8)*QKV_RS + s*8 + tig + 4];
    }

    float oacc[8][4];
#pragma unroll
    for (int dn = 0; dn < 8; dn++)
#pragma unroll
        for (int i = 0; i < 4; i++) oacc[dn][i] = 0.f;
    float m0 = -1e30f, m1 = -1e30f, l0 = 0.f, l1 = 0.f;
    const float scale = 0.125f;

    const int kr = tid >> 3, kq = (tid & 7) << 2;   // K loader: rows kr, kr+32
    const int vr = tid >> 2, vq = (tid & 3) << 3;   // Vraw loader: row vr, cols vq, vq+4
    const int np = tid >> 3, dq = tid & 7;          // permute

    // prologue: tile 0 into stage 0
    cp16(&Kst[kr*KST + kq],       QKV + kbase + (size_t)kr*QKV_RS + kq);
    cp16(&Kst[(kr+32)*KST + kq],  QKV + kbase + (size_t)(kr+32)*QKV_RS + kq);
    cp16(&Vraw[vr*VRS + vq],      QKV + vbase + (size_t)vr*QKV_RS + vq);
    cp16(&Vraw[vr*VRS + vq + 4],  QKV + vbase + (size_t)vr*QKV_RS + vq + 4);
    CP_COMMIT();

    int buf = 0;
    const int ntile = Nn/64;
    for (int jt = 0; jt < ntile; jt++) {
        if (jt + 1 < ntile) {
            int j1 = (jt+1)*64, nb = buf ^ 1;
            cp16(&Kst[nb*K_SZ + kr*KST + kq],      QKV + kbase + (size_t)(j1+kr)*QKV_RS + kq);
            cp16(&Kst[nb*K_SZ + (kr+32)*KST + kq], QKV + kbase + (size_t)(j1+kr+32)*QKV_RS + kq);
            cp16(&Vraw[nb*VR_SZ + vr*VRS + vq],    QKV + vbase + (size_t)(j1+vr)*QKV_RS + vq);
            cp16(&Vraw[nb*VR_SZ + vr*VRS + vq+4],  QKV + vbase + (size_t)(j1+vr)*QKV_RS + vq+4);
        }
        CP_COMMIT();
        CP_WAIT(1);
        __syncthreads();

        const uint32_t* Ks = &Kst[buf*K_SZ];
        const uint32_t* Vr = &Vraw[buf*VR_SZ];

        // permute V raw -> n-pair interleaved
        {
            uint4 r0 = *(const uint4*)(Vr + (2*np  )*VRS + dq*4);
            uint4 r1 = *(const uint4*)(Vr + (2*np+1)*VRS + dq*4);
            uint4 o0, o1;
            o0.x = __byte_perm(r0.x, r1.x, 0x5410); o0.y = __byte_perm(r0.x, r1.x, 0x7632);
            o0.z = __byte_perm(r0.y, r1.y, 0x5410); o0.w = __byte_perm(r0.y, r1.y, 0x7632);
            o1.x = __byte_perm(r0.z, r1.z, 0x5410); o1.y = __byte_perm(r0.z, r1.z, 0x7632);
            o1.z = __byte_perm(r0.w, r1.w, 0x5410); o1.w = __byte_perm(r0.w, r1.w, 0x7632);
            *(uint4*)&Vs[np*VST + dq*8]     = o0;
            *(uint4*)&Vs[np*VST + dq*8 + 4] = o1;
        }

        // S = Q @ K^T
        float sacc[8][4];
#pragma unroll
        for (int nt = 0; nt < 8; nt++)
#pragma unroll
            for (int i = 0; i < 4; i++) sacc[nt][i] = 0.f;
#pragma unroll
        for (int s = 0; s < 4; s++) {
#pragma unroll
            for (int nt = 0; nt < 8; nt++) {
                uint32_t bfrag[2];
                bfrag[0] = Ks[(nt*8+qid)*KST + s*8 + tig];
                bfrag[1] = Ks[(nt*8+qid)*KST + s*8 + tig + 4];
                mma_f16(sacc[nt], qa[s], bfrag);
            }
        }
#pragma unroll
        for (int nt = 0; nt < 8; nt++)
#pragma unroll
            for (int i = 0; i < 4; i++) sacc[nt][i] *= scale;

        // online softmax (rows qid, qid+8)
        float tm0 = -1e30f, tm1 = -1e30f;
#pragma unroll
        for (int nt = 0; nt < 8; nt++) {
            tm0 = fmaxf(tm0, fmaxf(sacc[nt][0], sacc[nt][1]));
            tm1 = fmaxf(tm1, fmaxf(sacc[nt][2], sacc[nt][3]));
        }
        tm0 = fmaxf(tm0, __shfl_xor_sync(0xffffffffu, tm0, 1));
        tm0 = fmaxf(tm0, __shfl_xor_sync(0xffffffffu, tm0, 2));
        tm1 = fmaxf(tm1, __shfl_xor_sync(0xffffffffu, tm1, 1));
        tm1 = fmaxf(tm1, __shfl_xor_sync(0xffffffffu, tm1, 2));
        float mn0 = fmaxf(m0, tm0), mn1 = fmaxf(m1, tm1);
        float c0 = __expf(m0 - mn0), c1 = __expf(m1 - mn1);
        m0 = mn0; m1 = mn1;
        l0 *= c0; l1 *= c1;
#pragma unroll
        for (int dn = 0; dn < 8; dn++) {
            oacc[dn][0] *= c0; oacc[dn][1] *= c0;
            oacc[dn][2] *= c1; oacc[dn][3] *= c1;
        }
#pragma unroll
        for (int nt = 0; nt < 8; nt++) {
            float p0 = __expf(sacc[nt][0] - m0);
            float p1 = __expf(sacc[nt][1] - m0);
            float p2 = __expf(sacc[nt][2] - m1);
            float p3 = __expf(sacc[nt][3] - m1);
            l0 += p0 + p1; l1 += p2 + p3;
            Psw[qid*PST     + nt*4 + tig] = pkhf(p0, p1);
            Psw[(qid+8)*PST + nt*4 + tig] = pkhf(p2, p3);
        }
        __syncthreads();   // Vs permute complete for all warps (also after P store)

        // O += P @ V
#pragma unroll
        for (int sj = 0; sj < 4; sj++) {
            uint32_t afrag[4];
            afrag[0] = Psw[qid*PST     + sj*8 + tig];
            afrag[1] = Psw[(qid+8)*PST + sj*8 + tig];
            afrag[2] = Psw[qid*PST     + sj*8 + tig + 4];
            afrag[3] = Psw[(qid+8)*PST + sj*8 + tig + 4];
#pragma unroll
            for (int dn = 0; dn < 8; dn++) {
                uint32_t bfrag[2];
                bfrag[0] = Vs[(sj*8+tig  )*VST + dn*8 + qid];
                bfrag[1] = Vs[(sj*8+tig+4)*VST + dn*8 + qid];
                mma_f16(oacc[dn], afrag, bfrag);
            }
        }
        buf ^= 1;
        // next iteration's top __syncthreads orders PV reads before Vs overwrite
    }

    l0 += __shfl_xor_sync(0xffffffffu, l0, 1);
    l0 += __shfl_xor_sync(0xffffffffu, l0, 2);
    l1 += __shfl_xor_sync(0xffffffffu, l1, 1);
    l1 += __shfl_xor_sync(0xffffffffu, l1, 2);
    float inv0 = 1.f / l0, inv1 = 1.f / l1;
#pragma unroll
    for (int dn = 0; dn < 8; dn++) {
        int cu = dn*4 + tig;
        O[obase + (size_t)(q0+qid  )*O_RS + cu] = pkhf(oacc[dn][0]*inv0, oacc[dn][1]*inv0);
        O[obase + (size_t)(q0+qid+8)*O_RS + cu] = pkhf(oacc[dn][2]*inv1, oacc[dn][3]*inv1);
    }
}

// ---------------- LayerNorm(h + res) in place (fp16) ----------------
__global__ void ln_res_kernel(uint32_t* __restrict__ h, const uint32_t* __restrict__ res,
                              const float* __restrict__ g, const float* __restrict__ bta)
{
    int row = blockIdx.x*8 + (threadIdx.x >> 5);
    int lane = threadIdx.x & 31;
    size_t off = (size_t)row * (Dd/2);
    float v[8];
    float s = 0.f;
#pragma unroll
    for (int i = 0; i < 4; i++) {
        uint32_t hu = h[off + lane + i*32];
        uint32_t ru = res[off + lane + i*32];
        __half2 hb = *(__half2*)&hu;
        __half2 rb = *(__half2*)&ru;
        v[2*i]   = __half2float(hb.x) + __half2float(rb.x);
        v[2*i+1] = __half2float(hb.y) + __half2float(rb.y);
        s += v[2*i] + v[2*i+1];
    }
#pragma unroll
    for (int o = 16; o; o >>= 1) s += __shfl_xor_sync(0xffffffffu, s, o);
    float mean = s * (1.f/256.f);
    float vs = 0.f;
#pragma unroll
    for (int i = 0; i < 8; i++) { float d = v[i]-mean; vs = fmaf(d, d, vs); }
#pragma unroll
    for (int o = 16; o; o >>= 1) vs += __shfl_xor_sync(0xffffffffu, vs, o);
    float rstd = rsqrtf(vs * (1.f/256.f) + 1e-5f);
#pragma unroll
    for (int i = 0; i < 4; i++) {
        int c = 2*(lane + i*32);
        float o0 = (v[2*i]  -mean)*rstd*g[c]   + bta[c];
        float o1 = (v[2*i+1]-mean)*rstd*g[c+1] + bta[c+1];
        h[off + lane + i*32] = pkhf(o0, o1);
    }
}

// ---------------- h_mean (fp16 in, fp32 out) ----------------
__global__ void hmean_kernel(const __half* __restrict__ h, float* __restrict__ hm)
{
    int b = blockIdx.x, d = threadIdx.x;
    const __half* p = h + (size_t)b*Nn*Dd + d;
    float s = 0.f;
#pragma unroll 8
    for (int n = 0; n < Nn; n++) s += __half2float(p[(size_t)n*Dd]);
    hm[b*Dd + d] = s * (1.f/1024.f);
}

// ---------------- small row GEMM (fp32) ----------------
template<int RELU>
__global__ void rowgemm_kernel(const float* __restrict__ A, const float* __restrict__ W,
                               const float* __restrict__ bias, float* __restrict__ C,
                               int Kd, int Nd)
{
    int b = blockIdx.x;
    __shared__ float xs[1024];
    for (int i = threadIdx.x; i < Kd; i += blockDim.x) xs[i] = A[(size_t)b*Kd + i];
    __syncthreads();
    for (int d = threadIdx.x; d < Nd; d += blockDim.x) {
        float acc = bias ? bias[d] : 0.f;
        for (int k = 0; k < Kd; k++) acc = fmaf(xs[k], W[(size_t)k*Nd + d], acc);
        if (RELU) acc = fmaxf(acc, 0.f);
        C[(size_t)b*Nd + d] = acc;
    }
}

// ---------------- finale: softmaxes + top-64 + sel ----------------
__global__ void finale_kernel(const float* __restrict__ scores, const float* __restrict__ gumbel,
                              const float* __restrict__ logits,
                              float* __restrict__ out_w, float* __restrict__ out_idx,
                              float* __restrict__ out_sel)
{
    int b = blockIdx.x, tid = threadIdx.x;
    __shared__ float w[1024];
    __shared__ float al[1024];
    __shared__ float red[256];
    __shared__ int   redi[256];
    __shared__ int   selidx[64];

    float lm = -1e30f;
    for (int i = tid; i < 1024; i += 256) {
        float v = (scores[b*Nn+i] + gumbel[b*Nn+i]) * 2.0f;
        w[i] = v; lm = fmaxf(lm, v);
    }
    red[tid] = lm; __syncthreads();
    for (int s = 128; s; s >>= 1) { if (tid < s) red[tid] = fmaxf(red[tid], red[tid+s]); __syncthreads(); }
    float M = red[0]; __syncthreads();
    float ls = 0.f;
    for (int i = tid; i < 1024; i += 256) { float e = __expf(w[i]-M); w[i] = e; ls += e; }
    red[tid] = ls; __syncthreads();
    for (int s = 128; s; s >>= 1) { if (tid < s) red[tid] += red[tid+s]; __syncthreads(); }
    float invS = 1.f / red[0]; __syncthreads();
    for (int i = tid; i < 1024; i += 256) {
        float wi = w[i]*invS; w[i] = wi; out_w[b*Nn+i] = wi;
    }

    lm = -1e30f;
    for (int i = tid; i < 1024; i += 256) { float v = logits[b*Nn+i]; al[i] = v; lm = fmaxf(lm, v); }
    __syncthreads();
    red[tid] = lm; __syncthreads();
    for (int s = 128; s; s >>= 1) { if (tid < s) red[tid] = fmaxf(red[tid], red[tid+s]); __syncthreads(); }
    M = red[0]; __syncthreads();
    ls = 0.f;
    for (int i = tid; i < 1024; i += 256) { float e = __expf(al[i]-M); al[i] = e; ls += e; }
    red[tid] = ls; __syncthreads();
    for (int s = 128; s; s >>= 1) { if (tid < s) red[tid] += red[tid+s]; __syncthreads(); }
    invS = 1.f / red[0]; __syncthreads();
    for (int i = tid; i < 1024; i += 256) al[i] *= invS;
    __syncthreads();

    for (int kk = 0; kk < 64; kk++) {
        float bv = -1e30f; int bi = 0x7fffffff;
        for (int i = tid; i < 1024; i += 256) {
            float v = w[i];
            if (v > bv) { bv = v; bi = i; }
        }
        red[tid] = bv; redi[tid] = bi; __syncthreads();
        for (int s = 128; s; s >>= 1) {
            if (tid < s) {
                float ov = red[tid+s]; int oi = redi[tid+s];
                if (ov > red[tid] || (ov == red[tid] && oi < redi[tid])) { red[tid] = ov; redi[tid] = oi; }
            }
            __syncthreads();
        }
        if (tid == 0) { selidx[kk] = redi[0]; w[redi[0]] = -2e30f; }
        __syncthreads();
    }

    float sv = 0.f;
    if (tid < 64) sv = al[selidx[tid]];
    red[tid] = (tid < 64) ? sv : 0.f; __syncthreads();
    for (int s = 128; s; s >>= 1) { if (tid < s) red[tid] += red[tid+s]; __syncthreads(); }
    float inv = 1.f / (red[0] + 1e-12f);
    if (tid < 64) {
        out_idx[b*64 + tid] = (float)selidx[tid];
        out_sel[b*64 + tid] = sv * inv;
    }
}

// ---------------- launch ----------------
extern "C" void kernel_launch(void* const* d_in, const int* in_sizes, int n_in,
                              void* d_out, int out_size)
{
    const float* x       = (const float*)d_in[0];
    const float* gumbel  = (const float*)d_in[1];
    const float* emb_W   = (const float*)d_in[2];
    const float* emb_b   = (const float*)d_in[3];
    const float* Wq      = (const float*)d_in[4];
    const float* Wk      = (const float*)d_in[5];
    const float* Wv      = (const float*)d_in[6];
    const float* Wo      = (const float*)d_in[7];
    const float* ln1_g   = (const float*)d_in[8];
    const float* ln1_b   = (const float*)d_in[9];
    const float* ln2_g   = (const float*)d_in[10];
    const float* ln2_b   = (const float*)d_in[11];
    const float* ffn_W1  = (const float*)d_in[12];
    const float* ffn_b1  = (const float*)d_in[13];
    const float* ffn_W2  = (const float*)d_in[14];
    const float* ffn_b2  = (const float*)d_in[15];
    const float* sha_Wq  = (const float*)d_in[16];
    const float* sha_Wk  = (const float*)d_in[17];
    const float* alloc_W1= (const float*)d_in[18];
    const float* alloc_b1= (const float*)d_in[19];
    const float* alloc_W2= (const float*)d_in[20];
    const float* alloc_b2= (const float*)d_in[21];

    __half *h, *scr, *tmp;
    uint32_t* wpk;
    float *hmean, *qv, *t1, *logits, *scores;
    cudaGetSymbolAddress((void**)&h,      g_h);
    cudaGetSymbolAddress((void**)&scr,    g_scr);
    cudaGetSymbolAddress((void**)&tmp,    g_tmp);
    cudaGetSymbolAddress((void**)&wpk,    g_wpk);
    cudaGetSymbolAddress((void**)&hmean,  g_hmean);
    cudaGetSymbolAddress((void**)&qv,     g_qv);
    cudaGetSymbolAddress((void**)&t1,     g_t1);
    cudaGetSymbolAddress((void**)&logits, g_logits);
    cudaGetSymbolAddress((void**)&scores, g_scores);

    static int cfg_done = 0;
    if (!cfg_done) {
        cudaFuncSetAttribute(tgemm_kernel<0,0>,
                             cudaFuncAttributeMaxDynamicSharedMemorySize, TG_SMEM);
        cudaFuncSetAttribute(tgemm_kernel<1,0>,
                             cudaFuncAttributeMaxDynamicSharedMemorySize, TG_SMEM);
        cudaFuncSetAttribute(tgemm_kernel<0,1>,
                             cudaFuncAttributeMaxDynamicSharedMemorySize, TG_SMEM);
        cudaFuncSetAttribute(attn_mma_kernel,
                             cudaFuncAttributeMaxDynamicSharedMemorySize, ATT_SMEM);
        cfg_done = 1;
    }

    // pack weights -> fp16x2 [K/2][cols]; QKV fused side-by-side into [128][768]
    {
        int t;
        t = 3*128*256;
        packh_kernel<<<(t+255)/256, 256>>>(Wq, wpk + OFF_QKV, 256, 768, 0,   256*256, 128*256, 128*768, t);
        packh_kernel<<<(t+255)/256, 256>>>(Wk, wpk + OFF_QKV, 256, 768, 256, 256*256, 128*256, 128*768, t);
        packh_kernel<<<(t+255)/256, 256>>>(Wv, wpk + OFF_QKV, 256, 768, 512, 256*256, 128*256, 128*768, t);
        packh_kernel<<<(t+255)/256, 256>>>(Wo, wpk + OFF_WO, 256, 256, 0, 256*256, 128*256, 128*256, t);
        t = 3*128*1024;
        packh_kernel<<<(t+255)/256, 256>>>(ffn_W1, wpk + OFF_W1, 1024, 1024, 0, 256*1024, 128*1024, 128*1024, t);
        t = 3*512*256;
        packh_kernel<<<(t+255)/256, 256>>>(ffn_W2, wpk + OFF_W2, 256, 256, 0, 1024*256, 512*256, 512*256, t);
        t = 128*256;
        packh_kernel<<<(t+255)/256, 256>>>(sha_Wk, wpk + OFF_SHA, 256, 256, 0, 256*256, 128*256, 128*256, t);
    }

    __half* qkv = scr;                          // [M][768]
    __half* ao  = scr + (size_t)MM*768;         // [M][256]

    embed_kernel<<<MM/16, 256>>>(x, emb_W, emb_b, h);

    const dim3 gQKV(768/128, MM/128);  // (6,512)
    const dim3 gP(Dd/128, MM/128);     // (2,512)
    const dim3 gF1(DFF/128, MM/128);   // (8,512)

    for (int i = 0; i < Ll; i++) {
        tgemm_kernel<0,0><<<gQKV, 256, TG_SMEM>>>((const uint32_t*)h, wpk + OFF_QKV + (size_t)i*128*768, nullptr, (uint32_t*)qkv, MM, 768, Dd, nullptr, nullptr);
        attn_mma_kernel<<<dim3(Nn/128, Hh, Bb), 256, ATT_SMEM>>>((const uint32_t*)qkv, (uint32_t*)ao);
        tgemm_kernel<0,0><<<gP, 256, TG_SMEM>>>((const uint32_t*)ao, wpk + OFF_WO + (size_t)i*128*256, nullptr, (uint32_t*)tmp, MM, Dd, Dd, nullptr, nullptr);
        ln_res_kernel<<<MM/8, 256>>>((uint32_t*)h, (const uint32_t*)tmp, ln1_g + i*Dd, ln1_b + i*Dd);
        tgemm_kernel<1,0><<<gF1, 256, TG_SMEM>>>((const uint32_t*)h, wpk + OFF_W1 + (size_t)i*128*1024, ffn_b1 + i*DFF, (uint32_t*)scr, MM, DFF, Dd, nullptr, nullptr);
        tgemm_kernel<0,0><<<gP, 256, TG_SMEM>>>((const uint32_t*)scr, wpk + OFF_W2 + (size_t)i*512*256, ffn_b2 + i*Dd, (uint32_t*)tmp, MM, Dd, DFF, nullptr, nullptr);
        ln_res_kernel<<<MM/8, 256>>>((uint32_t*)h, (const uint32_t*)tmp, ln2_g + i*Dd, ln2_b + i*Dd);
    }

    hmean_kernel<<<Bb, 256>>>(h, hmean);
    rowgemm_kernel<0><<<Bb, 256>>>(hmean, sha_Wq, nullptr, qv, Dd, Dd);
    zero_kernel<<<Bb*Nn/256, 256>>>(scores);
    tgemm_kernel<0,1><<<gP, 256, TG_SMEM>>>((const uint32_t*)h, wpk + OFF_SHA, nullptr, (uint32_t*)tmp, MM, Dd, Dd, qv, scores);
    rowgemm_kernel<1><<<Bb, 256>>>(hmean, alloc_W1, alloc_b1, t1, Dd, Dd);
    rowgemm_kernel<0><<<Bb, 256>>>(t1, alloc_W2, alloc_b2, logits, Dd, Nn);

    float* out = (float*)d_out;
    finale_kernel<<<Bb, 256>>>(scores, gumbel, logits,
                               out,
                               out + Bb*Nn,
                               out + Bb*Nn + Bb*Kk);
}

// round 10
// speedup vs baseline: 7.6031x; 1.0111x over previous
#include <cuda_runtime.h>
#include <cuda_fp16.h>
#include <cstdint>

// ---------------- problem dims ----------------
#define Bb 64
#define Nn 1024
#define Din 16
#define Dd 256
#define Hh 4
#define DH 64
#define Ll 3
#define DFF 1024
#define Kk 64
#define MM (Bb*Nn)          // 65536 rows

// ---------------- scratch (static device memory) ----------------
__device__ __half g_h[MM*Dd];           // 32 MB hidden state (fp16)
__device__ __half g_scr[MM*DFF];        // 128 MB qkv|ao or ffn hidden
__device__ __half g_tmp[MM*Dd];         // 32 MB proj/ffn out
__device__ uint32_t g_wpk[1212416];     // packed fp16 weights (u64-fragment layout)
__device__ float g_hmean[Bb*Dd];
__device__ float g_qv[Bb*Dd];
__device__ float g_t1[Bb*Dd];
__device__ float g_logits[Bb*Nn];
__device__ float g_scores[Bb*Nn];

// packed-weight offsets (uint32 units)
#define OFF_QKV  0            // 3 x [64 u64-rows][768]
#define OFF_WO   294912       // 3 x [64][256]
#define OFF_W1   393216       // 3 x [64][1024]
#define OFF_W2   786432       // 3 x [256][256]
#define OFF_SHA  1179648      // [64][256]

__device__ __forceinline__ uint32_t pkhf(float lo, float hi) {
    uint32_t r;
    asm("cvt.rn.f16x2.f32 %0, %1, %2;" : "=r"(r) : "f"(hi), "f"(lo));
    return r;
}

__device__ __forceinline__ void mma_f16(float* c, const uint32_t* a, const uint32_t* b) {
    asm volatile(
        "mma.sync.aligned.m16n8k16.row.col.f32.f16.f16.f32 "
        "{%0,%1,%2,%3}, {%4,%5,%6,%7}, {%8,%9}, {%0,%1,%2,%3};"
        : "+f"(c[0]), "+f"(c[1]), "+f"(c[2]), "+f"(c[3])
        : "r"(a[0]), "r"(a[1]), "r"(a[2]), "r"(a[3]), "r"(b[0]), "r"(b[1]));
}

__device__ __forceinline__ void ldmx4(uint32_t* r, uint32_t saddr) {
    asm volatile("ldmatrix.sync.aligned.m8n8.x4.shared.b16 {%0,%1,%2,%3}, [%4];"
        : "=r"(r[0]), "=r"(r[1]), "=r"(r[2]), "=r"(r[3]) : "r"(saddr));
}

__device__ __forceinline__ void cp16(void* smem, const void* gmem) {
    uint32_t s = (uint32_t)__cvta_generic_to_shared(smem);
    asm volatile("cp.async.cg.shared.global [%0], [%1], 16;" :: "r"(s), "l"(gmem));
}
#define CP_COMMIT() asm volatile("cp.async.commit_group;")
#define CP_WAIT(n)  asm volatile("cp.async.wait_group %0;" :: "n"(n))

// ---------------- fused weight pack: all 7 weights in one launch ----------------
// dst layout per GEMM: u64-fragment rows: u64[(Kd/4)][Nd]; the u64 at (row = t*8 + j,
// col = n) holds {lo = pair(kp = 16t + (j>>2)*8 + (j&3)), hi = pair(kp+4)} for K32 tile t.
__global__ void packall_kernel(const float* __restrict__ Wq, const float* __restrict__ Wk,
                               const float* __restrict__ Wv, const float* __restrict__ Wo,
                               const float* __restrict__ W1, const float* __restrict__ W2,
                               const float* __restrict__ sha, uint32_t* __restrict__ dst)
{
    int seg = blockIdx.y;
    int i = blockIdx.x*256 + threadIdx.x;
    const float* src; int Nsrc, NdT, colOff, KN, KNh, lds, total, dstOff;
    switch (seg) {
        case 0: src=Wq;  dstOff=OFF_QKV; Nsrc=256;  NdT=768;  colOff=0;   KN=65536;  KNh=32768;  lds=98304;  total=98304;  break;
        case 1: src=Wk;  dstOff=OFF_QKV; Nsrc=256;  NdT=768;  colOff=256; KN=65536;  KNh=32768;  lds=98304;  total=98304;  break;
        case 2: src=Wv;  dstOff=OFF_QKV; Nsrc=256;  NdT=768;  colOff=512; KN=65536;  KNh=32768;  lds=98304;  total=98304;  break;
        case 3: src=Wo;  dstOff=OFF_WO;  Nsrc=256;  NdT=256;  colOff=0;   KN=65536;  KNh=32768;  lds=32768;  total=98304;  break;
        case 4: src=W1;  dstOff=OFF_W1;  Nsrc=1024; NdT=1024; colOff=0;   KN=262144; KNh=131072; lds=131072; total=393216; break;
        case 5: src=W2;  dstOff=OFF_W2;  Nsrc=256;  NdT=256;  colOff=0;   KN=262144; KNh=131072; lds=131072; total=393216; break;
        default:src=sha; dstOff=OFF_SHA; Nsrc=256;  NdT=256;  colOff=0;   KN=65536;  KNh=32768;  lds=32768;  total=32768;  break;
    }
    if (i >= total) return;
    int l = i / KNh;
    int rem = i - l*KNh;
    int kp = rem / Nsrc, n = rem - kp*Nsrc;
    int t = kp >> 4, r = kp & 15;
    int j = ((r >> 3) << 2) | (r & 3);
    int half = (r >> 2) & 1;
    const float* s = src + (size_t)l*KN;
    dst[(size_t)dstOff + (size_t)l*lds
        + ((size_t)(t*8 + j)*NdT + colOff + n)*2 + half] =
        pkhf(s[(size_t)(2*kp)*Nsrc + n], s[(size_t)(2*kp+1)*Nsrc + n]);
}

// ---------------- zero scores + hmean ----------------
__global__ void zero2_kernel(float* __restrict__ a, int na, float* __restrict__ b2)
{
    int i = blockIdx.x*256 + threadIdx.x;
    if (i < na) a[i] = 0.f;
    else b2[i - na] = 0.f;
}

// ---------------- embedding: 16 rows/block, W staged in smem ----------------
__global__ void embed_kernel(const float* __restrict__ x, const float* __restrict__ W,
                             const float* __restrict__ bb, __half* __restrict__ h)
{
    __shared__ float Ws[Din*Dd];
    __shared__ float xs[16*Din];
    __shared__ float bsm[Dd];
    const int tid = threadIdx.x;
    const int m0 = blockIdx.x*16;
#pragma unroll
    for (int i = tid; i < Din*Dd; i += 256) Ws[i] = W[i];
    xs[tid] = x[m0*Din + tid];
    bsm[tid] = bb[tid];
    __syncthreads();
    const int d = tid;
#pragma unroll
    for (int r = 0; r < 16; r++) {
        float a = bsm[d];
#pragma unroll
        for (int k = 0; k < Din; k++) a = fmaf(xs[r*Din + k], Ws[k*Dd + d], a);
        h[(size_t)(m0+r)*Dd + d] = __float2half(a);
    }
}

// ---------------- FP16 GEMM: 4-stage cp.async, ldmatrix A, u64 B fragments ----------------
#define AST 20
#define B2ST 132              // u64 row stride in smem
#define A_SZ (128*AST)        // 2560 u32 per stage
#define B_SZ (8*B2ST*2)       // 2112 u32 per stage (8 u64 rows)
#define TG_SMEM (4*(A_SZ + B_SZ)*4)   // 74752 bytes

template<int RELU, int SCORES>
__global__ __launch_bounds__(256, 2) void tgemm_kernel(
    const uint32_t* __restrict__ A, const uint32_t* __restrict__ Wp,
    const float* __restrict__ bias, uint32_t* __restrict__ C,
    int M, int Nd, int Kd,
    const float* __restrict__ qvv, float* __restrict__ sc)
{
    const int Kd2 = Kd >> 1, Nd2 = Nd >> 1;
    extern __shared__ uint32_t dsm[];
    uint32_t* Asm = dsm;               // [4][A_SZ]
    uint32_t* Bsm = dsm + 4*A_SZ;      // [4][B_SZ]

    const int tid = threadIdx.x;
    const int warp = tid >> 5;
    const int lane = tid & 31;
    const int bm = blockIdx.y, bn = blockIdx.x;
    const int wm = warp & 3;
    const int wn = warp >> 2;
    const int qid = lane >> 2;
    const int tig = lane & 3;

    const int a_r0 = tid >> 1, a_c0 = (tid & 1) << 3;
    const int b_r = tid >> 5, b_c = tid & 31;   // B loader: u64 row, 16B chunk

    // ldmatrix lane addressing for A fragments
    const int row_sel = (lane & 7) + ((lane >> 3) & 1) * 8;
    const int col_sel = (lane >> 4) * 4;
    const uint32_t a_lm_off = (uint32_t)(((wm*32 + row_sel)*AST + col_sel) * 4);
    const uint32_t asm_base = (uint32_t)__cvta_generic_to_shared(Asm);

    const uint32_t* Ap = A + (size_t)(bm*128)*Kd2;
    const uint64_t* Bp = (const uint64_t*)Wp + (size_t)bn*128;

    float acc[2][8][4];
#pragma unroll
    for (int mt = 0; mt < 2; mt++)
#pragma unroll
        for (int nt = 0; nt < 8; nt++)
#pragma unroll
            for (int i = 0; i < 4; i++) acc[mt][nt][i] = 0.f;

    const int niter = Kd >> 5;

    // prologue: preload K-tiles 0..2
#pragma unroll
    for (int s = 0; s < 3; s++) {
        const uint32_t* Ap2 = Ap + s*16;
        const uint64_t* Bp2 = Bp + (size_t)(s*8 + b_r)*Nd;
        cp16(&Asm[s*A_SZ + a_r0*AST + a_c0],     Ap2 + (size_t)a_r0*Kd2 + a_c0);
        cp16(&Asm[s*A_SZ + a_r0*AST + a_c0 + 4], Ap2 + (size_t)a_r0*Kd2 + a_c0 + 4);
        cp16(&Bsm[s*B_SZ + b_r*(2*B2ST) + b_c*4],       Bp2 + b_c*2);
        cp16(&Bsm[s*B_SZ + b_r*(2*B2ST) + b_c*4 + 128], Bp2 + b_c*2 + 64);
        CP_COMMIT();
    }

    for (int it = 0; it < niter; it++) {
        CP_WAIT(2);
        __syncthreads();

        int pf = it + 3;
        if (pf < niter) {
            int sb = pf & 3;
            const uint32_t* Ap2 = Ap + pf*16;
            const uint64_t* Bp2 = Bp + (size_t)(pf*8 + b_r)*Nd;
            cp16(&Asm[sb*A_SZ + a_r0*AST + a_c0],     Ap2 + (size_t)a_r0*Kd2 + a_c0);
            cp16(&Asm[sb*A_SZ + a_r0*AST + a_c0 + 4], Ap2 + (size_t)a_r0*Kd2 + a_c0 + 4);
            cp16(&Bsm[sb*B_SZ + b_r*(2*B2ST) + b_c*4],       Bp2 + b_c*2);
            cp16(&Bsm[sb*B_SZ + b_r*(2*B2ST) + b_c*4 + 128], Bp2 + b_c*2 + 64);
        }
        CP_COMMIT();

        const uint32_t stage_base = asm_base + (uint32_t)((it & 3)*A_SZ)*4;
        const uint2* B2 = (const uint2*)(Bsm + (it & 3)*B_SZ);
#pragma unroll
        for (int ks = 0; ks < 2; ks++) {
            uint32_t afrag[2][4];
#pragma unroll
            for (int mt = 0; mt < 2; mt++)
                ldmx4(afrag[mt], stage_base + a_lm_off + (uint32_t)((mt*16*AST + ks*8)*4));
#pragma unroll
            for (int nt = 0; nt < 8; nt++) {
                int cn = wn*64 + nt*8 + qid;
                uint2 bv = B2[(ks*4 + tig)*B2ST + cn];
                uint32_t bfrag[2] = { bv.x, bv.y };
#pragma unroll
                for (int mt = 0; mt < 2; mt++)
                    mma_f16(acc[mt][nt], afrag[mt], bfrag);
            }
        }
    }

    if (SCORES) {
        int b = bm >> 3;
        const float* qrow = qvv + b*Dd;
#pragma unroll
        for (int mt = 0; mt < 2; mt++) {
            float p0 = 0.f, p1 = 0.f;
#pragma unroll
            for (int nt = 0; nt < 8; nt++) {
                int c0 = bn*128 + wn*64 + nt*8 + 2*tig;
                float q0 = qrow[c0], q1 = qrow[c0+1];
                p0 += acc[mt][nt][0]*q0 + acc[mt][nt][1]*q1;
                p1 += acc[mt][nt][2]*q0 + acc[mt][nt][3]*q1;
            }
            p0 += __shfl_xor_sync(0xffffffffu, p0, 1);
            p0 += __shfl_xor_sync(0xffffffffu, p0, 2);
            p1 += __shfl_xor_sync(0xffffffffu, p1, 1);
            p1 += __shfl_xor_sync(0xffffffffu, p1, 2);
            if (tig == 0) {
                int r0 = bm*128 + wm*32 + mt*16 + qid;
                atomicAdd(&sc[r0],     p0 * 0.0625f);
                atomicAdd(&sc[r0 + 8], p1 * 0.0625f);
            }
        }
        return;
    }

    // epilogue: bias + relu + fp16 pack
#pragma unroll
    for (int mt = 0; mt < 2; mt++) {
        int r0 = bm*128 + wm*32 + mt*16 + qid;
#pragma unroll
        for (int nt = 0; nt < 8; nt++) {
            int c0 = bn*128 + wn*64 + nt*8 + 2*tig;
            float b0 = bias ? bias[c0]   : 0.f;
            float b1 = bias ? bias[c0+1] : 0.f;
            float v0 = acc[mt][nt][0] + b0, v1 = acc[mt][nt][1] + b1;
            float v2 = acc[mt][nt][2] + b0, v3 = acc[mt][nt][3] + b1;
            if (RELU) {
                v0 = fmaxf(v0, 0.f); v1 = fmaxf(v1, 0.f);
                v2 = fmaxf(v2, 0.f); v3 = fmaxf(v3, 0.f);
            }
            int cu = c0 >> 1;
            C[(size_t)r0*Nd2 + cu]     = pkhf(v0, v1);
            C[(size_t)(r0+8)*Nd2 + cu] = pkhf(v2, v3);
        }
    }
}

// ---------------- fp16 flash attention: cp.async double-buffered K + raw V ----------------
#define QKV_RS 384
#define O_RS   128
#define KST 36
#define VRS 32
#define VST 72
#define PST 36
#define K_SZ (64*KST)
#define VR_SZ (64*VRS)
#define ATT_SMEM ((2*K_SZ + 2*VR_SZ + 32*VST + 8*16*PST)*4)   // 62464 bytes

__global__ void __launch_bounds__(256) attn_mma_kernel(
    const uint32_t* __restrict__ QKV, uint32_t* __restrict__ O)
{
    extern __shared__ uint32_t sm[];
    uint32_t* Kst  = sm;                         // [2][K_SZ]
    uint32_t* Vraw = sm + 2*K_SZ;                // [2][VR_SZ]
    uint32_t* Vs   = sm + 2*K_SZ + 2*VR_SZ;      // [32*VST] permuted
    const int tid = threadIdx.x;
    const int warp = tid >> 5, lane = tid & 31;
    const int qid = lane >> 2, tig = lane & 3;
    uint32_t* Psw = sm + 2*K_SZ + 2*VR_SZ + 32*VST + warp*16*PST;

    const int qt = blockIdx.x, head = blockIdx.y, b = blockIdx.z;
    const size_t qbase = ((size_t)b*Nn)*QKV_RS + head*(DH/2);
    const size_t kbase = qbase + 128;
    const size_t vbase = qbase + 256;
    const size_t obase = ((size_t)b*Nn)*O_RS + head*(DH/2);
    const int q0 = qt*128 + warp*16;

    uint32_t qa[4][4];
#pragma unroll
    for (int s = 0; s < 4; s++) {
        qa[s][0] = QKV[qbase + (size_t)(q0+qid  )*QKV_RS + s*8 + tig];
        qa[s][1] = QKV[qbase + (size_t)(q0+qid+8)*QKV_RS + s*8 + tig];
        qa[s][2] = QKV[qbase + (size_t)(q0+qid  )*QKV_RS + s*8 + tig + 4];
        qa[s][3] = QKV[qbase + (size_t)(q0+qid+8)*QKV_RS + s*8 + tig + 4];
    }

    float oacc[8][4];
#pragma unroll
    for (int dn = 0; dn < 8; dn++)
#pragma unroll
        for (int i = 0; i < 4; i++) oacc[dn][i] = 0.f;
    float m0 = -1e30f, m1 = -1e30f, l0 = 0.f, l1 = 0.f;
    const float scale = 0.125f;

    const int kr = tid >> 3, kq = (tid & 7) << 2;
    const int vr = tid >> 2, vq = (tid & 3) << 3;
    const int np = tid >> 3, dq = tid & 7;

    cp16(&Kst[kr*KST + kq],       QKV + kbase + (size_t)kr*QKV_RS + kq);
    cp16(&Kst[(kr+32)*KST + kq],  QKV + kbase + (size_t)(kr+32)*QKV_RS + kq);
    cp16(&Vraw[vr*VRS + vq],      QKV + vbase + (size_t)vr*QKV_RS + vq);
    cp16(&Vraw[vr*VRS + vq + 4],  QKV + vbase + (size_t)vr*QKV_RS + vq + 4);
    CP_COMMIT();

    int buf = 0;
    const int ntile = Nn/64;
    for (int jt = 0; jt < ntile; jt++) {
        if (jt + 1 < ntile) {
            int j1 = (jt+1)*64, nb = buf ^ 1;
            cp16(&Kst[nb*K_SZ + kr*KST + kq],      QKV + kbase + (size_t)(j1+kr)*QKV_RS + kq);
            cp16(&Kst[nb*K_SZ + (kr+32)*KST + kq], QKV + kbase + (size_t)(j1+kr+32)*QKV_RS + kq);
            cp16(&Vraw[nb*VR_SZ + vr*VRS + vq],    QKV + vbase + (size_t)(j1+vr)*QKV_RS + vq);
            cp16(&Vraw[nb*VR_SZ + vr*VRS + vq+4],  QKV + vbase + (size_t)(j1+vr)*QKV_RS + vq+4);
        }
        CP_COMMIT();
        CP_WAIT(1);
        __syncthreads();

        const uint32_t* Ks = &Kst[buf*K_SZ];
        const uint32_t* Vr = &Vraw[buf*VR_SZ];

        {
            uint4 r0 = *(const uint4*)(Vr + (2*np  )*VRS + dq*4);
            uint4 r1 = *(const uint4*)(Vr + (2*np+1)*VRS + dq*4);
            uint4 o0, o1;
            o0.x = __byte_perm(r0.x, r1.x, 0x5410); o0.y = __byte_perm(r0.x, r1.x, 0x7632);
            o0.z = __byte_perm(r0.y, r1.y, 0x5410); o0.w = __byte_perm(r0.y, r1.y, 0x7632);
            o1.x = __byte_perm(r0.z, r1.z, 0x5410); o1.y = __byte_perm(r0.z, r1.z, 0x7632);
            o1.z = __byte_perm(r0.w, r1.w, 0x5410); o1.w = __byte_perm(r0.w, r1.w, 0x7632);
            *(uint4*)&Vs[np*VST + dq*8]     = o0;
            *(uint4*)&Vs[np*VST + dq*8 + 4] = o1;
        }

        float sacc[8][4];
#pragma unroll
        for (int nt = 0; nt < 8; nt++)
#pragma unroll
            for (int i = 0; i < 4; i++) sacc[nt][i] = 0.f;
#pragma unroll
        for (int s = 0; s < 4; s++) {
#pragma unroll
            for (int nt = 0; nt < 8; nt++) {
                uint32_t bfrag[2];
                bfrag[0] = Ks[(nt*8+qid)*KST + s*8 + tig];
                bfrag[1] = Ks[(nt*8+qid)*KST + s*8 + tig + 4];
                mma_f16(sacc[nt], qa[s], bfrag);
            }
        }
#pragma unroll
        for (int nt = 0; nt < 8; nt++)
#pragma unroll
            for (int i = 0; i < 4; i++) sacc[nt][i] *= scale;

        float tm0 = -1e30f, tm1 = -1e30f;
#pragma unroll
        for (int nt = 0; nt < 8; nt++) {
            tm0 = fmaxf(tm0, fmaxf(sacc[nt][0], sacc[nt][1]));
            tm1 = fmaxf(tm1, fmaxf(sacc[nt][2], sacc[nt][3]));
        }
        tm0 = fmaxf(tm0, __shfl_xor_sync(0xffffffffu, tm0, 1));
        tm0 = fmaxf(tm0, __shfl_xor_sync(0xffffffffu, tm0, 2));
        tm1 = fmaxf(tm1, __shfl_xor_sync(0xffffffffu, tm1, 1));
        tm1 = fmaxf(tm1, __shfl_xor_sync(0xffffffffu, tm1, 2));
        float mn0 = fmaxf(m0, tm0), mn1 = fmaxf(m1, tm1);
        float c0 = __expf(m0 - mn0), c1 = __expf(m1 - mn1);
        m0 = mn0; m1 = mn1;
        l0 *= c0; l1 *= c1;
#pragma unroll
        for (int dn = 0; dn < 8; dn++) {
            oacc[dn][0] *= c0; oacc[dn][1] *= c0;
            oacc[dn][2] *= c1; oacc[dn][3] *= c1;
        }
#pragma unroll
        for (int nt = 0; nt < 8; nt++) {
            float p0 = __expf(sacc[nt][0] - m0);
            float p1 = __expf(sacc[nt][1] - m0);
            float p2 = __expf(sacc[nt][2] - m1);
            float p3 = __expf(sacc[nt][3] - m1);
            l0 += p0 + p1; l1 += p2 + p3;
            Psw[qid*PST     + nt*4 + tig] = pkhf(p0, p1);
            Psw[(qid+8)*PST + nt*4 + tig] = pkhf(p2, p3);
        }
        __syncthreads();

#pragma unroll
        for (int sj = 0; sj < 4; sj++) {
            uint32_t afrag[4];
            afrag[0] = Psw[qid*PST     + sj*8 + tig];
            afrag[1] = Psw[(qid+8)*PST + sj*8 + tig];
            afrag[2] = Psw[qid*PST     + sj*8 + tig + 4];
            afrag[3] = Psw[(qid+8)*PST + sj*8 + tig + 4];
#pragma unroll
            for (int dn = 0; dn < 8; dn++) {
                uint32_t bfrag[2];
                bfrag[0] = Vs[(sj*8+tig  )*VST + dn*8 + qid];
                bfrag[1] = Vs[(sj*8+tig+4)*VST + dn*8 + qid];
                mma_f16(oacc[dn], afrag, bfrag);
            }
        }
        buf ^= 1;
    }

    l0 += __shfl_xor_sync(0xffffffffu, l0, 1);
    l0 += __shfl_xor_sync(0xffffffffu, l0, 2);
    l1 += __shfl_xor_sync(0xffffffffu, l1, 1);
    l1 += __shfl_xor_sync(0xffffffffu, l1, 2);
    float inv0 = 1.f / l0, inv1 = 1.f / l1;
#pragma unroll
    for (int dn = 0; dn < 8; dn++) {
        int cu = dn*4 + tig;
        O[obase + (size_t)(q0+qid  )*O_RS + cu] = pkhf(oacc[dn][0]*inv0, oacc[dn][1]*inv0);
        O[obase + (size_t)(q0+qid+8)*O_RS + cu] = pkhf(oacc[dn][2]*inv1, oacc[dn][3]*inv1);
    }
}

// ---------------- LayerNorm(h + res) in place (fp16) ----------------
__global__ void ln_res_kernel(uint32_t* __restrict__ h, const uint32_t* __restrict__ res,
                              const float* __restrict__ g, const float* __restrict__ bta)
{
    int row = blockIdx.x*8 + (threadIdx.x >> 5);
    int lane = threadIdx.x & 31;
    size_t off = (size_t)row * (Dd/2);
    float v[8];
    float s = 0.f;
#pragma unroll
    for (int i = 0; i < 4; i++) {
        uint32_t hu = h[off + lane + i*32];
        uint32_t ru = res[off + lane + i*32];
        __half2 hb = *(__half2*)&hu;
        __half2 rb = *(__half2*)&ru;
        v[2*i]   = __half2float(hb.x) + __half2float(rb.x);
        v[2*i+1] = __half2float(hb.y) + __half2float(rb.y);
        s += v[2*i] + v[2*i+1];
    }
#pragma unroll
    for (int o = 16; o; o >>= 1) s += __shfl_xor_sync(0xffffffffu, s, o);
    float mean = s * (1.f/256.f);
    float vs = 0.f;
#pragma unroll
    for (int i = 0; i < 8; i++) { float d = v[i]-mean; vs = fmaf(d, d, vs); }
#pragma unroll
    for (int o = 16; o; o >>= 1) vs += __shfl_xor_sync(0xffffffffu, vs, o);
    float rstd = rsqrtf(vs * (1.f/256.f) + 1e-5f);
#pragma unroll
    for (int i = 0; i < 4; i++) {
        int c = 2*(lane + i*32);
        float o0 = (v[2*i]  -mean)*rstd*g[c]   + bta[c];
        float o1 = (v[2*i+1]-mean)*rstd*g[c+1] + bta[c+1];
        h[off + lane + i*32] = pkhf(o0, o1);
    }
}

// ---------------- h_mean: 4 partial blocks per batch + atomics ----------------
__global__ void hmean_kernel(const __half* __restrict__ h, float* __restrict__ hm)
{
    int b = blockIdx.y, seg = blockIdx.x;
    int d = threadIdx.x;
    const __half* p = h + ((size_t)b*Nn + seg*256)*Dd + d;
    float s = 0.f;
#pragma unroll 8
    for (int n = 0; n < 256; n++) s += __half2float(p[(size_t)n*Dd]);
    atomicAdd(&hm[b*Dd + d], s * (1.f/1024.f));
}

// ---------------- small row GEMM (fp32) ----------------
template<int RELU>
__global__ void rowgemm_kernel(const float* __restrict__ A, const float* __restrict__ W,
                               const float* __restrict__ bias, float* __restrict__ C,
                               int Kd, int Nd)
{
    int b = blockIdx.x;
    __shared__ float xs[1024];
    for (int i = threadIdx.x; i < Kd; i += blockDim.x) xs[i] = A[(size_t)b*Kd + i];
    __syncthreads();
    for (int d = threadIdx.x; d < Nd; d += blockDim.x) {
        float acc = bias ? bias[d] : 0.f;
        for (int k = 0; k < Kd; k++) acc = fmaf(xs[k], W[(size_t)k*Nd + d], acc);
        if (RELU) acc = fmaxf(acc, 0.f);
        C[(size_t)b*Nd + d] = acc;
    }
}

// ---------------- finale: softmaxes + top-64 + sel ----------------
__global__ void finale_kernel(const float* __restrict__ scores, const float* __restrict__ gumbel,
                              const float* __restrict__ logits,
                              float* __restrict__ out_w, float* __restrict__ out_idx,
                              float* __restrict__ out_sel)
{
    int b = blockIdx.x, tid = threadIdx.x;
    __shared__ float w[1024];
    __shared__ float al[1024];
    __shared__ float red[256];
    __shared__ int   redi[256];
    __shared__ int   selidx[64];

    float lm = -1e30f;
    for (int i = tid; i < 1024; i += 256) {
        float v = (scores[b*Nn+i] + gumbel[b*Nn+i]) * 2.0f;
        w[i] = v; lm = fmaxf(lm, v);
    }
    red[tid] = lm; __syncthreads();
    for (int s = 128; s; s >>= 1) { if (tid < s) red[tid] = fmaxf(red[tid], red[tid+s]); __syncthreads(); }
    float M = red[0]; __syncthreads();
    float ls = 0.f;
    for (int i = tid; i < 1024; i += 256) { float e = __expf(w[i]-M); w[i] = e; ls += e; }
    red[tid] = ls; __syncthreads();
    for (int s = 128; s; s >>= 1) { if (tid < s) red[tid] += red[tid+s]; __syncthreads(); }
    float invS = 1.f / red[0]; __syncthreads();
    for (int i = tid; i < 1024; i += 256) {
        float wi = w[i]*invS; w[i] = wi; out_w[b*Nn+i] = wi;
    }

    lm = -1e30f;
    for (int i = tid; i < 1024; i += 256) { float v = logits[b*Nn+i]; al[i] = v; lm = fmaxf(lm, v); }
    __syncthreads();
    red[tid] = lm; __syncthreads();
    for (int s = 128; s; s >>= 1) { if (tid < s) red[tid] = fmaxf(red[tid], red[tid+s]); __syncthreads(); }
    M = red[0]; __syncthreads();
    ls = 0.f;
    for (int i = tid; i < 1024; i += 256) { float e = __expf(al[i]-M); al[i] = e; ls += e; }
    red[tid] = ls; __syncthreads();
    for (int s = 128; s; s >>= 1) { if (tid < s) red[tid] += red[tid+s]; __syncthreads(); }
    invS = 1.f / red[0]; __syncthreads();
    for (int i = tid; i < 1024; i += 256) al[i] *= invS;
    __syncthreads();

    for (int kk = 0; kk < 64; kk++) {
        float bv = -1e30f; int bi = 0x7fffffff;
        for (int i = tid; i < 1024; i += 256) {
            float v = w[i];
            if (v > bv) { bv = v; bi = i; }
        }
        red[tid] = bv; redi[tid] = bi; __syncthreads();
        for (int s = 128; s; s >>= 1) {
            if (tid < s) {
                float ov = red[tid+s]; int oi = redi[tid+s];
                if (ov > red[tid] || (ov == red[tid] && oi < redi[tid])) { red[tid] = ov; redi[tid] = oi; }
            }
            __syncthreads();
        }
        if (tid == 0) { selidx[kk] = redi[0]; w[redi[0]] = -2e30f; }
        __syncthreads();
    }

    float sv = 0.f;
    if (tid < 64) sv = al[selidx[tid]];
    red[tid] = (tid < 64) ? sv : 0.f; __syncthreads();
    for (int s = 128; s; s >>= 1) { if (tid < s) red[tid] += red[tid+s]; __syncthreads(); }
    float inv = 1.f / (red[0] + 1e-12f);
    if (tid < 64) {
        out_idx[b*64 + tid] = (float)selidx[tid];
        out_sel[b*64 + tid] = sv * inv;
    }
}

// ---------------- launch ----------------
extern "C" void kernel_launch(void* const* d_in, const int* in_sizes, int n_in,
                              void* d_out, int out_size)
{
    const float* x       = (const float*)d_in[0];
    const float* gumbel  = (const float*)d_in[1];
    const float* emb_W   = (const float*)d_in[2];
    const float* emb_b   = (const float*)d_in[3];
    const float* Wq      = (const float*)d_in[4];
    const float* Wk      = (const float*)d_in[5];
    const float* Wv      = (const float*)d_in[6];
    const float* Wo      = (const float*)d_in[7];
    const float* ln1_g   = (const float*)d_in[8];
    const float* ln1_b   = (const float*)d_in[9];
    const float* ln2_g   = (const float*)d_in[10];
    const float* ln2_b   = (const float*)d_in[11];
    const float* ffn_W1  = (const float*)d_in[12];
    const float* ffn_b1  = (const float*)d_in[13];
    const float* ffn_W2  = (const float*)d_in[14];
    const float* ffn_b2  = (const float*)d_in[15];
    const float* sha_Wq  = (const float*)d_in[16];
    const float* sha_Wk  = (const float*)d_in[17];
    const float* alloc_W1= (const float*)d_in[18];
    const float* alloc_b1= (const float*)d_in[19];
    const float* alloc_W2= (const float*)d_in[20];
    const float* alloc_b2= (const float*)d_in[21];

    __half *h, *scr, *tmp;
    uint32_t* wpk;
    float *hmean, *qv, *t1, *logits, *scores;
    cudaGetSymbolAddress((void**)&h,      g_h);
    cudaGetSymbolAddress((void**)&scr,    g_scr);
    cudaGetSymbolAddress((void**)&tmp,    g_tmp);
    cudaGetSymbolAddress((void**)&wpk,    g_wpk);
    cudaGetSymbolAddress((void**)&hmean,  g_hmean);
    cudaGetSymbolAddress((void**)&qv,     g_qv);
    cudaGetSymbolAddress((void**)&t1,     g_t1);
    cudaGetSymbolAddress((void**)&logits, g_logits);
    cudaGetSymbolAddress((void**)&scores, g_scores);

    static int cfg_done = 0;
    if (!cfg_done) {
        cudaFuncSetAttribute(tgemm_kernel<0,0>,
                             cudaFuncAttributeMaxDynamicSharedMemorySize, TG_SMEM);
        cudaFuncSetAttribute(tgemm_kernel<1,0>,
                             cudaFuncAttributeMaxDynamicSharedMemorySize, TG_SMEM);
        cudaFuncSetAttribute(tgemm_kernel<0,1>,
                             cudaFuncAttributeMaxDynamicSharedMemorySize, TG_SMEM);
        cudaFuncSetAttribute(attn_mma_kernel,
                             cudaFuncAttributeMaxDynamicSharedMemorySize, ATT_SMEM);
        cfg_done = 1;
    }

    // fused weight pack (single launch, all 7 weights)
    packall_kernel<<<dim3(1536, 7), 256>>>(Wq, Wk, Wv, Wo, ffn_W1, ffn_W2, sha_Wk, wpk);

    // zero scores + hmean accumulators
    zero2_kernel<<<(Bb*Nn + Bb*Dd)/256, 256>>>(scores, Bb*Nn, hmean);

    __half* qkv = scr;                          // [M][768]
    __half* ao  = scr + (size_t)MM*768;         // [M][256]

    embed_kernel<<<MM/16, 256>>>(x, emb_W, emb_b, h);

    const dim3 gQKV(768/128, MM/128);  // (6,512)
    const dim3 gP(Dd/128, MM/128);     // (2,512)
    const dim3 gF1(DFF/128, MM/128);   // (8,512)

    for (int i = 0; i < Ll; i++) {
        tgemm_kernel<0,0><<<gQKV, 256, TG_SMEM>>>((const uint32_t*)h, wpk + OFF_QKV + (size_t)i*128*768, nullptr, (uint32_t*)qkv, MM, 768, Dd, nullptr, nullptr);
        attn_mma_kernel<<<dim3(Nn/128, Hh, Bb), 256, ATT_SMEM>>>((const uint32_t*)qkv, (uint32_t*)ao);
        tgemm_kernel<0,0><<<gP, 256, TG_SMEM>>>((const uint32_t*)ao, wpk + OFF_WO + (size_t)i*128*256, nullptr, (uint32_t*)tmp, MM, Dd, Dd, nullptr, nullptr);
        ln_res_kernel<<<MM/8, 256>>>((uint32_t*)h, (const uint32_t*)tmp, ln1_g + i*Dd, ln1_b + i*Dd);
        tgemm_kernel<1,0><<<gF1, 256, TG_SMEM>>>((const uint32_t*)h, wpk + OFF_W1 + (size_t)i*128*1024, ffn_b1 + i*DFF, (uint32_t*)scr, MM, DFF, Dd, nullptr, nullptr);
        tgemm_kernel<0,0><<<gP, 256, TG_SMEM>>>((const uint32_t*)scr, wpk + OFF_W2 + (size_t)i*512*256, ffn_b2 + i*Dd, (uint32_t*)tmp, MM, Dd, DFF, nullptr, nullptr);
        ln_res_kernel<<<MM/8, 256>>>((uint32_t*)h, (const uint32_t*)tmp, ln2_g + i*Dd, ln2_b + i*Dd);
    }

    hmean_kernel<<<dim3(4, Bb), 256>>>(h, hmean);
    rowgemm_kernel<0><<<Bb, 256>>>(hmean, sha_Wq, nullptr, qv, Dd, Dd);
    tgemm_kernel<0,1><<<gP, 256, TG_SMEM>>>((const uint32_t*)h, wpk + OFF_SHA, nullptr, (uint32_t*)tmp, MM, Dd, Dd, qv, scores);
    rowgemm_kernel<1><<<Bb, 256>>>(hmean, alloc_W1, alloc_b1, t1, Dd, Dd);
    rowgemm_kernel<0><<<Bb, 256>>>(t1, alloc_W2, alloc_b2, logits, Dd, Nn);

    float* out = (float*)d_out;
    finale_kernel<<<Bb, 256>>>(scores, gumbel, logits,
                               out,
                               out + Bb*Nn,
                               out + Bb*Nn + Bb*Kk);
}

// round 12
// speedup vs baseline: 8.0887x; 1.0639x over previous
#include <cuda_runtime.h>
#include <cuda_fp16.h>
#include <cstdint>

// ---------------- problem dims ----------------
#define Bb 64
#define Nn 1024
#define Din 16
#define Dd 256
#define Hh 4
#define DH 64
#define Ll 3
#define DFF 1024
#define Kk 64
#define MM (Bb*Nn)          // 65536 rows

// ---------------- scratch (static device memory) ----------------
__device__ __half g_h[MM*Dd];           // 32 MB hidden state (fp16)
__device__ __half g_scr[MM*DFF];        // 128 MB qkv|ao or ffn hidden
__device__ __half g_tmp[MM*Dd];         // 32 MB proj/ffn out
__device__ uint32_t g_wpk[1212416];     // packed fp16 weights (u64-fragment layout)
__device__ float g_hmean[Bb*Dd];
__device__ float g_qv[Bb*Dd];
__device__ float g_t1[Bb*Dd];
__device__ float g_logits[Bb*Nn];
__device__ float g_scores[Bb*Nn];

// packed-weight offsets (uint32 units)
#define OFF_QKV  0            // 3 x [64 u64-rows][768]
#define OFF_WO   294912       // 3 x [64][256]
#define OFF_W1   393216       // 3 x [64][1024]
#define OFF_W2   786432       // 3 x [256][256]
#define OFF_SHA  1179648      // [64][256]

__device__ __forceinline__ uint32_t pkhf(float lo, float hi) {
    uint32_t r;
    asm("cvt.rn.f16x2.f32 %0, %1, %2;" : "=r"(r) : "f"(hi), "f"(lo));
    return r;
}

__device__ __forceinline__ void mma_f16(float* c, const uint32_t* a, const uint32_t* b) {
    asm volatile(
        "mma.sync.aligned.m16n8k16.row.col.f32.f16.f16.f32 "
        "{%0,%1,%2,%3}, {%4,%5,%6,%7}, {%8,%9}, {%0,%1,%2,%3};"
        : "+f"(c[0]), "+f"(c[1]), "+f"(c[2]), "+f"(c[3])
        : "r"(a[0]), "r"(a[1]), "r"(a[2]), "r"(a[3]), "r"(b[0]), "r"(b[1]));
}

__device__ __forceinline__ void ldmx4(uint32_t* r, uint32_t saddr) {
    asm volatile("ldmatrix.sync.aligned.m8n8.x4.shared.b16 {%0,%1,%2,%3}, [%4];"
        : "=r"(r[0]), "=r"(r[1]), "=r"(r[2]), "=r"(r[3]) : "r"(saddr));
}

__device__ __forceinline__ void cp16(void* smem, const void* gmem) {
    uint32_t s = (uint32_t)__cvta_generic_to_shared(smem);
    asm volatile("cp.async.cg.shared.global [%0], [%1], 16;" :: "r"(s), "l"(gmem));
}
#define CP_COMMIT() asm volatile("cp.async.commit_group;")
#define CP_WAIT(n)  asm volatile("cp.async.wait_group %0;" :: "n"(n))

// ---------------- fused weight pack: all 7 weights in one launch ----------------
__global__ void packall_kernel(const float* __restrict__ Wq, const float* __restrict__ Wk,
                               const float* __restrict__ Wv, const float* __restrict__ Wo,
                               const float* __restrict__ W1, const float* __restrict__ W2,
                               const float* __restrict__ sha, uint32_t* __restrict__ dst)
{
    int seg = blockIdx.y;
    int i = blockIdx.x*256 + threadIdx.x;
    const float* src; int Nsrc, NdT, colOff, KN, KNh, lds, total, dstOff;
    switch (seg) {
        case 0: src=Wq;  dstOff=OFF_QKV; Nsrc=256;  NdT=768;  colOff=0;   KN=65536;  KNh=32768;  lds=98304;  total=98304;  break;
        case 1: src=Wk;  dstOff=OFF_QKV; Nsrc=256;  NdT=768;  colOff=256; KN=65536;  KNh=32768;  lds=98304;  total=98304;  break;
        case 2: src=Wv;  dstOff=OFF_QKV; Nsrc=256;  NdT=768;  colOff=512; KN=65536;  KNh=32768;  lds=98304;  total=98304;  break;
        case 3: src=Wo;  dstOff=OFF_WO;  Nsrc=256;  NdT=256;  colOff=0;   KN=65536;  KNh=32768;  lds=32768;  total=98304;  break;
        case 4: src=W1;  dstOff=OFF_W1;  Nsrc=1024; NdT=1024; colOff=0;   KN=262144; KNh=131072; lds=131072; total=393216; break;
        case 5: src=W2;  dstOff=OFF_W2;  Nsrc=256;  NdT=256;  colOff=0;   KN=262144; KNh=131072; lds=131072; total=393216; break;
        default:src=sha; dstOff=OFF_SHA; Nsrc=256;  NdT=256;  colOff=0;   KN=65536;  KNh=32768;  lds=32768;  total=32768;  break;
    }
    if (i >= total) return;
    int l = i / KNh;
    int rem = i - l*KNh;
    int kp = rem / Nsrc, n = rem - kp*Nsrc;
    int t = kp >> 4, r = kp & 15;
    int j = ((r >> 3) << 2) | (r & 3);
    int half = (r >> 2) & 1;
    const float* s = src + (size_t)l*KN;
    dst[(size_t)dstOff + (size_t)l*lds
        + ((size_t)(t*8 + j)*NdT + colOff + n)*2 + half] =
        pkhf(s[(size_t)(2*kp)*Nsrc + n], s[(size_t)(2*kp+1)*Nsrc + n]);
}

// ---------------- zero scores + hmean ----------------
__global__ void zero2_kernel(float* __restrict__ a, int na, float* __restrict__ b2)
{
    int i = blockIdx.x*256 + threadIdx.x;
    if (i < na) a[i] = 0.f;
    else b2[i - na] = 0.f;
}

// ---------------- embedding: 16 rows/block, W staged in smem ----------------
__global__ void embed_kernel(const float* __restrict__ x, const float* __restrict__ W,
                             const float* __restrict__ bb, __half* __restrict__ h)
{
    __shared__ float Ws[Din*Dd];
    __shared__ float xs[16*Din];
    __shared__ float bsm[Dd];
    const int tid = threadIdx.x;
    const int m0 = blockIdx.x*16;
#pragma unroll
    for (int i = tid; i < Din*Dd; i += 256) Ws[i] = W[i];
    xs[tid] = x[m0*Din + tid];
    bsm[tid] = bb[tid];
    __syncthreads();
    const int d = tid;
#pragma unroll
    for (int r = 0; r < 16; r++) {
        float a = bsm[d];
#pragma unroll
        for (int k = 0; k < Din; k++) a = fmaf(xs[r*Din + k], Ws[k*Dd + d], a);
        h[(size_t)(m0+r)*Dd + d] = __float2half(a);
    }
}

// ---------------- FP16 GEMM: pair-wise double-buffered cp.async, ldmatrix A, u64 B ----------------
#define AST 20
#define B2ST 132              // u64 row stride in smem
#define A_SZ (128*AST)        // 2560 u32 per stage
#define B_SZ (8*B2ST*2)       // 2112 u32 per stage (8 u64 rows)
#define TG_SMEM (4*(A_SZ + B_SZ)*4)   // 74752 bytes

template<int RELU, int SCORES>
__global__ __launch_bounds__(256, 2) void tgemm_kernel(
    const uint32_t* __restrict__ A, const uint32_t* __restrict__ Wp,
    const float* __restrict__ bias, uint32_t* __restrict__ C,
    int M, int Nd, int Kd,
    const float* __restrict__ qvv, float* __restrict__ sc)
{
    const int Kd2 = Kd >> 1, Nd2 = Nd >> 1;
    extern __shared__ uint32_t dsm[];
    uint32_t* Asm = dsm;               // [4][A_SZ]
    uint32_t* Bsm = dsm + 4*A_SZ;      // [4][B_SZ]

    const int tid = threadIdx.x;
    const int warp = tid >> 5;
    const int lane = tid & 31;
    const int bm = blockIdx.y, bn = blockIdx.x;
    const int wm = warp & 3;
    const int wn = warp >> 2;
    const int qid = lane >> 2;
    const int tig = lane & 3;

    const int a_r0 = tid >> 1, a_c0 = (tid & 1) << 3;
    const int b_r = tid >> 5, b_c = tid & 31;   // B loader: u64 row, 16B chunk

    // ldmatrix lane addressing for A fragments
    const int row_sel = (lane & 7) + ((lane >> 3) & 1) * 8;
    const int col_sel = (lane >> 4) * 4;
    const uint32_t a_lm_off = (uint32_t)(((wm*32 + row_sel)*AST + col_sel) * 4);
    const uint32_t asm_base = (uint32_t)__cvta_generic_to_shared(Asm);

    const uint32_t* Ap = A + (size_t)(bm*128)*Kd2;
    const uint64_t* Bp = (const uint64_t*)Wp + (size_t)bn*128;

    float acc[2][8][4];
#pragma unroll
    for (int mt = 0; mt < 2; mt++)
#pragma unroll
        for (int nt = 0; nt < 8; nt++)
#pragma unroll
            for (int i = 0; i < 4; i++) acc[mt][nt][i] = 0.f;

    const int niter = Kd >> 5;     // 8 (K=256) or 32 (K=1024); always even
    const int npair = niter >> 1;

#define LOAD_TILE(ck, s) do {                                                      \
        int _ck = (ck), _s = (s);                                                  \
        const uint32_t* Ap2 = Ap + _ck*16;                                         \
        const uint64_t* Bp2 = Bp + (size_t)(_ck*8 + b_r)*Nd;                       \
        cp16(&Asm[_s*A_SZ + a_r0*AST + a_c0],     Ap2 + (size_t)a_r0*Kd2 + a_c0);  \
        cp16(&Asm[_s*A_SZ + a_r0*AST + a_c0 + 4], Ap2 + (size_t)a_r0*Kd2 + a_c0 + 4); \
        cp16(&Bsm[_s*B_SZ + b_r*(2*B2ST) + b_c*4],       Bp2 + b_c*2);             \
        cp16(&Bsm[_s*B_SZ + b_r*(2*B2ST) + b_c*4 + 128], Bp2 + b_c*2 + 64);        \
    } while (0)

    // prologue: pair 0 -> stages 0,1 (one commit group per pair)
    LOAD_TILE(0, 0);
    LOAD_TILE(1, 1);
    CP_COMMIT();

    for (int p = 0; p < npair; p++) {
        CP_WAIT(0);              // pair p resident
        __syncthreads();         // all warps done with pair p-1 stages (prefetch targets)

        if (p + 1 < npair) {
            int sb = ((p + 1) & 1) << 1;
            LOAD_TILE(2*(p+1),     sb);
            LOAD_TILE(2*(p+1) + 1, sb + 1);
        }
        CP_COMMIT();

#pragma unroll
        for (int half = 0; half < 2; half++) {
            const int stg = ((p & 1) << 1) + half;
            const uint32_t stage_base = asm_base + (uint32_t)(stg*A_SZ)*4;
            const uint2* B2 = (const uint2*)(Bsm + stg*B_SZ);
#pragma unroll
            for (int ks = 0; ks < 2; ks++) {
                uint32_t afrag[2][4];
#pragma unroll
                for (int mt = 0; mt < 2; mt++)
                    ldmx4(afrag[mt], stage_base + a_lm_off + (uint32_t)((mt*16*AST + ks*8)*4));
#pragma unroll
                for (int nt = 0; nt < 8; nt++) {
                    int cn = wn*64 + nt*8 + qid;
                    uint2 bv = B2[(ks*4 + tig)*B2ST + cn];
                    uint32_t bfrag[2] = { bv.x, bv.y };
#pragma unroll
                    for (int mt = 0; mt < 2; mt++)
                        mma_f16(acc[mt][nt], afrag[mt], bfrag);
                }
            }
        }
    }
#undef LOAD_TILE

    if (SCORES) {
        int b = bm >> 3;
        const float* qrow = qvv + b*Dd;
#pragma unroll
        for (int mt = 0; mt < 2; mt++) {
            float p0 = 0.f, p1 = 0.f;
#pragma unroll
            for (int nt = 0; nt < 8; nt++) {
                int c0 = bn*128 + wn*64 + nt*8 + 2*tig;
                float q0 = qrow[c0], q1 = qrow[c0+1];
                p0 += acc[mt][nt][0]*q0 + acc[mt][nt][1]*q1;
                p1 += acc[mt][nt][2]*q0 + acc[mt][nt][3]*q1;
            }
            p0 += __shfl_xor_sync(0xffffffffu, p0, 1);
            p0 += __shfl_xor_sync(0xffffffffu, p0, 2);
            p1 += __shfl_xor_sync(0xffffffffu, p1, 1);
            p1 += __shfl_xor_sync(0xffffffffu, p1, 2);
            if (tig == 0) {
                int r0 = bm*128 + wm*32 + mt*16 + qid;
                atomicAdd(&sc[r0],     p0 * 0.0625f);
                atomicAdd(&sc[r0 + 8], p1 * 0.0625f);
            }
        }
        return;
    }

    // epilogue: bias + relu + fp16 pack
#pragma unroll
    for (int mt = 0; mt < 2; mt++) {
        int r0 = bm*128 + wm*32 + mt*16 + qid;
#pragma unroll
        for (int nt = 0; nt < 8; nt++) {
            int c0 = bn*128 + wn*64 + nt*8 + 2*tig;
            float b0 = bias ? bias[c0]   : 0.f;
            float b1 = bias ? bias[c0+1] : 0.f;
            float v0 = acc[mt][nt][0] + b0, v1 = acc[mt][nt][1] + b1;
            float v2 = acc[mt][nt][2] + b0, v3 = acc[mt][nt][3] + b1;
            if (RELU) {
                v0 = fmaxf(v0, 0.f); v1 = fmaxf(v1, 0.f);
                v2 = fmaxf(v2, 0.f); v3 = fmaxf(v3, 0.f);
            }
            int cu = c0 >> 1;
            C[(size_t)r0*Nd2 + cu]     = pkhf(v0, v1);
            C[(size_t)(r0+8)*Nd2 + cu] = pkhf(v2, v3);
        }
    }
}

// ---------------- fp16 flash attention: cp.async double-buffered K + raw V ----------------
#define QKV_RS 384
#define O_RS   128
#define KST 36
#define VRS 32
#define VST 72
#define PST 36
#define K_SZ (64*KST)
#define VR_SZ (64*VRS)
#define ATT_SMEM ((2*K_SZ + 2*VR_SZ + 32*VST + 8*16*PST)*4)   // 62464 bytes

__global__ void __launch_bounds__(256) attn_mma_kernel(
    const uint32_t* __restrict__ QKV, uint32_t* __restrict__ O)
{
    extern __shared__ uint32_t sm[];
    uint32_t* Kst  = sm;
    uint32_t* Vraw = sm + 2*K_SZ;
    uint32_t* Vs   = sm + 2*K_SZ + 2*VR_SZ;
    const int tid = threadIdx.x;
    const int warp = tid >> 5, lane = tid & 31;
    const int qid = lane >> 2, tig = lane & 3;
    uint32_t* Psw = sm + 2*K_SZ + 2*VR_SZ + 32*VST + warp*16*PST;

    const int qt = blockIdx.x, head = blockIdx.y, b = blockIdx.z;
    const size_t qbase = ((size_t)b*Nn)*QKV_RS + head*(DH/2);
    const size_t kbase = qbase + 128;
    const size_t vbase = qbase + 256;
    const size_t obase = ((size_t)b*Nn)*O_RS + head*(DH/2);
    const int q0 = qt*128 + warp*16;

    uint32_t qa[4][4];
#pragma unroll
    for (int s = 0; s < 4; s++) {
        qa[s][0] = QKV[qbase + (size_t)(q0+qid  )*QKV_RS + s*8 + tig];
        qa[s][1] = QKV[qbase + (size_t)(q0+qid+8)*QKV_RS + s*8 + tig];
        qa[s][2] = QKV[qbase + (size_t)(q0+qid  )*QKV_RS + s*8 + tig + 4];
        qa[s][3] = QKV[qbase + (size_t)(q0+qid+8)*QKV_RS + s*8 + tig + 4];
    }

    float oacc[8][4];
#pragma unroll
    for (int dn = 0; dn < 8; dn++)
#pragma unroll
        for (int i = 0; i < 4; i++) oacc[dn][i] = 0.f;
    float m0 = -1e30f, m1 = -1e30f, l0 = 0.f, l1 = 0.f;
    const float scale = 0.125f;

    const int kr = tid >> 3, kq = (tid & 7) << 2;
    const int vr = tid >> 2, vq = (tid & 3) << 3;
    const int np = tid >> 3, dq = tid & 7;

    cp16(&Kst[kr*KST + kq],       QKV + kbase + (size_t)kr*QKV_RS + kq);
    cp16(&Kst[(kr+32)*KST + kq],  QKV + kbase + (size_t)(kr+32)*QKV_RS + kq);
    cp16(&Vraw[vr*VRS + vq],      QKV + vbase + (size_t)vr*QKV_RS + vq);
    cp16(&Vraw[vr*VRS + vq + 4],  QKV + vbase + (size_t)vr*QKV_RS + vq + 4);
    CP_COMMIT();

    int buf = 0;
    const int ntile = Nn/64;
    for (int jt = 0; jt < ntile; jt++) {
        if (jt + 1 < ntile) {
            int j1 = (jt+1)*64, nb = buf ^ 1;
            cp16(&Kst[nb*K_SZ + kr*KST + kq],      QKV + kbase + (size_t)(j1+kr)*QKV_RS + kq);
            cp16(&Kst[nb*K_SZ + (kr+32)*KST + kq], QKV + kbase + (size_t)(j1+kr+32)*QKV_RS + kq);
            cp16(&Vraw[nb*VR_SZ + vr*VRS + vq],    QKV + vbase + (size_t)(j1+vr)*QKV_RS + vq);
            cp16(&Vraw[nb*VR_SZ + vr*VRS + vq+4],  QKV + vbase + (size_t)(j1+vr)*QKV_RS + vq+4);
        }
        CP_COMMIT();
        CP_WAIT(1);
        __syncthreads();

        const uint32_t* Ks = &Kst[buf*K_SZ];
        const uint32_t* Vr = &Vraw[buf*VR_SZ];

        {
            uint4 r0 = *(const uint4*)(Vr + (2*np  )*VRS + dq*4);
            uint4 r1 = *(const uint4*)(Vr + (2*np+1)*VRS + dq*4);
            uint4 o0, o1;
            o0.x = __byte_perm(r0.x, r1.x, 0x5410); o0.y = __byte_perm(r0.x, r1.x, 0x7632);
            o0.z = __byte_perm(r0.y, r1.y, 0x5410); o0.w = __byte_perm(r0.y, r1.y, 0x7632);
            o1.x = __byte_perm(r0.z, r1.z, 0x5410); o1.y = __byte_perm(r0.z, r1.z, 0x7632);
            o1.z = __byte_perm(r0.w, r1.w, 0x5410); o1.w = __byte_perm(r0.w, r1.w, 0x7632);
            *(uint4*)&Vs[np*VST + dq*8]     = o0;
            *(uint4*)&Vs[np*VST + dq*8 + 4] = o1;
        }

        float sacc[8][4];
#pragma unroll
        for (int nt = 0; nt < 8; nt++)
#pragma unroll
            for (int i = 0; i < 4; i++) sacc[nt][i] = 0.f;
#pragma unroll
        for (int s = 0; s < 4; s++) {
#pragma unroll
            for (int nt = 0; nt < 8; nt++) {
                uint32_t bfrag[2];
                bfrag[0] = Ks[(nt*8+qid)*KST + s*8 + tig];
                bfrag[1] = Ks[(nt*8+qid)*KST + s*8 + tig + 4];
                mma_f16(sacc[nt], qa[s], bfrag);
            }
        }
#pragma unroll
        for (int nt = 0; nt < 8; nt++)
#pragma unroll
            for (int i = 0; i < 4; i++) sacc[nt][i] *= scale;

        float tm0 = -1e30f, tm1 = -1e30f;
#pragma unroll
        for (int nt = 0; nt < 8; nt++) {
            tm0 = fmaxf(tm0, fmaxf(sacc[nt][0], sacc[nt][1]));
            tm1 = fmaxf(tm1, fmaxf(sacc[nt][2], sacc[nt][3]));
        }
        tm0 = fmaxf(tm0, __shfl_xor_sync(0xffffffffu, tm0, 1));
        tm0 = fmaxf(tm0, __shfl_xor_sync(0xffffffffu, tm0, 2));
        tm1 = fmaxf(tm1, __shfl_xor_sync(0xffffffffu, tm1, 1));
        tm1 = fmaxf(tm1, __shfl_xor_sync(0xffffffffu, tm1, 2));
        float mn0 = fmaxf(m0, tm0), mn1 = fmaxf(m1, tm1);
        float c0 = __expf(m0 - mn0), c1 = __expf(m1 - mn1);
        m0 = mn0; m1 = mn1;
        l0 *= c0; l1 *= c1;
#pragma unroll
        for (int dn = 0; dn < 8; dn++) {
            oacc[dn][0] *= c0; oacc[dn][1] *= c0;
            oacc[dn][2] *= c1; oacc[dn][3] *= c1;
        }
#pragma unroll
        for (int nt = 0; nt < 8; nt++) {
            float p0 = __expf(sacc[nt][0] - m0);
            float p1 = __expf(sacc[nt][1] - m0);
            float p2 = __expf(sacc[nt][2] - m1);
            float p3 = __expf(sacc[nt][3] - m1);
            l0 += p0 + p1; l1 += p2 + p3;
            Psw[qid*PST     + nt*4 + tig] = pkhf(p0, p1);
            Psw[(qid+8)*PST + nt*4 + tig] = pkhf(p2, p3);
        }
        __syncthreads();

#pragma unroll
        for (int sj = 0; sj < 4; sj++) {
            uint32_t afrag[4];
            afrag[0] = Psw[qid*PST     + sj*8 + tig];
            afrag[1] = Psw[(qid+8)*PST + sj*8 + tig];
            afrag[2] = Psw[qid*PST     + sj*8 + tig + 4];
            afrag[3] = Psw[(qid+8)*PST + sj*8 + tig + 4];
#pragma unroll
            for (int dn = 0; dn < 8; dn++) {
                uint32_t bfrag[2];
                bfrag[0] = Vs[(sj*8+tig  )*VST + dn*8 + qid];
                bfrag[1] = Vs[(sj*8+tig+4)*VST + dn*8 + qid];
                mma_f16(oacc[dn], afrag, bfrag);
            }
        }
        buf ^= 1;
    }

    l0 += __shfl_xor_sync(0xffffffffu, l0, 1);
    l0 += __shfl_xor_sync(0xffffffffu, l0, 2);
    l1 += __shfl_xor_sync(0xffffffffu, l1, 1);
    l1 += __shfl_xor_sync(0xffffffffu, l1, 2);
    float inv0 = 1.f / l0, inv1 = 1.f / l1;
#pragma unroll
    for (int dn = 0; dn < 8; dn++) {
        int cu = dn*4 + tig;
        O[obase + (size_t)(q0+qid  )*O_RS + cu] = pkhf(oacc[dn][0]*inv0, oacc[dn][1]*inv0);
        O[obase + (size_t)(q0+qid+8)*O_RS + cu] = pkhf(oacc[dn][2]*inv1, oacc[dn][3]*inv1);
    }
}

// ---------------- LayerNorm(h + res) in place (fp16) ----------------
__global__ void ln_res_kernel(uint32_t* __restrict__ h, const uint32_t* __restrict__ res,
                              const float* __restrict__ g, const float* __restrict__ bta)
{
    int row = blockIdx.x*8 + (threadIdx.x >> 5);
    int lane = threadIdx.x & 31;
    size_t off = (size_t)row * (Dd/2);
    float v[8];
    float s = 0.f;
#pragma unroll
    for (int i = 0; i < 4; i++) {
        uint32_t hu = h[off + lane + i*32];
        uint32_t ru = res[off + lane + i*32];
        __half2 hb = *(__half2*)&hu;
        __half2 rb = *(__half2*)&ru;
        v[2*i]   = __half2float(hb.x) + __half2float(rb.x);
        v[2*i+1] = __half2float(hb.y) + __half2float(rb.y);
        s += v[2*i] + v[2*i+1];
    }
#pragma unroll
    for (int o = 16; o; o >>= 1) s += __shfl_xor_sync(0xffffffffu, s, o);
    float mean = s * (1.f/256.f);
    float vs = 0.f;
#pragma unroll
    for (int i = 0; i < 8; i++) { float d = v[i]-mean; vs = fmaf(d, d, vs); }
#pragma unroll
    for (int o = 16; o; o >>= 1) vs += __shfl_xor_sync(0xffffffffu, vs, o);
    float rstd = rsqrtf(vs * (1.f/256.f) + 1e-5f);
#pragma unroll
    for (int i = 0; i < 4; i++) {
        int c = 2*(lane + i*32);
        float o0 = (v[2*i]  -mean)*rstd*g[c]   + bta[c];
        float o1 = (v[2*i+1]-mean)*rstd*g[c+1] + bta[c+1];
        h[off + lane + i*32] = pkhf(o0, o1);
    }
}

// ---------------- h_mean: 4 partial blocks per batch + atomics ----------------
__global__ void hmean_kernel(const __half* __restrict__ h, float* __restrict__ hm)
{
    int b = blockIdx.y, seg = blockIdx.x;
    int d = threadIdx.x;
    const __half* p = h + ((size_t)b*Nn + seg*256)*Dd + d;
    float s = 0.f;
#pragma unroll 8
    for (int n = 0; n < 256; n++) s += __half2float(p[(size_t)n*Dd]);
    atomicAdd(&hm[b*Dd + d], s * (1.f/1024.f));
}

// ---------------- small row GEMM (fp32) ----------------
template<int RELU>
__global__ void rowgemm_kernel(const float* __restrict__ A, const float* __restrict__ W,
                               const float* __restrict__ bias, float* __restrict__ C,
                               int Kd, int Nd)
{
    int b = blockIdx.x;
    __shared__ float xs[1024];
    for (int i = threadIdx.x; i < Kd; i += blockDim.x) xs[i] = A[(size_t)b*Kd + i];
    __syncthreads();
    for (int d = threadIdx.x; d < Nd; d += blockDim.x) {
        float acc = bias ? bias[d] : 0.f;
        for (int k = 0; k < Kd; k++) acc = fmaf(xs[k], W[(size_t)k*Nd + d], acc);
        if (RELU) acc = fmaxf(acc, 0.f);
        C[(size_t)b*Nd + d] = acc;
    }
}

// ---------------- finale: softmaxes + fast top-64 + sel ----------------
__global__ void finale_kernel(const float* __restrict__ scores, const float* __restrict__ gumbel,
                              const float* __restrict__ logits,
                              float* __restrict__ out_w, float* __restrict__ out_idx,
                              float* __restrict__ out_sel)
{
    int b = blockIdx.x, tid = threadIdx.x;
    const int wid = tid >> 5, lane = tid & 31;
    __shared__ float w[1024];
    __shared__ float al[1024];
    __shared__ float red[256];
    __shared__ unsigned long long kred[8];
    __shared__ int selidx[64];

    float lm = -1e30f;
    for (int i = tid; i < 1024; i += 256) {
        float v = (scores[b*Nn+i] + gumbel[b*Nn+i]) * 2.0f;
        w[i] = v; lm = fmaxf(lm, v);
    }
    red[tid] = lm; __syncthreads();
    for (int s = 128; s; s >>= 1) { if (tid < s) red[tid] = fmaxf(red[tid], red[tid+s]); __syncthreads(); }
    float M = red[0]; __syncthreads();
    float ls = 0.f;
    for (int i = tid; i < 1024; i += 256) { float e = __expf(w[i]-M); w[i] = e; ls += e; }
    red[tid] = ls; __syncthreads();
    for (int s = 128; s; s >>= 1) { if (tid < s) red[tid] += red[tid+s]; __syncthreads(); }
    float invS = 1.f / red[0]; __syncthreads();
    for (int i = tid; i < 1024; i += 256) {
        float wi = w[i]*invS; w[i] = wi; out_w[b*Nn+i] = wi;
    }

    lm = -1e30f;
    for (int i = tid; i < 1024; i += 256) { float v = logits[b*Nn+i]; al[i] = v; lm = fmaxf(lm, v); }
    __syncthreads();
    red[tid] = lm; __syncthreads();
    for (int s = 128; s; s >>= 1) { if (tid < s) red[tid] = fmaxf(red[tid], red[tid+s]); __syncthreads(); }
    M = red[0]; __syncthreads();
    ls = 0.f;
    for (int i = tid; i < 1024; i += 256) { float e = __expf(al[i]-M); al[i] = e; ls += e; }
    red[tid] = ls; __syncthreads();
    for (int s = 128; s; s >>= 1) { if (tid < s) red[tid] += red[tid+s]; __syncthreads(); }
    invS = 1.f / red[0]; __syncthreads();
    for (int i = tid; i < 1024; i += 256) al[i] *= invS;
    __syncthreads();

    // top-64 via u64 keys: (float bits << 32) | (1023 - idx); taken entries key 0.
    // w >= 0 always (softmax output); positive-float bits are order-monotonic.
    // Tie -> larger (1023-idx) -> lowest idx, matching lax.top_k.
    for (int kk = 0; kk < 64; kk++) {
        unsigned long long best = 0ull;
#pragma unroll
        for (int t = 0; t < 4; t++) {
            int i = tid + t*256;
            float v = w[i];
            unsigned long long key = (v < 0.f) ? 0ull
                : (((unsigned long long)__float_as_uint(v)) << 32) | (unsigned long long)(1023 - i);
            best = (key > best) ? key : best;
        }
#pragma unroll
        for (int o = 16; o; o >>= 1) {
            unsigned long long ot = __shfl_xor_sync(0xffffffffu, best, o);
            best = (ot > best) ? ot : best;
        }
        if (lane == 0) kred[wid] = best;
        __syncthreads();
        if (tid == 0) {
            unsigned long long bb2 = kred[0];
#pragma unroll
            for (int j = 1; j < 8; j++) if (kred[j] > bb2) bb2 = kred[j];
            int idx = 1023 - (int)(bb2 & 0x3FFull);
            selidx[kk] = idx;
            w[idx] = -1.0f;
        }
        __syncthreads();
    }

    float sv = 0.f;
    if (tid < 64) sv = al[selidx[tid]];
    red[tid] = (tid < 64) ? sv : 0.f; __syncthreads();
    for (int s = 128; s; s >>= 1) { if (tid < s) red[tid] += red[tid+s]; __syncthreads(); }
    float inv = 1.f / (red[0] + 1e-12f);
    if (tid < 64) {
        out_idx[b*64 + tid] = (float)selidx[tid];
        out_sel[b*64 + tid] = sv * inv;
    }
}

// ---------------- launch ----------------
extern "C" void kernel_launch(void* const* d_in, const int* in_sizes, int n_in,
                              void* d_out, int out_size)
{
    const float* x       = (const float*)d_in[0];
    const float* gumbel  = (const float*)d_in[1];
    const float* emb_W   = (const float*)d_in[2];
    const float* emb_b   = (const float*)d_in[3];
    const float* Wq      = (const float*)d_in[4];
    const float* Wk      = (const float*)d_in[5];
    const float* Wv      = (const float*)d_in[6];
    const float* Wo      = (const float*)d_in[7];
    const float* ln1_g   = (const float*)d_in[8];
    const float* ln1_b   = (const float*)d_in[9];
    const float* ln2_g   = (const float*)d_in[10];
    const float* ln2_b   = (const float*)d_in[11];
    const float* ffn_W1  = (const float*)d_in[12];
    const float* ffn_b1  = (const float*)d_in[13];
    const float* ffn_W2  = (const float*)d_in[14];
    const float* ffn_b2  = (const float*)d_in[15];
    const float* sha_Wq  = (const float*)d_in[16];
    const float* sha_Wk  = (const float*)d_in[17];
    const float* alloc_W1= (const float*)d_in[18];
    const float* alloc_b1= (const float*)d_in[19];
    const float* alloc_W2= (const float*)d_in[20];
    const float* alloc_b2= (const float*)d_in[21];

    __half *h, *scr, *tmp;
    uint32_t* wpk;
    float *hmean, *qv, *t1, *logits, *scores;
    cudaGetSymbolAddress((void**)&h,      g_h);
    cudaGetSymbolAddress((void**)&scr,    g_scr);
    cudaGetSymbolAddress((void**)&tmp,    g_tmp);
    cudaGetSymbolAddress((void**)&wpk,    g_wpk);
    cudaGetSymbolAddress((void**)&hmean,  g_hmean);
    cudaGetSymbolAddress((void**)&qv,     g_qv);
    cudaGetSymbolAddress((void**)&t1,     g_t1);
    cudaGetSymbolAddress((void**)&logits, g_logits);
    cudaGetSymbolAddress((void**)&scores, g_scores);

    static int cfg_done = 0;
    if (!cfg_done) {
        cudaFuncSetAttribute(tgemm_kernel<0,0>,
                             cudaFuncAttributeMaxDynamicSharedMemorySize, TG_SMEM);
        cudaFuncSetAttribute(tgemm_kernel<1,0>,
                             cudaFuncAttributeMaxDynamicSharedMemorySize, TG_SMEM);
        cudaFuncSetAttribute(tgemm_kernel<0,1>,
                             cudaFuncAttributeMaxDynamicSharedMemorySize, TG_SMEM);
        cudaFuncSetAttribute(attn_mma_kernel,
                             cudaFuncAttributeMaxDynamicSharedMemorySize, ATT_SMEM);
        cfg_done = 1;
    }

    // fused weight pack (single launch, all 7 weights)
    packall_kernel<<<dim3(1536, 7), 256>>>(Wq, Wk, Wv, Wo, ffn_W1, ffn_W2, sha_Wk, wpk);

    // zero scores + hmean accumulators
    zero2_kernel<<<(Bb*Nn + Bb*Dd)/256, 256>>>(scores, Bb*Nn, hmean);

    __half* qkv = scr;                          // [M][768]
    __half* ao  = scr + (size_t)MM*768;         // [M][256]

    embed_kernel<<<MM/16, 256>>>(x, emb_W, emb_b, h);

    const dim3 gQKV(768/128, MM/128);  // (6,512)
    const dim3 gP(Dd/128, MM/128);     // (2,512)
    const dim3 gF1(DFF/128, MM/128);   // (8,512)

    for (int i = 0; i < Ll; i++) {
        tgemm_kernel<0,0><<<gQKV, 256, TG_SMEM>>>((const uint32_t*)h, wpk + OFF_QKV + (size_t)i*128*768, nullptr, (uint32_t*)qkv, MM, 768, Dd, nullptr, nullptr);
        attn_mma_kernel<<<dim3(Nn/128, Hh, Bb), 256, ATT_SMEM>>>((const uint32_t*)qkv, (uint32_t*)ao);
        tgemm_kernel<0,0><<<gP, 256, TG_SMEM>>>((const uint32_t*)ao, wpk + OFF_WO + (size_t)i*128*256, nullptr, (uint32_t*)tmp, MM, Dd, Dd, nullptr, nullptr);
        ln_res_kernel<<<MM/8, 256>>>((uint32_t*)h, (const uint32_t*)tmp, ln1_g + i*Dd, ln1_b + i*Dd);
        tgemm_kernel<1,0><<<gF1, 256, TG_SMEM>>>((const uint32_t*)h, wpk + OFF_W1 + (size_t)i*128*1024, ffn_b1 + i*DFF, (uint32_t*)scr, MM, DFF, Dd, nullptr, nullptr);
        tgemm_kernel<0,0><<<gP, 256, TG_SMEM>>>((const uint32_t*)scr, wpk + OFF_W2 + (size_t)i*512*256, ffn_b2 + i*Dd, (uint32_t*)tmp, MM, Dd, DFF, nullptr, nullptr);
        ln_res_kernel<<<MM/8, 256>>>((uint32_t*)h, (const uint32_t*)tmp, ln2_g + i*Dd, ln2_b + i*Dd);
    }

    hmean_kernel<<<dim3(4, Bb), 256>>>(h, hmean);
    rowgemm_kernel<0><<<Bb, 256>>>(hmean, sha_Wq, nullptr, qv, Dd, Dd);
    tgemm_kernel<0,1><<<gP, 256, TG_SMEM>>>((const uint32_t*)h, wpk + OFF_SHA, nullptr, (uint32_t*)tmp, MM, Dd, Dd, qv, scores);
    rowgemm_kernel<1><<<Bb, 256>>>(hmean, alloc_W1, alloc_b1, t1, Dd, Dd);
    rowgemm_kernel<0><<<Bb, 256>>>(t1, alloc_W2, alloc_b2, logits, Dd, Nn);

    float* out = (float*)d_out;
    finale_kernel<<<Bb, 256>>>(scores, gumbel, logits,
                               out,
                               out + Bb*Nn,
                               out + Bb*Nn + Bb*Kk);
}

// round 13
// speedup vs baseline: 8.2769x; 1.0233x over previous
#include <cuda_runtime.h>
#include <cuda_fp16.h>
#include <cstdint>

// ---------------- problem dims ----------------
#define Bb 64
#define Nn 1024
#define Din 16
#define Dd 256
#define Hh 4
#define DH 64
#define Ll 3
#define DFF 1024
#define Kk 64
#define MM (Bb*Nn)          // 65536 rows

// ---------------- scratch (static device memory) ----------------
__device__ __half g_h[MM*Dd];           // 32 MB hidden state (fp16)
__device__ __half g_scr[MM*DFF];        // 128 MB qkv|ao or ffn hidden
__device__ uint32_t g_wpk[1212416];     // packed fp16 weights (u64-fragment layout)
__device__ float g_hmean[Bb*Dd];
__device__ float g_qv[Bb*Dd];
__device__ float g_t1[Bb*Dd];
__device__ float g_logits[Bb*Nn];
__device__ float g_scores[Bb*Nn];

// packed-weight offsets (uint32 units)
#define OFF_QKV  0            // 3 x [64 u64-rows][768]
#define OFF_WO   294912       // 3 x [64][256]
#define OFF_W1   393216       // 3 x [64][1024]
#define OFF_W2   786432       // 3 x [256][256]
#define OFF_SHA  1179648      // [64][256]

__device__ __forceinline__ uint32_t pkhf(float lo, float hi) {
    uint32_t r;
    asm("cvt.rn.f16x2.f32 %0, %1, %2;" : "=r"(r) : "f"(hi), "f"(lo));
    return r;
}

__device__ __forceinline__ void mma_f16(float* c, const uint32_t* a, const uint32_t* b) {
    asm volatile(
        "mma.sync.aligned.m16n8k16.row.col.f32.f16.f16.f32 "
        "{%0,%1,%2,%3}, {%4,%5,%6,%7}, {%8,%9}, {%0,%1,%2,%3};"
        : "+f"(c[0]), "+f"(c[1]), "+f"(c[2]), "+f"(c[3])
        : "r"(a[0]), "r"(a[1]), "r"(a[2]), "r"(a[3]), "r"(b[0]), "r"(b[1]));
}

__device__ __forceinline__ void ldmx4(uint32_t* r, uint32_t saddr) {
    asm volatile("ldmatrix.sync.aligned.m8n8.x4.shared.b16 {%0,%1,%2,%3}, [%4];"
        : "=r"(r[0]), "=r"(r[1]), "=r"(r[2]), "=r"(r[3]) : "r"(saddr));
}

__device__ __forceinline__ void cp16(void* smem, const void* gmem) {
    uint32_t s = (uint32_t)__cvta_generic_to_shared(smem);
    asm volatile("cp.async.cg.shared.global [%0], [%1], 16;" :: "r"(s), "l"(gmem));
}
#define CP_COMMIT() asm volatile("cp.async.commit_group;")
#define CP_WAIT(n)  asm volatile("cp.async.wait_group %0;" :: "n"(n))

// ---------------- fused weight pack: all 7 weights in one launch ----------------
__global__ void packall_kernel(const float* __restrict__ Wq, const float* __restrict__ Wk,
                               const float* __restrict__ Wv, const float* __restrict__ Wo,
                               const float* __restrict__ W1, const float* __restrict__ W2,
                               const float* __restrict__ sha, uint32_t* __restrict__ dst)
{
    int seg = blockIdx.y;
    int i = blockIdx.x*256 + threadIdx.x;
    const float* src; int Nsrc, NdT, colOff, KN, KNh, lds, total, dstOff;
    switch (seg) {
        case 0: src=Wq;  dstOff=OFF_QKV; Nsrc=256;  NdT=768;  colOff=0;   KN=65536;  KNh=32768;  lds=98304;  total=98304;  break;
        case 1: src=Wk;  dstOff=OFF_QKV; Nsrc=256;  NdT=768;  colOff=256; KN=65536;  KNh=32768;  lds=98304;  total=98304;  break;
        case 2: src=Wv;  dstOff=OFF_QKV; Nsrc=256;  NdT=768;  colOff=512; KN=65536;  KNh=32768;  lds=98304;  total=98304;  break;
        case 3: src=Wo;  dstOff=OFF_WO;  Nsrc=256;  NdT=256;  colOff=0;   KN=65536;  KNh=32768;  lds=32768;  total=98304;  break;
        case 4: src=W1;  dstOff=OFF_W1;  Nsrc=1024; NdT=1024; colOff=0;   KN=262144; KNh=131072; lds=131072; total=393216; break;
        case 5: src=W2;  dstOff=OFF_W2;  Nsrc=256;  NdT=256;  colOff=0;   KN=262144; KNh=131072; lds=131072; total=393216; break;
        default:src=sha; dstOff=OFF_SHA; Nsrc=256;  NdT=256;  colOff=0;   KN=65536;  KNh=32768;  lds=32768;  total=32768;  break;
    }
    if (i >= total) return;
    int l = i / KNh;
    int rem = i - l*KNh;
    int kp = rem / Nsrc, n = rem - kp*Nsrc;
    int t = kp >> 4, r = kp & 15;
    int j = ((r >> 3) << 2) | (r & 3);
    int half = (r >> 2) & 1;
    const float* s = src + (size_t)l*KN;
    dst[(size_t)dstOff + (size_t)l*lds
        + ((size_t)(t*8 + j)*NdT + colOff + n)*2 + half] =
        pkhf(s[(size_t)(2*kp)*Nsrc + n], s[(size_t)(2*kp+1)*Nsrc + n]);
}

// ---------------- zero hmean ----------------
__global__ void zeroh_kernel(float* __restrict__ p)
{
    p[blockIdx.x*256 + threadIdx.x] = 0.f;
}

// ---------------- embedding: 16 rows/block, W staged in smem ----------------
__global__ void embed_kernel(const float* __restrict__ x, const float* __restrict__ W,
                             const float* __restrict__ bb, __half* __restrict__ h)
{
    __shared__ float Ws[Din*Dd];
    __shared__ float xs[16*Din];
    __shared__ float bsm[Dd];
    const int tid = threadIdx.x;
    const int m0 = blockIdx.x*16;
#pragma unroll
    for (int i = tid; i < Din*Dd; i += 256) Ws[i] = W[i];
    xs[tid] = x[m0*Din + tid];
    bsm[tid] = bb[tid];
    __syncthreads();
    const int d = tid;
#pragma unroll
    for (int r = 0; r < 16; r++) {
        float a = bsm[d];
#pragma unroll
        for (int k = 0; k < Din; k++) a = fmaf(xs[r*Din + k], Ws[k*Dd + d], a);
        h[(size_t)(m0+r)*Dd + d] = __float2half(a);
    }
}

// ---------------- FP16 GEMM (128x128 tile): pair-wise cp.async, ldmatrix A, u64 B ----------------
#define AST 20
#define B2ST 132
#define A_SZ (128*AST)
#define B_SZ (8*B2ST*2)
#define TG_SMEM (4*(A_SZ + B_SZ)*4)   // 74752 bytes

template<int RELU>
__global__ __launch_bounds__(256, 2) void tgemm_kernel(
    const uint32_t* __restrict__ A, const uint32_t* __restrict__ Wp,
    const float* __restrict__ bias, uint32_t* __restrict__ C,
    int M, int Nd, int Kd)
{
    const int Kd2 = Kd >> 1, Nd2 = Nd >> 1;
    extern __shared__ uint32_t dsm[];
    uint32_t* Asm = dsm;
    uint32_t* Bsm = dsm + 4*A_SZ;

    const int tid = threadIdx.x;
    const int warp = tid >> 5;
    const int lane = tid & 31;
    const int bm = blockIdx.y, bn = blockIdx.x;
    const int wm = warp & 3;
    const int wn = warp >> 2;
    const int qid = lane >> 2;
    const int tig = lane & 3;

    const int a_r0 = tid >> 1, a_c0 = (tid & 1) << 3;
    const int b_r = tid >> 5, b_c = tid & 31;

    const int row_sel = (lane & 7) + ((lane >> 3) & 1) * 8;
    const int col_sel = (lane >> 4) * 4;
    const uint32_t a_lm_off = (uint32_t)(((wm*32 + row_sel)*AST + col_sel) * 4);
    const uint32_t asm_base = (uint32_t)__cvta_generic_to_shared(Asm);

    const uint32_t* Ap = A + (size_t)(bm*128)*Kd2;
    const uint64_t* Bp = (const uint64_t*)Wp + (size_t)bn*128;

    float acc[2][8][4];
#pragma unroll
    for (int mt = 0; mt < 2; mt++)
#pragma unroll
        for (int nt = 0; nt < 8; nt++)
#pragma unroll
            for (int i = 0; i < 4; i++) acc[mt][nt][i] = 0.f;

    const int niter = Kd >> 5;
    const int npair = niter >> 1;

#define LOAD_TILE(ck, s) do {                                                      \
        int _ck = (ck), _s = (s);                                                  \
        const uint32_t* Ap2 = Ap + _ck*16;                                         \
        const uint64_t* Bp2 = Bp + (size_t)(_ck*8 + b_r)*Nd;                       \
        cp16(&Asm[_s*A_SZ + a_r0*AST + a_c0],     Ap2 + (size_t)a_r0*Kd2 + a_c0);  \
        cp16(&Asm[_s*A_SZ + a_r0*AST + a_c0 + 4], Ap2 + (size_t)a_r0*Kd2 + a_c0 + 4); \
        cp16(&Bsm[_s*B_SZ + b_r*(2*B2ST) + b_c*4],       Bp2 + b_c*2);             \
        cp16(&Bsm[_s*B_SZ + b_r*(2*B2ST) + b_c*4 + 128], Bp2 + b_c*2 + 64);        \
    } while (0)

    LOAD_TILE(0, 0);
    LOAD_TILE(1, 1);
    CP_COMMIT();

    for (int p = 0; p < npair; p++) {
        CP_WAIT(0);
        __syncthreads();

        if (p + 1 < npair) {
            int sb = ((p + 1) & 1) << 1;
            LOAD_TILE(2*(p+1),     sb);
            LOAD_TILE(2*(p+1) + 1, sb + 1);
        }
        CP_COMMIT();

#pragma unroll
        for (int half = 0; half < 2; half++) {
            const int stg = ((p & 1) << 1) + half;
            const uint32_t stage_base = asm_base + (uint32_t)(stg*A_SZ)*4;
            const uint2* B2 = (const uint2*)(Bsm + stg*B_SZ);
#pragma unroll
            for (int ks = 0; ks < 2; ks++) {
                uint32_t afrag[2][4];
#pragma unroll
                for (int mt = 0; mt < 2; mt++)
                    ldmx4(afrag[mt], stage_base + a_lm_off + (uint32_t)((mt*16*AST + ks*8)*4));
#pragma unroll
                for (int nt = 0; nt < 8; nt++) {
                    int cn = wn*64 + nt*8 + qid;
                    uint2 bv = B2[(ks*4 + tig)*B2ST + cn];
                    uint32_t bfrag[2] = { bv.x, bv.y };
#pragma unroll
                    for (int mt = 0; mt < 2; mt++)
                        mma_f16(acc[mt][nt], afrag[mt], bfrag);
                }
            }
        }
    }
#undef LOAD_TILE

#pragma unroll
    for (int mt = 0; mt < 2; mt++) {
        int r0 = bm*128 + wm*32 + mt*16 + qid;
#pragma unroll
        for (int nt = 0; nt < 8; nt++) {
            int c0 = bn*128 + wn*64 + nt*8 + 2*tig;
            float b0 = bias ? bias[c0]   : 0.f;
            float b1 = bias ? bias[c0+1] : 0.f;
            float v0 = acc[mt][nt][0] + b0, v1 = acc[mt][nt][1] + b1;
            float v2 = acc[mt][nt][2] + b0, v3 = acc[mt][nt][3] + b1;
            if (RELU) {
                v0 = fmaxf(v0, 0.f); v1 = fmaxf(v1, 0.f);
                v2 = fmaxf(v2, 0.f); v3 = fmaxf(v3, 0.f);
            }
            int cu = c0 >> 1;
            C[(size_t)r0*Nd2 + cu]     = pkhf(v0, v1);
            C[(size_t)(r0+8)*Nd2 + cu] = pkhf(v2, v3);
        }
    }
}

// ---------------- fused GEMM (64x256 tile) + LN epilogue OR scores epilogue ----------------
// MODE 0: h = LN(h + A@W + bias) in place.  MODE 1: sc[row] = dot(A@W, qv[b]) / 16.
#define ASTF 20
#define B2STF 260
#define A_SZF (64*ASTF)       // 1280 u32 per stage
#define B_SZF (8*B2STF*2)     // 4160 u32 per stage
#define TL_SMEM (4*(A_SZF + B_SZF)*4)   // 87040 bytes

template<int MODE>
__global__ __launch_bounds__(256, 2) void tgemm_ln_kernel(
    const uint32_t* __restrict__ A, const uint32_t* __restrict__ Wp,
    const float* __restrict__ bias, uint32_t* __restrict__ Hio,
    int Kd,
    const float* __restrict__ g, const float* __restrict__ bta,
    const float* __restrict__ qvv, float* __restrict__ sc)
{
    const int Kd2 = Kd >> 1;
    extern __shared__ uint32_t dsm[];
    uint32_t* Asm = dsm;
    uint32_t* Bsm = dsm + 4*A_SZF;

    const int tid = threadIdx.x;
    const int warp = tid >> 5;
    const int lane = tid & 31;
    const int bm = blockIdx.x;
    const int wm = warp & 1;
    const int wn = warp >> 1;
    const int qid = lane >> 2;
    const int tig = lane & 3;

    const int a_r0 = tid >> 2, a_c0 = (tid & 3) << 2;
    const int b_r = tid >> 5, b_c = tid & 31;

    const int row_sel = (lane & 7) + ((lane >> 3) & 1) * 8;
    const int col_sel = (lane >> 4) * 4;
    const uint32_t a_lm_off = (uint32_t)(((wm*32 + row_sel)*ASTF + col_sel) * 4);
    const uint32_t asm_base = (uint32_t)__cvta_generic_to_shared(Asm);

    const uint32_t* Ap = A + (size_t)(bm*64)*Kd2;
    const uint64_t* Bp = (const uint64_t*)Wp;

    float acc[2][8][4];
#pragma unroll
    for (int mt = 0; mt < 2; mt++)
#pragma unroll
        for (int nt = 0; nt < 8; nt++)
#pragma unroll
            for (int i = 0; i < 4; i++) acc[mt][nt][i] = 0.f;

    const int niter = Kd >> 5;
    const int npair = niter >> 1;

#define LOAD_TILEF(ck, s) do {                                                     \
        int _ck = (ck), _s = (s);                                                  \
        const uint32_t* Ap2 = Ap + _ck*16;                                         \
        const uint64_t* Bp2 = Bp + (size_t)(_ck*8 + b_r)*256;                      \
        cp16(&Asm[_s*A_SZF + a_r0*ASTF + a_c0], Ap2 + (size_t)a_r0*Kd2 + a_c0);    \
        _Pragma("unroll")                                                          \
        for (int _j = 0; _j < 4; _j++)                                             \
            cp16(&Bsm[_s*B_SZF + b_r*(2*B2STF) + (b_c + 32*_j)*4],                 \
                 Bp2 + (b_c + 32*_j)*2);                                           \
    } while (0)

    LOAD_TILEF(0, 0);
    LOAD_TILEF(1, 1);
    CP_COMMIT();

    for (int p = 0; p < npair; p++) {
        CP_WAIT(0);
        __syncthreads();

        if (p + 1 < npair) {
            int sb = ((p + 1) & 1) << 1;
            LOAD_TILEF(2*(p+1),     sb);
            LOAD_TILEF(2*(p+1) + 1, sb + 1);
        }
        CP_COMMIT();

#pragma unroll
        for (int half = 0; half < 2; half++) {
            const int stg = ((p & 1) << 1) + half;
            const uint32_t stage_base = asm_base + (uint32_t)(stg*A_SZF)*4;
            const uint2* B2 = (const uint2*)(Bsm + stg*B_SZF);
#pragma unroll
            for (int ks = 0; ks < 2; ks++) {
                uint32_t afrag[2][4];
#pragma unroll
                for (int mt = 0; mt < 2; mt++)
                    ldmx4(afrag[mt], stage_base + a_lm_off + (uint32_t)((mt*16*ASTF + ks*8)*4));
#pragma unroll
                for (int nt = 0; nt < 8; nt++) {
                    int cn = wn*64 + nt*8 + qid;
                    uint2 bv = B2[(ks*4 + tig)*B2STF + cn];
                    uint32_t bfrag[2] = { bv.x, bv.y };
#pragma unroll
                    for (int mt = 0; mt < 2; mt++)
                        mma_f16(acc[mt][nt], afrag[mt], bfrag);
                }
            }
        }
    }
#undef LOAD_TILEF

    // ---- stage (acc [+bias] [+residual]) to smem as float2 rows (stride 132 f2) ----
    __syncthreads();                      // all MMA reads of smem done
    float2* Sf2 = (float2*)dsm;           // [64][132] float2 = 67.6KB <= 87KB
#pragma unroll
    for (int mt = 0; mt < 2; mt++) {
        int rl0 = wm*32 + mt*16 + qid;    // local rows rl0, rl0+8
#pragma unroll
        for (int nt = 0; nt < 8; nt++) {
            int cu = wn*32 + nt*4 + tig;  // f2 col (pairs c0=2cu, 2cu+1)
            float b0 = 0.f, b1 = 0.f;
            if (MODE == 0 && bias) { b0 = bias[2*cu]; b1 = bias[2*cu+1]; }
            float v0 = acc[mt][nt][0] + b0, v1 = acc[mt][nt][1] + b1;
            float v2 = acc[mt][nt][2] + b0, v3 = acc[mt][nt][3] + b1;
            if (MODE == 0) {
                uint32_t h0 = Hio[(size_t)(bm*64 + rl0)*128 + cu];
                uint32_t h1 = Hio[(size_t)(bm*64 + rl0 + 8)*128 + cu];
                __half2 hh0 = *(__half2*)&h0;
                __half2 hh1 = *(__half2*)&h1;
                v0 += __half2float(hh0.x); v1 += __half2float(hh0.y);
                v2 += __half2float(hh1.x); v3 += __half2float(hh1.y);
            }
            float2 p0; p0.x = v0; p0.y = v1;
            float2 p1; p1.x = v2; p1.y = v3;
            Sf2[rl0*132 + cu]       = p0;
            Sf2[(rl0 + 8)*132 + cu] = p1;
        }
    }
    __syncthreads();

    // ---- per-row epilogue: warp handles 8 rows ----
    if (MODE == 0) {
#pragma unroll
        for (int r = 0; r < 8; r++) {
            int row = warp*8 + r;
            float v[8];
            float s = 0.f;
#pragma unroll
            for (int j = 0; j < 4; j++) {
                float2 t = Sf2[row*132 + lane + j*32];
                v[2*j] = t.x; v[2*j+1] = t.y;
                s += t.x + t.y;
            }
#pragma unroll
            for (int o = 16; o; o >>= 1) s += __shfl_xor_sync(0xffffffffu, s, o);
            float mean = s * (1.f/256.f);
            float vs = 0.f;
#pragma unroll
            for (int i = 0; i < 8; i++) { float d = v[i]-mean; vs = fmaf(d, d, vs); }
#pragma unroll
            for (int o = 16; o; o >>= 1) vs += __shfl_xor_sync(0xffffffffu, vs, o);
            float rstd = rsqrtf(vs * (1.f/256.f) + 1e-5f);
#pragma unroll
            for (int j = 0; j < 4; j++) {
                int c = 2*(lane + j*32);
                float o0 = (v[2*j]  -mean)*rstd*g[c]   + bta[c];
                float o1 = (v[2*j+1]-mean)*rstd*g[c+1] + bta[c+1];
                Hio[(size_t)(bm*64 + row)*128 + lane + j*32] = pkhf(o0, o1);
            }
        }
    } else {
        const int b = (bm*64) >> 10;
        const float* qrow = qvv + b*Dd;
#pragma unroll
        for (int r = 0; r < 8; r++) {
            int row = warp*8 + r;
            float s = 0.f;
#pragma unroll
            for (int j = 0; j < 4; j++) {
                float2 t = Sf2[row*132 + lane + j*32];
                int c = 2*(lane + j*32);
                s = fmaf(t.x, qrow[c], s);
                s = fmaf(t.y, qrow[c+1], s);
            }
#pragma unroll
            for (int o = 16; o; o >>= 1) s += __shfl_xor_sync(0xffffffffu, s, o);
            if (lane == 0) sc[bm*64 + row] = s * 0.0625f;
        }
    }
}

// ---------------- fp16 flash attention: cp.async double-buffered K + raw V ----------------
#define QKV_RS 384
#define O_RS   128
#define KST 36
#define VRS 32
#define VST 72
#define PST 36
#define K_SZ (64*KST)
#define VR_SZ (64*VRS)
#define ATT_SMEM ((2*K_SZ + 2*VR_SZ + 32*VST + 8*16*PST)*4)

__global__ void __launch_bounds__(256) attn_mma_kernel(
    const uint32_t* __restrict__ QKV, uint32_t* __restrict__ O)
{
    extern __shared__ uint32_t sm[];
    uint32_t* Kst  = sm;
    uint32_t* Vraw = sm + 2*K_SZ;
    uint32_t* Vs   = sm + 2*K_SZ + 2*VR_SZ;
    const int tid = threadIdx.x;
    const int warp = tid >> 5, lane = tid & 31;
    const int qid = lane >> 2, tig = lane & 3;
    uint32_t* Psw = sm + 2*K_SZ + 2*VR_SZ + 32*VST + warp*16*PST;

    const int qt = blockIdx.x, head = blockIdx.y, b = blockIdx.z;
    const size_t qbase = ((size_t)b*Nn)*QKV_RS + head*(DH/2);
    const size_t kbase = qbase + 128;
    const size_t vbase = qbase + 256;
    const size_t obase = ((size_t)b*Nn)*O_RS + head*(DH/2);
    const int q0 = qt*128 + warp*16;

    uint32_t qa[4][4];
#pragma unroll
    for (int s = 0; s < 4; s++) {
        qa[s][0] = QKV[qbase + (size_t)(q0+qid  )*QKV_RS + s*8 + tig];
        qa[s][1] = QKV[qbase + (size_t)(q0+qid+8)*QKV_RS + s*8 + tig];
        qa[s][2] = QKV[qbase + (size_t)(q0+qid  )*QKV_RS + s*8 + tig + 4];
        qa[s][3] = QKV[qbase + (size_t)(q0+qid+8)*QKV_RS + s*8 + tig + 4];
    }

    float oacc[8][4];
#pragma unroll
    for (int dn = 0; dn < 8; dn++)
#pragma unroll
        for (int i = 0; i < 4; i++) oacc[dn][i] = 0.f;
    float m0 = -1e30f, m1 = -1e30f, l0 = 0.f, l1 = 0.f;
    const float scale = 0.125f;

    const int kr = tid >> 3, kq = (tid & 7) << 2;
    const int vr = tid >> 2, vq = (tid & 3) << 3;
    const int np = tid >> 3, dq = tid & 7;

    cp16(&Kst[kr*KST + kq],       QKV + kbase + (size_t)kr*QKV_RS + kq);
    cp16(&Kst[(kr+32)*KST + kq],  QKV + kbase + (size_t)(kr+32)*QKV_RS + kq);
    cp16(&Vraw[vr*VRS + vq],      QKV + vbase + (size_t)vr*QKV_RS + vq);
    cp16(&Vraw[vr*VRS + vq + 4],  QKV + vbase + (size_t)vr*QKV_RS + vq + 4);
    CP_COMMIT();

    int buf = 0;
    const int ntile = Nn/64;
    for (int jt = 0; jt < ntile; jt++) {
        if (jt + 1 < ntile) {
            int j1 = (jt+1)*64, nb = buf ^ 1;
            cp16(&Kst[nb*K_SZ + kr*KST + kq],      QKV + kbase + (size_t)(j1+kr)*QKV_RS + kq);
            cp16(&Kst[nb*K_SZ + (kr+32)*KST + kq], QKV + kbase + (size_t)(j1+kr+32)*QKV_RS + kq);
            cp16(&Vraw[nb*VR_SZ + vr*VRS + vq],    QKV + vbase + (size_t)(j1+vr)*QKV_RS + vq);
            cp16(&Vraw[nb*VR_SZ + vr*VRS + vq+4],  QKV + vbase + (size_t)(j1+vr)*QKV_RS + vq+4);
        }
        CP_COMMIT();
        CP_WAIT(1);
        __syncthreads();

        const uint32_t* Ks = &Kst[buf*K_SZ];
        const uint32_t* Vr = &Vraw[buf*VR_SZ];

        {
            uint4 r0 = *(const uint4*)(Vr + (2*np  )*VRS + dq*4);
            uint4 r1 = *(const uint4*)(Vr + (2*np+1)*VRS + dq*4);
            uint4 o0, o1;
            o0.x = __byte_perm(r0.x, r1.x, 0x5410); o0.y = __byte_perm(r0.x, r1.x, 0x7632);
            o0.z = __byte_perm(r0.y, r1.y, 0x5410); o0.w = __byte_perm(r0.y, r1.y, 0x7632);
            o1.x = __byte_perm(r0.z, r1.z, 0x5410); o1.y = __byte_perm(r0.z, r1.z, 0x7632);
            o1.z = __byte_perm(r0.w, r1.w, 0x5410); o1.w = __byte_perm(r0.w, r1.w, 0x7632);
            *(uint4*)&Vs[np*VST + dq*8]     = o0;
            *(uint4*)&Vs[np*VST + dq*8 + 4] = o1;
        }

        float sacc[8][4];
#pragma unroll
        for (int nt = 0; nt < 8; nt++)
#pragma unroll
            for (int i = 0; i < 4; i++) sacc[nt][i] = 0.f;
#pragma unroll
        for (int s = 0; s < 4; s++) {
#pragma unroll
            for (int nt = 0; nt < 8; nt++) {
                uint32_t bfrag[2];
                bfrag[0] = Ks[(nt*8+qid)*KST + s*8 + tig];
                bfrag[1] = Ks[(nt*8+qid)*KST + s*8 + tig + 4];
                mma_f16(sacc[nt], qa[s], bfrag);
            }
        }
#pragma unroll
        for (int nt = 0; nt < 8; nt++)
#pragma unroll
            for (int i = 0; i < 4; i++) sacc[nt][i] *= scale;

        float tm0 = -1e30f, tm1 = -1e30f;
#pragma unroll
        for (int nt = 0; nt < 8; nt++) {
            tm0 = fmaxf(tm0, fmaxf(sacc[nt][0], sacc[nt][1]));
            tm1 = fmaxf(tm1, fmaxf(sacc[nt][2], sacc[nt][3]));
        }
        tm0 = fmaxf(tm0, __shfl_xor_sync(0xffffffffu, tm0, 1));
        tm0 = fmaxf(tm0, __shfl_xor_sync(0xffffffffu, tm0, 2));
        tm1 = fmaxf(tm1, __shfl_xor_sync(0xffffffffu, tm1, 1));
        tm1 = fmaxf(tm1, __shfl_xor_sync(0xffffffffu, tm1, 2));
        float mn0 = fmaxf(m0, tm0), mn1 = fmaxf(m1, tm1);
        float c0 = __expf(m0 - mn0), c1 = __expf(m1 - mn1);
        m0 = mn0; m1 = mn1;
        l0 *= c0; l1 *= c1;
#pragma unroll
        for (int dn = 0; dn < 8; dn++) {
            oacc[dn][0] *= c0; oacc[dn][1] *= c0;
            oacc[dn][2] *= c1; oacc[dn][3] *= c1;
        }
#pragma unroll
        for (int nt = 0; nt < 8; nt++) {
            float p0 = __expf(sacc[nt][0] - m0);
            float p1 = __expf(sacc[nt][1] - m0);
            float p2 = __expf(sacc[nt][2] - m1);
            float p3 = __expf(sacc[nt][3] - m1);
            l0 += p0 + p1; l1 += p2 + p3;
            Psw[qid*PST     + nt*4 + tig] = pkhf(p0, p1);
            Psw[(qid+8)*PST + nt*4 + tig] = pkhf(p2, p3);
        }
        __syncthreads();

#pragma unroll
        for (int sj = 0; sj < 4; sj++) {
            uint32_t afrag[4];
            afrag[0] = Psw[qid*PST     + sj*8 + tig];
            afrag[1] = Psw[(qid+8)*PST + sj*8 + tig];
            afrag[2] = Psw[qid*PST     + sj*8 + tig + 4];
            afrag[3] = Psw[(qid+8)*PST + sj*8 + tig + 4];
#pragma unroll
            for (int dn = 0; dn < 8; dn++) {
                uint32_t bfrag[2];
                bfrag[0] = Vs[(sj*8+tig  )*VST + dn*8 + qid];
                bfrag[1] = Vs[(sj*8+tig+4)*VST + dn*8 + qid];
                mma_f16(oacc[dn], afrag, bfrag);
            }
        }
        buf ^= 1;
    }

    l0 += __shfl_xor_sync(0xffffffffu, l0, 1);
    l0 += __shfl_xor_sync(0xffffffffu, l0, 2);
    l1 += __shfl_xor_sync(0xffffffffu, l1, 1);
    l1 += __shfl_xor_sync(0xffffffffu, l1, 2);
    float inv0 = 1.f / l0, inv1 = 1.f / l1;
#pragma unroll
    for (int dn = 0; dn < 8; dn++) {
        int cu = dn*4 + tig;
        O[obase + (size_t)(q0+qid  )*O_RS + cu] = pkhf(oacc[dn][0]*inv0, oacc[dn][1]*inv0);
        O[obase + (size_t)(q0+qid+8)*O_RS + cu] = pkhf(oacc[dn][2]*inv1, oacc[dn][3]*inv1);
    }
}

// ---------------- h_mean: 4 partial blocks per batch + atomics ----------------
__global__ void hmean_kernel(const __half* __restrict__ h, float* __restrict__ hm)
{
    int b = blockIdx.y, seg = blockIdx.x;
    int d = threadIdx.x;
    const __half* p = h + ((size_t)b*Nn + seg*256)*Dd + d;
    float s = 0.f;
#pragma unroll 8
    for (int n = 0; n < 256; n++) s += __half2float(p[(size_t)n*Dd]);
    atomicAdd(&hm[b*Dd + d], s * (1.f/1024.f));
}

// ---------------- small row GEMM (fp32) ----------------
template<int RELU>
__global__ void rowgemm_kernel(const float* __restrict__ A, const float* __restrict__ W,
                               const float* __restrict__ bias, float* __restrict__ C,
                               int Kd, int Nd)
{
    int b = blockIdx.x;
    __shared__ float xs[1024];
    for (int i = threadIdx.x; i < Kd; i += blockDim.x) xs[i] = A[(size_t)b*Kd + i];
    __syncthreads();
    for (int d = threadIdx.x; d < Nd; d += blockDim.x) {
        float acc = bias ? bias[d] : 0.f;
        for (int k = 0; k < Kd; k++) acc = fmaf(xs[k], W[(size_t)k*Nd + d], acc);
        if (RELU) acc = fmaxf(acc, 0.f);
        C[(size_t)b*Nd + d] = acc;
    }
}

// ---------------- finale: softmaxes + fast top-64 + sel ----------------
__global__ void finale_kernel(const float* __restrict__ scores, const float* __restrict__ gumbel,
                              const float* __restrict__ logits,
                              float* __restrict__ out_w, float* __restrict__ out_idx,
                              float* __restrict__ out_sel)
{
    int b = blockIdx.x, tid = threadIdx.x;
    const int wid = tid >> 5, lane = tid & 31;
    __shared__ float w[1024];
    __shared__ float al[1024];
    __shared__ float red[256];
    __shared__ unsigned long long kred[8];
    __shared__ int selidx[64];

    float lm = -1e30f;
    for (int i = tid; i < 1024; i += 256) {
        float v = (scores[b*Nn+i] + gumbel[b*Nn+i]) * 2.0f;
        w[i] = v; lm = fmaxf(lm, v);
    }
    red[tid] = lm; __syncthreads();
    for (int s = 128; s; s >>= 1) { if (tid < s) red[tid] = fmaxf(red[tid], red[tid+s]); __syncthreads(); }
    float M = red[0]; __syncthreads();
    float ls = 0.f;
    for (int i = tid; i < 1024; i += 256) { float e = __expf(w[i]-M); w[i] = e; ls += e; }
    red[tid] = ls; __syncthreads();
    for (int s = 128; s; s >>= 1) { if (tid < s) red[tid] += red[tid+s]; __syncthreads(); }
    float invS = 1.f / red[0]; __syncthreads();
    for (int i = tid; i < 1024; i += 256) {
        float wi = w[i]*invS; w[i] = wi; out_w[b*Nn+i] = wi;
    }

    lm = -1e30f;
    for (int i = tid; i < 1024; i += 256) { float v = logits[b*Nn+i]; al[i] = v; lm = fmaxf(lm, v); }
    __syncthreads();
    red[tid] = lm; __syncthreads();
    for (int s = 128; s; s >>= 1) { if (tid < s) red[tid] = fmaxf(red[tid], red[tid+s]); __syncthreads(); }
    M = red[0]; __syncthreads();
    ls = 0.f;
    for (int i = tid; i < 1024; i += 256) { float e = __expf(al[i]-M); al[i] = e; ls += e; }
    red[tid] = ls; __syncthreads();
    for (int s = 128; s; s >>= 1) { if (tid < s) red[tid] += red[tid+s]; __syncthreads(); }
    invS = 1.f / red[0]; __syncthreads();
    for (int i = tid; i < 1024; i += 256) al[i] *= invS;
    __syncthreads();

    for (int kk = 0; kk < 64; kk++) {
        unsigned long long best = 0ull;
#pragma unroll
        for (int t = 0; t < 4; t++) {
            int i = tid + t*256;
            float v = w[i];
            unsigned long long key = (v < 0.f) ? 0ull
                : (((unsigned long long)__float_as_uint(v)) << 32) | (unsigned long long)(1023 - i);
            best = (key > best) ? key : best;
        }
#pragma unroll
        for (int o = 16; o; o >>= 1) {
            unsigned long long ot = __shfl_xor_sync(0xffffffffu, best, o);
            best = (ot > best) ? ot : best;
        }
        if (lane == 0) kred[wid] = best;
        __syncthreads();
        if (tid == 0) {
            unsigned long long bb2 = kred[0];
#pragma unroll
            for (int j = 1; j < 8; j++) if (kred[j] > bb2) bb2 = kred[j];
            int idx = 1023 - (int)(bb2 & 0x3FFull);
            selidx[kk] = idx;
            w[idx] = -1.0f;
        }
        __syncthreads();
    }

    float sv = 0.f;
    if (tid < 64) sv = al[selidx[tid]];
    red[tid] = (tid < 64) ? sv : 0.f; __syncthreads();
    for (int s = 128; s; s >>= 1) { if (tid < s) red[tid] += red[tid+s]; __syncthreads(); }
    float inv = 1.f / (red[0] + 1e-12f);
    if (tid < 64) {
        out_idx[b*64 + tid] = (float)selidx[tid];
        out_sel[b*64 + tid] = sv * inv;
    }
}

// ---------------- launch ----------------
extern "C" void kernel_launch(void* const* d_in, const int* in_sizes, int n_in,
                              void* d_out, int out_size)
{
    const float* x       = (const float*)d_in[0];
    const float* gumbel  = (const float*)d_in[1];
    const float* emb_W   = (const float*)d_in[2];
    const float* emb_b   = (const float*)d_in[3];
    const float* Wq      = (const float*)d_in[4];
    const float* Wk      = (const float*)d_in[5];
    const float* Wv      = (const float*)d_in[6];
    const float* Wo      = (const float*)d_in[7];
    const float* ln1_g   = (const float*)d_in[8];
    const float* ln1_b   = (const float*)d_in[9];
    const float* ln2_g   = (const float*)d_in[10];
    const float* ln2_b   = (const float*)d_in[11];
    const float* ffn_W1  = (const float*)d_in[12];
    const float* ffn_b1  = (const float*)d_in[13];
    const float* ffn_W2  = (const float*)d_in[14];
    const float* ffn_b2  = (const float*)d_in[15];
    const float* sha_Wq  = (const float*)d_in[16];
    const float* sha_Wk  = (const float*)d_in[17];
    const float* alloc_W1= (const float*)d_in[18];
    const float* alloc_b1= (const float*)d_in[19];
    const float* alloc_W2= (const float*)d_in[20];
    const float* alloc_b2= (const float*)d_in[21];

    __half *h, *scr;
    uint32_t* wpk;
    float *hmean, *qv, *t1, *logits, *scores;
    cudaGetSymbolAddress((void**)&h,      g_h);
    cudaGetSymbolAddress((void**)&scr,    g_scr);
    cudaGetSymbolAddress((void**)&wpk,    g_wpk);
    cudaGetSymbolAddress((void**)&hmean,  g_hmean);
    cudaGetSymbolAddress((void**)&qv,     g_qv);
    cudaGetSymbolAddress((void**)&t1,     g_t1);
    cudaGetSymbolAddress((void**)&logits, g_logits);
    cudaGetSymbolAddress((void**)&scores, g_scores);

    static int cfg_done = 0;
    if (!cfg_done) {
        cudaFuncSetAttribute(tgemm_kernel<0>,
                             cudaFuncAttributeMaxDynamicSharedMemorySize, TG_SMEM);
        cudaFuncSetAttribute(tgemm_kernel<1>,
                             cudaFuncAttributeMaxDynamicSharedMemorySize, TG_SMEM);
        cudaFuncSetAttribute(tgemm_ln_kernel<0>,
                             cudaFuncAttributeMaxDynamicSharedMemorySize, TL_SMEM);
        cudaFuncSetAttribute(tgemm_ln_kernel<1>,
                             cudaFuncAttributeMaxDynamicSharedMemorySize, TL_SMEM);
        cudaFuncSetAttribute(attn_mma_kernel,
                             cudaFuncAttributeMaxDynamicSharedMemorySize, ATT_SMEM);
        cfg_done = 1;
    }

    packall_kernel<<<dim3(1536, 7), 256>>>(Wq, Wk, Wv, Wo, ffn_W1, ffn_W2, sha_Wk, wpk);
    zeroh_kernel<<<Bb*Dd/256, 256>>>(hmean);

    __half* qkv = scr;                          // [M][768]
    __half* ao  = scr + (size_t)MM*768;         // [M][256]

    embed_kernel<<<MM/16, 256>>>(x, emb_W, emb_b, h);

    const dim3 gQKV(768/128, MM/128);  // (6,512)
    const dim3 gF1(DFF/128, MM/128);   // (8,512)

    for (int i = 0; i < Ll; i++) {
        tgemm_kernel<0><<<gQKV, 256, TG_SMEM>>>((const uint32_t*)h, wpk + OFF_QKV + (size_t)i*128*768, nullptr, (uint32_t*)qkv, MM, 768, Dd);
        attn_mma_kernel<<<dim3(Nn/128, Hh, Bb), 256, ATT_SMEM>>>((const uint32_t*)qkv, (uint32_t*)ao);
        tgemm_ln_kernel<0><<<MM/64, 256, TL_SMEM>>>(
            (const uint32_t*)ao, wpk + OFF_WO + (size_t)i*128*256, nullptr, (uint32_t*)h,
            Dd, ln1_g + i*Dd, ln1_b + i*Dd, nullptr, nullptr);
        tgemm_kernel<1><<<gF1, 256, TG_SMEM>>>((const uint32_t*)h, wpk + OFF_W1 + (size_t)i*128*1024, ffn_b1 + i*DFF, (uint32_t*)scr, MM, DFF, Dd);
        tgemm_ln_kernel<0><<<MM/64, 256, TL_SMEM>>>(
            (const uint32_t*)scr, wpk + OFF_W2 + (size_t)i*512*256, ffn_b2 + i*Dd, (uint32_t*)h,
            DFF, ln2_g + i*Dd, ln2_b + i*Dd, nullptr, nullptr);
    }

    hmean_kernel<<<dim3(4, Bb), 256>>>(h, hmean);
    rowgemm_kernel<0><<<Bb, 256>>>(hmean, sha_Wq, nullptr, qv, Dd, Dd);
    tgemm_ln_kernel<1><<<MM/64, 256, TL_SMEM>>>(
        (const uint32_t*)h, wpk + OFF_SHA, nullptr, (uint32_t*)h,
        Dd, nullptr, nullptr, qv, scores);
    rowgemm_kernel<1><<<Bb, 256>>>(hmean, alloc_W1, alloc_b1, t1, Dd, Dd);
    rowgemm_kernel<0><<<Bb, 256>>>(t1, alloc_W2, alloc_b2, logits, Dd, Nn);

    float* out = (float*)d_out;
    finale_kernel<<<Bb, 256>>>(scores, gumbel, logits,
                               out,
                               out + Bb*Nn,
                               out + Bb*Nn + Bb*Kk);
}